// round 3
// baseline (speedup 1.0000x reference)
#include <cuda_runtime.h>
#include <math.h>

// Problem constants (fixed by the reference)
#define B_  4
#define C_  64
#define O_  64
#define H_  128
#define W_  128
#define K2_ 9
#define HW_ (H_*W_)
#define CK_ (C_*K2_)          // 576

// ---------------- scratch (no allocations allowed) ----------------
__device__ float g_wom_t[CK_*28];          // transposed offset-conv weight, padded 27->28
__device__ float g_w_t  [CK_*O_];          // transposed main weight [ck][o]
__device__ float g_dy   [B_*K2_*HW_];
__device__ float g_dx   [B_*K2_*HW_];
__device__ float g_mask [B_*K2_*HW_];

// ---------------- packed f32x2 FMA (sm_100+) ----------------
__device__ __forceinline__ unsigned long long fma2(unsigned long long a,
                                                   unsigned long long b,
                                                   unsigned long long c) {
    unsigned long long d;
    asm("fma.rn.f32x2 %0, %1, %2, %3;" : "=l"(d) : "l"(a), "l"(b), "l"(c));
    return d;
}
__device__ __forceinline__ unsigned long long splat2(float v) {
    unsigned long long d;
    asm("mov.b64 %0, {%1, %1};" : "=l"(d) : "f"(v));
    return d;
}

// ---------------- kernel 0: weight transposes ----------------
__global__ void prep_weights(const float* __restrict__ w_om,
                             const float* __restrict__ weight) {
    int tid = blockIdx.x * blockDim.x + threadIdx.x;
    int stride = gridDim.x * blockDim.x;
    for (int i = tid; i < CK_*28; i += stride) {
        int ck = i / 28, r = i - ck*28;
        g_wom_t[i] = (r < 27) ? w_om[r*CK_ + ck] : 0.f;
    }
    for (int j = tid; j < CK_*O_; j += stride) {
        int ck = j >> 6, o = j & 63;
        g_w_t[j] = weight[o*CK_ + ck];
    }
}

// ---------------- kernel 1: offset/mask conv (27ch, 3x3, pad 1) ----------------
__global__ void __launch_bounds__(512)
offset_conv(const float* __restrict__ x, const float* __restrict__ b_om) {
    extern __shared__ float wA[];     // 576*28 floats = 64512 B

    const int tid = threadIdx.x;
    for (int i = tid; i < CK_*28; i += 512) wA[i] = g_wom_t[i];
    __syncthreads();

    const int p   = blockIdx.x*512 + tid;     // 0..65535
    const int b   = p >> 14;
    const int pix = p & (HW_ - 1);
    const int y   = pix >> 7, xq = pix & 127;
    const float* xb = x + (size_t)b*C_*HW_;

    const bool vy0 = (y  > 0),  vy2 = (y  < H_-1);
    const bool vx0 = (xq > 0),  vx2 = (xq < W_-1);
    const int base00 = (y-1)*W_ + (xq-1);

    unsigned long long acc[14];
    #pragma unroll
    for (int j = 0; j < 14; j++) acc[j] = 0ull;

    for (int c = 0; c < C_; c++) {
        const float* xp = xb + c*HW_ + base00;
        float v[9];
        v[0] = (vy0 && vx0) ? xp[0]        : 0.f;
        v[1] =  vy0         ? xp[1]        : 0.f;
        v[2] = (vy0 && vx2) ? xp[2]        : 0.f;
        v[3] =  vx0         ? xp[W_]       : 0.f;
        v[4] =                xp[W_+1];
        v[5] =  vx2         ? xp[W_+2]     : 0.f;
        v[6] = (vy2 && vx0) ? xp[2*W_]     : 0.f;
        v[7] =  vy2         ? xp[2*W_+1]   : 0.f;
        v[8] = (vy2 && vx2) ? xp[2*W_+2]   : 0.f;

        const float* wc = wA + c*9*28;
        #pragma unroll
        for (int t = 0; t < 9; t++) {
            unsigned long long vv = splat2(v[t]);
            const ulonglong2* wr = (const ulonglong2*)(wc + t*28);
            #pragma unroll
            for (int q = 0; q < 7; q++) {
                ulonglong2 w4 = wr[q];
                acc[2*q]   = fma2(vv, w4.x, acc[2*q]);
                acc[2*q+1] = fma2(vv, w4.y, acc[2*q+1]);
            }
        }
    }

    float a[28];
    #pragma unroll
    for (int j = 0; j < 14; j++) {
        a[2*j]   = __uint_as_float((unsigned)(acc[j] & 0xffffffffULL));
        a[2*j+1] = __uint_as_float((unsigned)(acc[j] >> 32));
    }
    #pragma unroll
    for (int k = 0; k < 9; k++) {
        int base = (b*9 + k)*HW_ + pix;
        g_dy[base]   = a[2*k]     + b_om[2*k];
        g_dx[base]   = a[2*k + 1] + b_om[2*k + 1];
        float mlog   = a[18 + k]  + b_om[18 + k];
        g_mask[base] = 1.f / (1.f + __expf(-mlog));
    }
}

// ---------------- kernel 2: fused bilinear sample + output GEMM ----------------
// 2-way output-channel split: grid (128, 2), 512 threads. Each CTA keeps a
// 576x32 half of the transposed weight in SMEM (73.7 KB) -> 2 CTAs/SM,
// 8 warps/SMSP, one clean wave (256 CTAs). 16 packed f32x2 accumulators per
// thread -> fits the 64-reg cap of __launch_bounds__(512,2) without spilling.
__global__ void __launch_bounds__(512, 2)
deform_out(const float* __restrict__ x, const float* __restrict__ bias,
           float* __restrict__ out) {
    extern __shared__ float swh[];    // 576*32 floats = 73728 B
    const int half = blockIdx.y;      // 0: channels 0..31, 1: channels 32..63
    {
        const float4* src = (const float4*)g_w_t;   // [ck][64] -> 16 float4 per ck
        float4* dst = (float4*)swh;                 // [ck][32] ->  8 float4 per ck
        for (int i = threadIdx.x; i < CK_*8; i += 512) {
            int ck = i >> 3, q = i & 7;
            dst[i] = src[ck*16 + half*8 + q];
        }
    }
    __syncthreads();

    const int p   = blockIdx.x*512 + threadIdx.x;   // 0..65535
    const int b   = p >> 14;
    const int pix = p & (HW_ - 1);
    const int y   = pix >> 7, xq = pix & 127;
    const float* xb = x + (size_t)b*C_*HW_;

    unsigned long long acc[16];
    #pragma unroll
    for (int i = 0; i < 16; i++) acc[i] = 0ull;

    #pragma unroll 1
    for (int k = 0; k < 9; k++) {
        const int base = (b*9 + k)*HW_ + pix;
        const float m  = g_mask[base];
        const int ky = k / 3, kx = k - ky*3;
        const float sy = g_dy[base] + (float)(ky + y - 1);
        const float sx = g_dx[base] + (float)(kx + xq - 1);

        const float y0f = floorf(sy), x0f = floorf(sx);
        const int iy0 = (int)y0f, ix0 = (int)x0f;
        const float wy1 = sy - y0f, wx1 = sx - x0f;
        const float wy0 = 1.f - wy1, wx0 = 1.f - wx1;

        const bool vy0 = (iy0   >= 0) && (iy0   < H_);
        const bool vy1 = (iy0+1 >= 0) && (iy0+1 < H_);
        const bool vx0 = (ix0   >= 0) && (ix0   < W_);
        const bool vx1 = (ix0+1 >= 0) && (ix0+1 < W_);

        const int y0c = min(max(iy0,   0), H_-1);
        const int y1c = min(max(iy0+1, 0), H_-1);
        const int x0c = min(max(ix0,   0), W_-1);
        const int x1c = min(max(ix0+1, 0), W_-1);

        const int o00 = y0c*W_ + x0c, o01 = y0c*W_ + x1c;
        const int o10 = y1c*W_ + x0c, o11 = y1c*W_ + x1c;

        const float c00 = (vy0 && vx0) ? wy0*wx0*m : 0.f;
        const float c01 = (vy0 && vx1) ? wy0*wx1*m : 0.f;
        const float c10 = (vy1 && vx0) ? wy1*wx0*m : 0.f;
        const float c11 = (vy1 && vx1) ? wy1*wx1*m : 0.f;

        const float* swk = swh + k*32;
        for (int c = 0; c < C_; c++) {
            const float* xp = xb + c*HW_;
            float v = c00 * xp[o00];
            v = fmaf(c01, xp[o01], v);
            v = fmaf(c10, xp[o10], v);
            v = fmaf(c11, xp[o11], v);

            unsigned long long vv = splat2(v);

            const ulonglong2* wr = (const ulonglong2*)(swk + c*(9*32));
            #pragma unroll
            for (int j = 0; j < 8; j++) {
                ulonglong2 w4 = wr[j];
                acc[2*j]   = fma2(vv, w4.x, acc[2*j]);
                acc[2*j+1] = fma2(vv, w4.y, acc[2*j+1]);
            }
        }
    }

    float* ob = out + (size_t)b*O_*HW_ + (size_t)(half*32)*HW_ + pix;
    const float* bi = bias + half*32;
    #pragma unroll
    for (int i = 0; i < 16; i++) {
        float lo = __uint_as_float((unsigned)(acc[i] & 0xffffffffULL));
        float hi = __uint_as_float((unsigned)(acc[i] >> 32));
        ob[(size_t)(2*i  )*HW_] = lo + bi[2*i];
        ob[(size_t)(2*i+1)*HW_] = hi + bi[2*i+1];
    }
}

// ---------------- launch ----------------
extern "C" void kernel_launch(void* const* d_in, const int* in_sizes, int n_in,
                              void* d_out, int out_size) {
    const float* x      = (const float*)d_in[0];
    const float* w_om   = (const float*)d_in[1];
    const float* b_om   = (const float*)d_in[2];
    const float* weight = (const float*)d_in[3];
    const float* bias   = (const float*)d_in[4];
    float* out = (float*)d_out;

    const int SMEM_A = (CK_*28) * 4;              // 64512
    const int SMEM_B = (CK_*32) * 4;              // 73728
    cudaFuncSetAttribute(offset_conv, cudaFuncAttributeMaxDynamicSharedMemorySize, SMEM_A);
    cudaFuncSetAttribute(deform_out,  cudaFuncAttributeMaxDynamicSharedMemorySize, SMEM_B);

    prep_weights<<<64, 256>>>(w_om, weight);
    offset_conv<<<128, 512, SMEM_A>>>(x, b_om);
    deform_out<<<dim3(128, 2), 512, SMEM_B>>>(x, bias, out);
}

// round 4
// speedup vs baseline: 1.1161x; 1.1161x over previous
#include <cuda_runtime.h>
#include <math.h>

// Problem constants (fixed by the reference)
#define B_  4
#define C_  64
#define O_  64
#define H_  128
#define W_  128
#define K2_ 9
#define HW_ (H_*W_)
#define CK_ (C_*K2_)          // 576

// ---------------- scratch (no allocations allowed) ----------------
__device__ float g_w_t  [CK_*O_];          // transposed main weight [ck][o]
__device__ float g_dy   [B_*K2_*HW_];
__device__ float g_dx   [B_*K2_*HW_];
__device__ float g_mask [B_*K2_*HW_];

// ---------------- packed f32x2 FMA (sm_100+) ----------------
__device__ __forceinline__ unsigned long long fma2(unsigned long long a,
                                                   unsigned long long b,
                                                   unsigned long long c) {
    unsigned long long d;
    asm("fma.rn.f32x2 %0, %1, %2, %3;" : "=l"(d) : "l"(a), "l"(b), "l"(c));
    return d;
}
__device__ __forceinline__ unsigned long long splat2(float v) {
    unsigned long long d;
    asm("mov.b64 %0, {%1, %1};" : "=l"(d) : "f"(v));
    return d;
}

// ---------------- kernel 1: offset/mask conv + weight transposes ----------------
// 512 threads, grid 128. Loads the offset-conv weight transposed straight from
// global into SMEM (one-time, small), and also writes the transposed main
// weight g_w_t for deform_out (kernel-boundary sync makes it visible).
__global__ void __launch_bounds__(512)
offset_conv(const float* __restrict__ x, const float* __restrict__ w_om,
            const float* __restrict__ b_om, const float* __restrict__ weight) {
    extern __shared__ float wA[];     // 576*28 floats = 64512 B

    const int tid = threadIdx.x;

    // main-weight transpose: [O][ck] -> g_w_t[ck][O]  (coalesced reads)
    {
        int idx = blockIdx.x*512 + tid;         // 65536 threads cover 36864
        if (idx < CK_*O_) {
            int o = idx / CK_, ck = idx - o*CK_;
            g_w_t[ck*O_ + o] = weight[idx];
        }
    }

    // offset-conv weight: w_om[r][ck] -> wA[ck][28] (pad zeroed)
    for (int i = tid; i < 27*CK_; i += 512) {
        int r = i / CK_, ck = i - r*CK_;        // consecutive ck: coalesced reads
        wA[ck*28 + r] = w_om[i];
    }
    for (int ck = tid; ck < CK_; ck += 512) wA[ck*28 + 27] = 0.f;
    __syncthreads();

    const int p   = blockIdx.x*512 + tid;     // 0..65535
    const int b   = p >> 14;
    const int pix = p & (HW_ - 1);
    const int y   = pix >> 7, xq = pix & 127;
    const float* xb = x + (size_t)b*C_*HW_;

    const bool vy0 = (y  > 0),  vy2 = (y  < H_-1);
    const bool vx0 = (xq > 0),  vx2 = (xq < W_-1);
    const int base00 = (y-1)*W_ + (xq-1);

    unsigned long long acc[14];
    #pragma unroll
    for (int j = 0; j < 14; j++) acc[j] = 0ull;

    for (int c = 0; c < C_; c++) {
        const float* xp = xb + c*HW_ + base00;
        float v[9];
        v[0] = (vy0 && vx0) ? xp[0]        : 0.f;
        v[1] =  vy0         ? xp[1]        : 0.f;
        v[2] = (vy0 && vx2) ? xp[2]        : 0.f;
        v[3] =  vx0         ? xp[W_]       : 0.f;
        v[4] =                xp[W_+1];
        v[5] =  vx2         ? xp[W_+2]     : 0.f;
        v[6] = (vy2 && vx0) ? xp[2*W_]     : 0.f;
        v[7] =  vy2         ? xp[2*W_+1]   : 0.f;
        v[8] = (vy2 && vx2) ? xp[2*W_+2]   : 0.f;

        const float* wc = wA + c*9*28;
        #pragma unroll
        for (int t = 0; t < 9; t++) {
            unsigned long long vv = splat2(v[t]);
            const ulonglong2* wr = (const ulonglong2*)(wc + t*28);
            #pragma unroll
            for (int q = 0; q < 7; q++) {
                ulonglong2 w4 = wr[q];
                acc[2*q]   = fma2(vv, w4.x, acc[2*q]);
                acc[2*q+1] = fma2(vv, w4.y, acc[2*q+1]);
            }
        }
    }

    float a[28];
    #pragma unroll
    for (int j = 0; j < 14; j++) {
        a[2*j]   = __uint_as_float((unsigned)(acc[j] & 0xffffffffULL));
        a[2*j+1] = __uint_as_float((unsigned)(acc[j] >> 32));
    }
    #pragma unroll
    for (int k = 0; k < 9; k++) {
        int base = (b*9 + k)*HW_ + pix;
        g_dy[base]   = a[2*k]     + b_om[2*k];
        g_dx[base]   = a[2*k + 1] + b_om[2*k + 1];
        float mlog   = a[18 + k]  + b_om[18 + k];
        g_mask[base] = 1.f / (1.f + __expf(-mlog));
    }
}

// ---------------- kernel 2: fused bilinear sample + output GEMM ----------------
// 512 threads, grid 128, full 64 output channels (32 f32x2 accs), full
// transposed weight in SMEM (147 KB). Taps processed in rows of 3 with
// precomputed coefficients/offsets; per channel the 12 gathers are issued
// together (MLP=12) and 8 of 12 hit L1 because the 3 taps overlap spatially.
__global__ void __launch_bounds__(512)
deform_out(const float* __restrict__ x, const float* __restrict__ bias,
           float* __restrict__ out) {
    extern __shared__ float sw[];     // 576*64 floats = 147456 B
    {
        const float4* src = (const float4*)g_w_t;
        float4* dst = (float4*)sw;
        for (int i = threadIdx.x; i < CK_*O_/4; i += 512) dst[i] = src[i];
    }
    __syncthreads();

    const int p   = blockIdx.x*512 + threadIdx.x;   // 0..65535
    const int b   = p >> 14;
    const int pix = p & (HW_ - 1);
    const int y   = pix >> 7, xq = pix & 127;
    const float* xb = x + (size_t)b*C_*HW_;

    unsigned long long acc[32];
    #pragma unroll
    for (int i = 0; i < 32; i++) acc[i] = 0ull;

    #pragma unroll 1
    for (int g = 0; g < 3; g++) {       // tap row (ky)
        float C00[3], C01[3], C10[3], C11[3];
        int   O00[3], O01[3], O10[3], O11[3];

        #pragma unroll
        for (int t = 0; t < 3; t++) {
            const int k = g*3 + t;
            const int base = (b*9 + k)*HW_ + pix;
            const float m  = g_mask[base];
            const float sy = g_dy[base] + (float)(g + y - 1);
            const float sx = g_dx[base] + (float)(t + xq - 1);

            const float y0f = floorf(sy), x0f = floorf(sx);
            const int iy0 = (int)y0f, ix0 = (int)x0f;
            const float wy1 = sy - y0f, wx1 = sx - x0f;
            const float wy0 = 1.f - wy1, wx0 = 1.f - wx1;

            const bool vy0 = (iy0   >= 0) && (iy0   < H_);
            const bool vy1 = (iy0+1 >= 0) && (iy0+1 < H_);
            const bool vx0 = (ix0   >= 0) && (ix0   < W_);
            const bool vx1 = (ix0+1 >= 0) && (ix0+1 < W_);

            const int y0c = min(max(iy0,   0), H_-1);
            const int y1c = min(max(iy0+1, 0), H_-1);
            const int x0c = min(max(ix0,   0), W_-1);
            const int x1c = min(max(ix0+1, 0), W_-1);

            O00[t] = y0c*W_ + x0c;  O01[t] = y0c*W_ + x1c;
            O10[t] = y1c*W_ + x0c;  O11[t] = y1c*W_ + x1c;

            C00[t] = (vy0 && vx0) ? wy0*wx0*m : 0.f;
            C01[t] = (vy0 && vx1) ? wy0*wx1*m : 0.f;
            C10[t] = (vy1 && vx0) ? wy1*wx0*m : 0.f;
            C11[t] = (vy1 && vx1) ? wy1*wx1*m : 0.f;
        }

        #pragma unroll 2
        for (int c = 0; c < C_; c++) {
            const float* xp = xb + c*HW_;
            // batch all 12 independent gathers (MLP=12)
            float a00[3], a01[3], a10[3], a11[3];
            #pragma unroll
            for (int t = 0; t < 3; t++) {
                a00[t] = xp[O00[t]];
                a01[t] = xp[O01[t]];
                a10[t] = xp[O10[t]];
                a11[t] = xp[O11[t]];
            }
            #pragma unroll
            for (int t = 0; t < 3; t++) {
                float u = fmaf(C01[t], a01[t], C00[t]*a00[t]);
                float w = fmaf(C11[t], a11[t], C10[t]*a10[t]);
                float v = u + w;
                unsigned long long vv = splat2(v);
                const ulonglong2* wr =
                    (const ulonglong2*)(sw + (c*9 + g*3 + t)*64);
                #pragma unroll
                for (int j = 0; j < 16; j++) {
                    ulonglong2 w4 = wr[j];
                    acc[2*j]   = fma2(vv, w4.x, acc[2*j]);
                    acc[2*j+1] = fma2(vv, w4.y, acc[2*j+1]);
                }
            }
        }
    }

    float* ob = out + (size_t)b*O_*HW_ + pix;
    #pragma unroll
    for (int i = 0; i < 32; i++) {
        float lo = __uint_as_float((unsigned)(acc[i] & 0xffffffffULL));
        float hi = __uint_as_float((unsigned)(acc[i] >> 32));
        ob[(size_t)(2*i  )*HW_] = lo + bias[2*i];
        ob[(size_t)(2*i+1)*HW_] = hi + bias[2*i+1];
    }
}

// ---------------- launch ----------------
extern "C" void kernel_launch(void* const* d_in, const int* in_sizes, int n_in,
                              void* d_out, int out_size) {
    const float* x      = (const float*)d_in[0];
    const float* w_om   = (const float*)d_in[1];
    const float* b_om   = (const float*)d_in[2];
    const float* weight = (const float*)d_in[3];
    const float* bias   = (const float*)d_in[4];
    float* out = (float*)d_out;

    const int SMEM_A = (CK_*28) * 4;              // 64512
    const int SMEM_B = (CK_*O_) * 4;              // 147456
    cudaFuncSetAttribute(offset_conv, cudaFuncAttributeMaxDynamicSharedMemorySize, SMEM_A);
    cudaFuncSetAttribute(deform_out,  cudaFuncAttributeMaxDynamicSharedMemorySize, SMEM_B);

    offset_conv<<<128, 512, SMEM_A>>>(x, w_om, b_om, weight);
    deform_out<<<128, 512, SMEM_B>>>(x, bias, out);
}

// round 7
// speedup vs baseline: 1.6356x; 1.4655x over previous
#include <cuda_runtime.h>
#include <cuda_bf16.h>
#include <math.h>

// Problem constants (fixed by the reference)
#define B_  4
#define C_  64
#define O_  64
#define H_  128
#define W_  128
#define K2_ 9
#define HW_ (H_*W_)
#define CK_ (C_*K2_)          // 576

// ---------------- scratch (no allocations allowed) ----------------
// Main weight pre-arranged in mma.sync B-fragment layout:
// entry idx = ((t*4 + kc)*8 + nt)*32 + lane ; .x = k-pair (lane%4)*2, .y = +8
__device__ uint2 g_wB_hi[9*4*8*32];
__device__ uint2 g_wB_lo[9*4*8*32];
__device__ float g_dy   [B_*K2_*HW_];
__device__ float g_dx   [B_*K2_*HW_];
__device__ float g_mask [B_*K2_*HW_];

// ---------------- packed f32x2 FMA (sm_100+) ----------------
__device__ __forceinline__ unsigned long long fma2(unsigned long long a,
                                                   unsigned long long b,
                                                   unsigned long long c) {
    unsigned long long d;
    asm("fma.rn.f32x2 %0, %1, %2, %3;" : "=l"(d) : "l"(a), "l"(b), "l"(c));
    return d;
}
__device__ __forceinline__ unsigned long long splat2(float v) {
    unsigned long long d;
    asm("mov.b64 %0, {%1, %1};" : "=l"(d) : "f"(v));
    return d;
}

__device__ __forceinline__ unsigned smem_u32(const void* p) {
    unsigned a;
    asm("{ .reg .u64 t; cvta.to.shared.u64 t, %1; cvt.u32.u64 %0, t; }"
        : "=r"(a) : "l"(p));
    return a;
}

__device__ __forceinline__ unsigned short bf16_bits(float v) {
    __nv_bfloat16 h = __float2bfloat16(v);
    return *reinterpret_cast<unsigned short*>(&h);
}
__device__ __forceinline__ float bf16_val(unsigned short u) {
    __nv_bfloat16 h = *reinterpret_cast<__nv_bfloat16*>(&u);
    return __bfloat162float(h);
}

// ---------------- kernel 1: offset/mask conv + B-fragment weight prep ----------------
__global__ void __launch_bounds__(512)
offset_conv(const float* __restrict__ x, const float* __restrict__ w_om,
            const float* __restrict__ b_om, const float* __restrict__ weight) {
    extern __shared__ float wA[];     // 576*28 floats = 64512 B

    const int tid = threadIdx.x;

    // --- main weight -> mma B-fragment layout, bf16 hi/lo split ---
    {
        int i = blockIdx.x*512 + tid;           // 65536 threads cover 9216
        if (i < 9216) {
            int t    = i / 1024;
            int r    = i - t*1024;
            int kc   = r >> 8;
            int r2   = r & 255;
            int nt   = r2 >> 5;
            int lane = r2 & 31;
            int n  = nt*8 + (lane >> 2);
            int kb = (lane & 3)*2;
            uint2 hi, lo;
            unsigned hv[2], lv[2];
            #pragma unroll
            for (int u = 0; u < 2; u++) {
                int c0 = kc*16 + kb + u*8;
                float w0 = weight[n*CK_ + c0*9 + t];
                float w1 = weight[n*CK_ + (c0+1)*9 + t];
                unsigned short h0 = bf16_bits(w0);
                unsigned short h1 = bf16_bits(w1);
                unsigned short l0 = bf16_bits(w0 - bf16_val(h0));
                unsigned short l1 = bf16_bits(w1 - bf16_val(h1));
                hv[u] = (unsigned)h0 | ((unsigned)h1 << 16);
                lv[u] = (unsigned)l0 | ((unsigned)l1 << 16);
            }
            hi.x = hv[0]; hi.y = hv[1];
            lo.x = lv[0]; lo.y = lv[1];
            g_wB_hi[i] = hi;
            g_wB_lo[i] = lo;
        }
    }

    // offset-conv weight: w_om[r][ck] -> wA[ck][28] (pad zeroed)
    for (int i = tid; i < 27*CK_; i += 512) {
        int r = i / CK_, ck = i - r*CK_;
        wA[ck*28 + r] = w_om[i];
    }
    for (int ck = tid; ck < CK_; ck += 512) wA[ck*28 + 27] = 0.f;
    __syncthreads();

    const int p   = blockIdx.x*512 + tid;
    const int b   = p >> 14;
    const int pix = p & (HW_ - 1);
    const int y   = pix >> 7, xq = pix & 127;
    const float* xb = x + (size_t)b*C_*HW_;

    const bool vy0 = (y  > 0),  vy2 = (y  < H_-1);
    const bool vx0 = (xq > 0),  vx2 = (xq < W_-1);
    const int base00 = (y-1)*W_ + (xq-1);

    unsigned long long acc[14];
    #pragma unroll
    for (int j = 0; j < 14; j++) acc[j] = 0ull;

    for (int c = 0; c < C_; c++) {
        const float* xp = xb + c*HW_ + base00;
        float v[9];
        v[0] = (vy0 && vx0) ? xp[0]        : 0.f;
        v[1] =  vy0         ? xp[1]        : 0.f;
        v[2] = (vy0 && vx2) ? xp[2]        : 0.f;
        v[3] =  vx0         ? xp[W_]       : 0.f;
        v[4] =                xp[W_+1];
        v[5] =  vx2         ? xp[W_+2]     : 0.f;
        v[6] = (vy2 && vx0) ? xp[2*W_]     : 0.f;
        v[7] =  vy2         ? xp[2*W_+1]   : 0.f;
        v[8] = (vy2 && vx2) ? xp[2*W_+2]   : 0.f;

        const float* wc = wA + c*9*28;
        #pragma unroll
        for (int t = 0; t < 9; t++) {
            unsigned long long vv = splat2(v[t]);
            const ulonglong2* wr = (const ulonglong2*)(wc + t*28);
            #pragma unroll
            for (int q = 0; q < 7; q++) {
                ulonglong2 w4 = wr[q];
                acc[2*q]   = fma2(vv, w4.x, acc[2*q]);
                acc[2*q+1] = fma2(vv, w4.y, acc[2*q+1]);
            }
        }
    }

    float a[28];
    #pragma unroll
    for (int j = 0; j < 14; j++) {
        a[2*j]   = __uint_as_float((unsigned)(acc[j] & 0xffffffffULL));
        a[2*j+1] = __uint_as_float((unsigned)(acc[j] >> 32));
    }
    #pragma unroll
    for (int k = 0; k < 9; k++) {
        int base = (b*9 + k)*HW_ + pix;
        g_dy[base]   = a[2*k]     + b_om[2*k];
        g_dx[base]   = a[2*k + 1] + b_om[2*k + 1];
        float mlog   = a[18 + k]  + b_om[18 + k];
        g_mask[base] = 1.f / (1.f + __expf(-mlog));
    }
}

// ---------------- kernel 2: implicit GEMM via mma.sync (bf16 3-pass) ----------------
// Per CTA: 128 pixels (one image row) x 64 outputs, K = 9 taps x 64 channels.
// Per tap: 256 threads gather+bilinear 128x64 vals (lane = consecutive px),
// bf16 hi/lo split into swizzled SMEM A-tiles; B fragments copied from global.
// Each warp owns 16 pixels: ldmatrix A frags + 96 mma.sync per tap.
__global__ void __launch_bounds__(256)
deform_mma(const float* __restrict__ x, const float* __restrict__ bias,
           float* __restrict__ out) {
    __shared__ __align__(16) unsigned char sA[32768];   // hi @0, lo @16384
    __shared__ uint2 sB_hi[1024];                       // 8 KB
    __shared__ uint2 sB_lo[1024];                       // 8 KB

    const int tid  = threadIdx.x;
    const int lane = tid & 31;
    const int wp   = tid >> 5;          // warp 0..7 -> pixels wp*16..+15
    const int b    = blockIdx.x >> 7;
    const int tile = blockIdx.x & 127;  // image row
    const float* xb = x + (size_t)b*C_*HW_;

    const int px  = tid & 127;          // gather pixel
    const int grp = tid >> 7;           // channel half 0/1
    const int gpix = tile*128 + px;

    const unsigned sAu = smem_u32(sA);

    float acc[8][4];
    #pragma unroll
    for (int nt = 0; nt < 8; nt++)
        #pragma unroll
        for (int j = 0; j < 4; j++) acc[nt][j] = 0.f;

    #pragma unroll 1
    for (int t = 0; t < 9; t++) {
        // ---- B fragments for this tap: global -> SMEM (8 KB each) ----
        {
            const uint4* srcH = (const uint4*)(g_wB_hi + t*1024);
            const uint4* srcL = (const uint4*)(g_wB_lo + t*1024);
            uint4* dstH = (uint4*)sB_hi;
            uint4* dstL = (uint4*)sB_lo;
            for (int j = tid; j < 512; j += 256) {
                dstH[j] = srcH[j];
                dstL[j] = srcL[j];
            }
        }

        // ---- bilinear coefficients for (px, tap) ----
        const int obase = (b*9 + t)*HW_ + gpix;
        const float m  = g_mask[obase];
        const int ky = t / 3, kx = t - ky*3;
        const float sy = g_dy[obase] + (float)(ky + tile - 1);
        const float sx = g_dx[obase] + (float)(kx + px   - 1);

        const float y0f = floorf(sy), x0f = floorf(sx);
        const int iy0 = (int)y0f, ix0 = (int)x0f;
        const float wy1 = sy - y0f, wx1 = sx - x0f;
        const float wy0 = 1.f - wy1, wx0 = 1.f - wx1;

        const bool py0 = (iy0   >= 0) && (iy0   < H_);
        const bool py1 = (iy0+1 >= 0) && (iy0+1 < H_);
        const bool pxv0 = (ix0   >= 0) && (ix0   < W_);
        const bool pxv1 = (ix0+1 >= 0) && (ix0+1 < W_);

        const int y0c = min(max(iy0,   0), H_-1);
        const int y1c = min(max(iy0+1, 0), H_-1);
        const int x0c = min(max(ix0,   0), W_-1);
        const int x1c = min(max(ix0+1, 0), W_-1);

        const int o00 = y0c*W_ + x0c, o01 = y0c*W_ + x1c;
        const int o10 = y1c*W_ + x0c, o11 = y1c*W_ + x1c;

        const float c00 = (py0 && pxv0) ? wy0*wx0*m : 0.f;
        const float c01 = (py0 && pxv1) ? wy0*wx1*m : 0.f;
        const float c10 = (py1 && pxv0) ? wy1*wx0*m : 0.f;
        const float c11 = (py1 && pxv1) ? wy1*wx1*m : 0.f;

        // ---- A tile: 32 channels per thread, bf16 hi/lo, swizzled STS.128 ----
        #pragma unroll
        for (int mch = 0; mch < 4; mch++) {
            const int cb = grp*32 + mch*8;
            float v[8];
            #pragma unroll
            for (int e = 0; e < 8; e++) {
                const float* xp = xb + (cb + e)*HW_;
                float a0 = xp[o00], a1 = xp[o01], a2 = xp[o10], a3 = xp[o11];
                v[e] = fmaf(c01, a1, c00*a0) + fmaf(c11, a3, c10*a2);
            }
            uint4 hv, lv;
            unsigned hs[4], ls[4];
            #pragma unroll
            for (int pr = 0; pr < 4; pr++) {
                unsigned short h0 = bf16_bits(v[2*pr]);
                unsigned short h1 = bf16_bits(v[2*pr+1]);
                unsigned short l0 = bf16_bits(v[2*pr]   - bf16_val(h0));
                unsigned short l1 = bf16_bits(v[2*pr+1] - bf16_val(h1));
                hs[pr] = (unsigned)h0 | ((unsigned)h1 << 16);
                ls[pr] = (unsigned)l0 | ((unsigned)l1 << 16);
            }
            hv.x = hs[0]; hv.y = hs[1]; hv.z = hs[2]; hv.w = hs[3];
            lv.x = ls[0]; lv.y = ls[1]; lv.z = ls[2]; lv.w = ls[3];
            const int chunk = grp*4 + mch;                    // 16B chunk 0..7
            const unsigned off = (unsigned)(px*128 + 16*(chunk ^ (px & 7)));
            *(uint4*)(sA + off)         = hv;
            *(uint4*)(sA + 16384 + off) = lv;
        }

        __syncthreads();

        // ---- mma phase: warp wp covers pixels wp*16..wp*16+15 ----
        #pragma unroll
        for (int kc = 0; kc < 4; kc++) {
            const int prow = wp*16 + (lane & 15);
            const int chnk = 2*kc + (lane >> 4);
            const unsigned aoff = sAu + (unsigned)(prow*128 + 16*(chnk ^ (prow & 7)));
            unsigned ah0, ah1, ah2, ah3, al0, al1, al2, al3;
            asm volatile("ldmatrix.sync.aligned.m8n8.x4.shared.b16 {%0,%1,%2,%3}, [%4];"
                         : "=r"(ah0), "=r"(ah1), "=r"(ah2), "=r"(ah3) : "r"(aoff));
            asm volatile("ldmatrix.sync.aligned.m8n8.x4.shared.b16 {%0,%1,%2,%3}, [%4];"
                         : "=r"(al0), "=r"(al1), "=r"(al2), "=r"(al3) : "r"(aoff + 16384u));

            #pragma unroll
            for (int nt = 0; nt < 8; nt++) {
                const uint2 bh = sB_hi[(kc*8 + nt)*32 + lane];
                const uint2 bl = sB_lo[(kc*8 + nt)*32 + lane];
                float* d = acc[nt];
                asm volatile(
                    "mma.sync.aligned.m16n8k16.row.col.f32.bf16.bf16.f32 "
                    "{%0,%1,%2,%3}, {%4,%5,%6,%7}, {%8,%9}, {%0,%1,%2,%3};"
                    : "+f"(d[0]), "+f"(d[1]), "+f"(d[2]), "+f"(d[3])
                    : "r"(ah0), "r"(ah1), "r"(ah2), "r"(ah3), "r"(bh.x), "r"(bh.y));
                asm volatile(
                    "mma.sync.aligned.m16n8k16.row.col.f32.bf16.bf16.f32 "
                    "{%0,%1,%2,%3}, {%4,%5,%6,%7}, {%8,%9}, {%0,%1,%2,%3};"
                    : "+f"(d[0]), "+f"(d[1]), "+f"(d[2]), "+f"(d[3])
                    : "r"(ah0), "r"(ah1), "r"(ah2), "r"(ah3), "r"(bl.x), "r"(bl.y));
                asm volatile(
                    "mma.sync.aligned.m16n8k16.row.col.f32.bf16.bf16.f32 "
                    "{%0,%1,%2,%3}, {%4,%5,%6,%7}, {%8,%9}, {%0,%1,%2,%3};"
                    : "+f"(d[0]), "+f"(d[1]), "+f"(d[2]), "+f"(d[3])
                    : "r"(al0), "r"(al1), "r"(al2), "r"(al3), "r"(bh.x), "r"(bh.y));
            }
        }

        __syncthreads();
    }

    // ---- epilogue: D fragments -> global ----
    {
        const int r0 = lane >> 2;
        const int cp = (lane & 3)*2;
        float* obase = out + (size_t)(b*O_)*HW_ + tile*128 + wp*16;
        #pragma unroll
        for (int nt = 0; nt < 8; nt++) {
            const int o = nt*8 + cp;
            const float bi0 = bias[o], bi1 = bias[o+1];
            obase[(size_t)o*HW_     + r0    ] = acc[nt][0] + bi0;
            obase[(size_t)(o+1)*HW_ + r0    ] = acc[nt][1] + bi1;
            obase[(size_t)o*HW_     + r0 + 8] = acc[nt][2] + bi0;
            obase[(size_t)(o+1)*HW_ + r0 + 8] = acc[nt][3] + bi1;
        }
    }
}

// ---------------- launch ----------------
extern "C" void kernel_launch(void* const* d_in, const int* in_sizes, int n_in,
                              void* d_out, int out_size) {
    const float* x      = (const float*)d_in[0];
    const float* w_om   = (const float*)d_in[1];
    const float* b_om   = (const float*)d_in[2];
    const float* weight = (const float*)d_in[3];
    const float* bias   = (const float*)d_in[4];
    float* out = (float*)d_out;

    const int SMEM_A = (CK_*28) * 4;              // 64512
    cudaFuncSetAttribute(offset_conv, cudaFuncAttributeMaxDynamicSharedMemorySize, SMEM_A);

    offset_conv<<<128, 512, SMEM_A>>>(x, w_om, b_om, weight);
    deform_mma<<<512, 256>>>(x, bias, out);
}

// round 8
// speedup vs baseline: 1.6377x; 1.0013x over previous
#include <cuda_runtime.h>
#include <cuda_bf16.h>
#include <math.h>

// Problem constants (fixed by the reference)
#define B_  4
#define C_  64
#define O_  64
#define H_  128
#define W_  128
#define K2_ 9
#define HW_ (H_*W_)
#define CK_ (C_*K2_)          // 576

// ---------------- scratch (no allocations allowed) ----------------
// Main weight pre-arranged in mma.sync B-fragment layout:
// entry idx = ((t*4 + kc)*8 + nt)*32 + lane ; .x = k-pair (lane%4)*2, .y = +8
__device__ uint2 g_wB_hi[9*4*8*32];
__device__ uint2 g_wB_lo[9*4*8*32];
__device__ float g_dy   [B_*K2_*HW_];
__device__ float g_dx   [B_*K2_*HW_];
__device__ float g_mask [B_*K2_*HW_];

// ---------------- packed f32x2 FMA (sm_100+) ----------------
__device__ __forceinline__ unsigned long long fma2(unsigned long long a,
                                                   unsigned long long b,
                                                   unsigned long long c) {
    unsigned long long d;
    asm("fma.rn.f32x2 %0, %1, %2, %3;" : "=l"(d) : "l"(a), "l"(b), "l"(c));
    return d;
}
__device__ __forceinline__ unsigned long long splat2(float v) {
    unsigned long long d;
    asm("mov.b64 %0, {%1, %1};" : "=l"(d) : "f"(v));
    return d;
}

__device__ __forceinline__ unsigned smem_u32(const void* p) {
    unsigned a;
    asm("{ .reg .u64 t; cvta.to.shared.u64 t, %1; cvt.u32.u64 %0, t; }"
        : "=r"(a) : "l"(p));
    return a;
}

__device__ __forceinline__ unsigned short bf16_bits(float v) {
    __nv_bfloat16 h = __float2bfloat16(v);
    return *reinterpret_cast<unsigned short*>(&h);
}
__device__ __forceinline__ float bf16_val(unsigned short u) {
    __nv_bfloat16 h = *reinterpret_cast<__nv_bfloat16*>(&u);
    return __bfloat162float(h);
}

// ---------------- kernel 1: offset/mask conv + B-fragment weight prep ----------------
// 256 CTAs x 256 threads (1 px/thread): full SM coverage + 2-3 CTAs/SM.
__global__ void __launch_bounds__(256)
offset_conv(const float* __restrict__ x, const float* __restrict__ w_om,
            const float* __restrict__ b_om, const float* __restrict__ weight) {
    extern __shared__ float wA[];     // 576*28 floats = 64512 B

    const int tid = threadIdx.x;

    // --- main weight -> mma B-fragment layout, bf16 hi/lo split ---
    {
        int i = blockIdx.x*256 + tid;           // 65536 threads cover 9216
        if (i < 9216) {
            int t    = i / 1024;
            int r    = i - t*1024;
            int kc   = r >> 8;
            int r2   = r & 255;
            int nt   = r2 >> 5;
            int lane = r2 & 31;
            int n  = nt*8 + (lane >> 2);
            int kb = (lane & 3)*2;
            uint2 hi, lo;
            unsigned hv[2], lv[2];
            #pragma unroll
            for (int u = 0; u < 2; u++) {
                int c0 = kc*16 + kb + u*8;
                float w0 = weight[n*CK_ + c0*9 + t];
                float w1 = weight[n*CK_ + (c0+1)*9 + t];
                unsigned short h0 = bf16_bits(w0);
                unsigned short h1 = bf16_bits(w1);
                unsigned short l0 = bf16_bits(w0 - bf16_val(h0));
                unsigned short l1 = bf16_bits(w1 - bf16_val(h1));
                hv[u] = (unsigned)h0 | ((unsigned)h1 << 16);
                lv[u] = (unsigned)l0 | ((unsigned)l1 << 16);
            }
            hi.x = hv[0]; hi.y = hv[1];
            lo.x = lv[0]; lo.y = lv[1];
            g_wB_hi[i] = hi;
            g_wB_lo[i] = lo;
        }
    }

    // offset-conv weight: w_om[r][ck] -> wA[ck][28] (pad zeroed)
    for (int i = tid; i < 27*CK_; i += 256) {
        int r = i / CK_, ck = i - r*CK_;
        wA[ck*28 + r] = w_om[i];
    }
    for (int ck = tid; ck < CK_; ck += 256) wA[ck*28 + 27] = 0.f;
    __syncthreads();

    const int p   = blockIdx.x*256 + tid;     // 0..65535
    const int b   = p >> 14;
    const int pix = p & (HW_ - 1);
    const int y   = pix >> 7, xq = pix & 127;
    const float* xb = x + (size_t)b*C_*HW_;

    const bool vy0 = (y  > 0),  vy2 = (y  < H_-1);
    const bool vx0 = (xq > 0),  vx2 = (xq < W_-1);
    const int base00 = (y-1)*W_ + (xq-1);

    unsigned long long acc[14];
    #pragma unroll
    for (int j = 0; j < 14; j++) acc[j] = 0ull;

    for (int c = 0; c < C_; c++) {
        const float* xp = xb + c*HW_ + base00;
        float v[9];
        v[0] = (vy0 && vx0) ? xp[0]        : 0.f;
        v[1] =  vy0         ? xp[1]        : 0.f;
        v[2] = (vy0 && vx2) ? xp[2]        : 0.f;
        v[3] =  vx0         ? xp[W_]       : 0.f;
        v[4] =                xp[W_+1];
        v[5] =  vx2         ? xp[W_+2]     : 0.f;
        v[6] = (vy2 && vx0) ? xp[2*W_]     : 0.f;
        v[7] =  vy2         ? xp[2*W_+1]   : 0.f;
        v[8] = (vy2 && vx2) ? xp[2*W_+2]   : 0.f;

        const float* wc = wA + c*9*28;
        #pragma unroll
        for (int t = 0; t < 9; t++) {
            unsigned long long vv = splat2(v[t]);
            const ulonglong2* wr = (const ulonglong2*)(wc + t*28);
            #pragma unroll
            for (int q = 0; q < 7; q++) {
                ulonglong2 w4 = wr[q];
                acc[2*q]   = fma2(vv, w4.x, acc[2*q]);
                acc[2*q+1] = fma2(vv, w4.y, acc[2*q+1]);
            }
        }
    }

    float a[28];
    #pragma unroll
    for (int j = 0; j < 14; j++) {
        a[2*j]   = __uint_as_float((unsigned)(acc[j] & 0xffffffffULL));
        a[2*j+1] = __uint_as_float((unsigned)(acc[j] >> 32));
    }
    #pragma unroll
    for (int k = 0; k < 9; k++) {
        int base = (b*9 + k)*HW_ + pix;
        g_dy[base]   = a[2*k]     + b_om[2*k];
        g_dx[base]   = a[2*k + 1] + b_om[2*k + 1];
        float mlog   = a[18 + k]  + b_om[18 + k];
        g_mask[base] = 1.f / (1.f + __expf(-mlog));
    }
}

// ---------------- kernel 2: implicit GEMM via mma.sync (bf16 3-pass) ----------------
// Per CTA: 128 pixels (one image row) x 64 outputs, K = 9 taps x 64 channels.
// __launch_bounds__(256,3) + max shared carveout -> 3 CTAs/SM so gather and
// mma phases of different CTAs overlap.
__global__ void __launch_bounds__(256, 3)
deform_mma(const float* __restrict__ x, const float* __restrict__ bias,
           float* __restrict__ out) {
    __shared__ __align__(16) unsigned char sA[32768];   // hi @0, lo @16384
    __shared__ uint2 sB_hi[1024];                       // 8 KB
    __shared__ uint2 sB_lo[1024];                       // 8 KB

    const int tid  = threadIdx.x;
    const int lane = tid & 31;
    const int wp   = tid >> 5;          // warp 0..7 -> pixels wp*16..+15
    const int b    = blockIdx.x >> 7;
    const int tile = blockIdx.x & 127;  // image row
    const float* xb = x + (size_t)b*C_*HW_;

    const int px  = tid & 127;          // gather pixel
    const int grp = tid >> 7;           // channel half 0/1
    const int gpix = tile*128 + px;

    const unsigned sAu = smem_u32(sA);

    float acc[8][4];
    #pragma unroll
    for (int nt = 0; nt < 8; nt++)
        #pragma unroll
        for (int j = 0; j < 4; j++) acc[nt][j] = 0.f;

    #pragma unroll 1
    for (int t = 0; t < 9; t++) {
        // ---- B fragments for this tap: global -> SMEM (8 KB each) ----
        {
            const uint4* srcH = (const uint4*)(g_wB_hi + t*1024);
            const uint4* srcL = (const uint4*)(g_wB_lo + t*1024);
            uint4* dstH = (uint4*)sB_hi;
            uint4* dstL = (uint4*)sB_lo;
            for (int j = tid; j < 512; j += 256) {
                dstH[j] = srcH[j];
                dstL[j] = srcL[j];
            }
        }

        // ---- bilinear coefficients for (px, tap) ----
        const int obase = (b*9 + t)*HW_ + gpix;
        const float m  = g_mask[obase];
        const int ky = t / 3, kx = t - ky*3;
        const float sy = g_dy[obase] + (float)(ky + tile - 1);
        const float sx = g_dx[obase] + (float)(kx + px   - 1);

        const float y0f = floorf(sy), x0f = floorf(sx);
        const int iy0 = (int)y0f, ix0 = (int)x0f;
        const float wy1 = sy - y0f, wx1 = sx - x0f;
        const float wy0 = 1.f - wy1, wx0 = 1.f - wx1;

        const bool py0 = (iy0   >= 0) && (iy0   < H_);
        const bool py1 = (iy0+1 >= 0) && (iy0+1 < H_);
        const bool pxv0 = (ix0   >= 0) && (ix0   < W_);
        const bool pxv1 = (ix0+1 >= 0) && (ix0+1 < W_);

        const int y0c = min(max(iy0,   0), H_-1);
        const int y1c = min(max(iy0+1, 0), H_-1);
        const int x0c = min(max(ix0,   0), W_-1);
        const int x1c = min(max(ix0+1, 0), W_-1);

        const int o00 = y0c*W_ + x0c, o01 = y0c*W_ + x1c;
        const int o10 = y1c*W_ + x0c, o11 = y1c*W_ + x1c;

        const float c00 = (py0 && pxv0) ? wy0*wx0*m : 0.f;
        const float c01 = (py0 && pxv1) ? wy0*wx1*m : 0.f;
        const float c10 = (py1 && pxv0) ? wy1*wx0*m : 0.f;
        const float c11 = (py1 && pxv1) ? wy1*wx1*m : 0.f;

        // ---- A tile: 32 channels per thread, bf16 hi/lo, swizzled STS.128 ----
        #pragma unroll
        for (int mch = 0; mch < 4; mch++) {
            const int cb = grp*32 + mch*8;
            float v[8];
            #pragma unroll
            for (int e = 0; e < 8; e++) {
                const float* xp = xb + (cb + e)*HW_;
                float a0 = xp[o00], a1 = xp[o01], a2 = xp[o10], a3 = xp[o11];
                v[e] = fmaf(c01, a1, c00*a0) + fmaf(c11, a3, c10*a2);
            }
            uint4 hv, lv;
            unsigned hs[4], ls[4];
            #pragma unroll
            for (int pr = 0; pr < 4; pr++) {
                unsigned short h0 = bf16_bits(v[2*pr]);
                unsigned short h1 = bf16_bits(v[2*pr+1]);
                unsigned short l0 = bf16_bits(v[2*pr]   - bf16_val(h0));
                unsigned short l1 = bf16_bits(v[2*pr+1] - bf16_val(h1));
                hs[pr] = (unsigned)h0 | ((unsigned)h1 << 16);
                ls[pr] = (unsigned)l0 | ((unsigned)l1 << 16);
            }
            hv.x = hs[0]; hv.y = hs[1]; hv.z = hs[2]; hv.w = hs[3];
            lv.x = ls[0]; lv.y = ls[1]; lv.z = ls[2]; lv.w = ls[3];
            const int chunk = grp*4 + mch;                    // 16B chunk 0..7
            const unsigned off = (unsigned)(px*128 + 16*(chunk ^ (px & 7)));
            *(uint4*)(sA + off)         = hv;
            *(uint4*)(sA + 16384 + off) = lv;
        }

        __syncthreads();

        // ---- mma phase: warp wp covers pixels wp*16..wp*16+15 ----
        #pragma unroll
        for (int kc = 0; kc < 4; kc++) {
            const int prow = wp*16 + (lane & 15);
            const int chnk = 2*kc + (lane >> 4);
            const unsigned aoff = sAu + (unsigned)(prow*128 + 16*(chnk ^ (prow & 7)));
            unsigned ah0, ah1, ah2, ah3, al0, al1, al2, al3;
            asm volatile("ldmatrix.sync.aligned.m8n8.x4.shared.b16 {%0,%1,%2,%3}, [%4];"
                         : "=r"(ah0), "=r"(ah1), "=r"(ah2), "=r"(ah3) : "r"(aoff));
            asm volatile("ldmatrix.sync.aligned.m8n8.x4.shared.b16 {%0,%1,%2,%3}, [%4];"
                         : "=r"(al0), "=r"(al1), "=r"(al2), "=r"(al3) : "r"(aoff + 16384u));

            #pragma unroll
            for (int nt = 0; nt < 8; nt++) {
                const uint2 bh = sB_hi[(kc*8 + nt)*32 + lane];
                const uint2 bl = sB_lo[(kc*8 + nt)*32 + lane];
                float* d = acc[nt];
                asm volatile(
                    "mma.sync.aligned.m16n8k16.row.col.f32.bf16.bf16.f32 "
                    "{%0,%1,%2,%3}, {%4,%5,%6,%7}, {%8,%9}, {%0,%1,%2,%3};"
                    : "+f"(d[0]), "+f"(d[1]), "+f"(d[2]), "+f"(d[3])
                    : "r"(ah0), "r"(ah1), "r"(ah2), "r"(ah3), "r"(bh.x), "r"(bh.y));
                asm volatile(
                    "mma.sync.aligned.m16n8k16.row.col.f32.bf16.bf16.f32 "
                    "{%0,%1,%2,%3}, {%4,%5,%6,%7}, {%8,%9}, {%0,%1,%2,%3};"
                    : "+f"(d[0]), "+f"(d[1]), "+f"(d[2]), "+f"(d[3])
                    : "r"(ah0), "r"(ah1), "r"(ah2), "r"(ah3), "r"(bl.x), "r"(bl.y));
                asm volatile(
                    "mma.sync.aligned.m16n8k16.row.col.f32.bf16.bf16.f32 "
                    "{%0,%1,%2,%3}, {%4,%5,%6,%7}, {%8,%9}, {%0,%1,%2,%3};"
                    : "+f"(d[0]), "+f"(d[1]), "+f"(d[2]), "+f"(d[3])
                    : "r"(al0), "r"(al1), "r"(al2), "r"(al3), "r"(bh.x), "r"(bh.y));
            }
        }

        __syncthreads();
    }

    // ---- epilogue: D fragments -> global ----
    {
        const int r0 = lane >> 2;
        const int cp = (lane & 3)*2;
        float* obase = out + (size_t)(b*O_)*HW_ + tile*128 + wp*16;
        #pragma unroll
        for (int nt = 0; nt < 8; nt++) {
            const int o = nt*8 + cp;
            const float bi0 = bias[o], bi1 = bias[o+1];
            obase[(size_t)o*HW_     + r0    ] = acc[nt][0] + bi0;
            obase[(size_t)(o+1)*HW_ + r0    ] = acc[nt][1] + bi1;
            obase[(size_t)o*HW_     + r0 + 8] = acc[nt][2] + bi0;
            obase[(size_t)(o+1)*HW_ + r0 + 8] = acc[nt][3] + bi1;
        }
    }
}

// ---------------- launch ----------------
extern "C" void kernel_launch(void* const* d_in, const int* in_sizes, int n_in,
                              void* d_out, int out_size) {
    const float* x      = (const float*)d_in[0];
    const float* w_om   = (const float*)d_in[1];
    const float* b_om   = (const float*)d_in[2];
    const float* weight = (const float*)d_in[3];
    const float* bias   = (const float*)d_in[4];
    float* out = (float*)d_out;

    const int SMEM_A = (CK_*28) * 4;              // 64512
    cudaFuncSetAttribute(offset_conv, cudaFuncAttributeMaxDynamicSharedMemorySize, SMEM_A);
    cudaFuncSetAttribute(offset_conv, cudaFuncAttributePreferredSharedMemoryCarveout, 100);
    cudaFuncSetAttribute(deform_mma,  cudaFuncAttributePreferredSharedMemoryCarveout, 100);

    offset_conv<<<256, 256, SMEM_A>>>(x, w_om, b_om, weight);
    deform_mma<<<512, 256>>>(x, bias, out);
}

// round 9
// speedup vs baseline: 1.6688x; 1.0190x over previous
#include <cuda_runtime.h>
#include <cuda_bf16.h>
#include <math.h>

// Problem constants (fixed by the reference)
#define B_  4
#define C_  64
#define O_  64
#define H_  128
#define W_  128
#define K2_ 9
#define HW_ (H_*W_)
#define CK_ (C_*K2_)          // 576

// ---------------- scratch (no allocations allowed) ----------------
// Main weight pre-arranged in mma.sync B-fragment layout:
// entry idx = ((t*4 + kc)*8 + nt)*32 + lane ; .x = k-pair (lane%4)*2, .y = +8
__device__ uint2 g_wB_hi[9*4*8*32];
__device__ uint2 g_wB_lo[9*4*8*32];
__device__ float g_dy   [B_*K2_*HW_];
__device__ float g_dx   [B_*K2_*HW_];
__device__ float g_mask [B_*K2_*HW_];

// ---------------- packed f32x2 FMA (sm_100+) ----------------
__device__ __forceinline__ unsigned long long fma2(unsigned long long a,
                                                   unsigned long long b,
                                                   unsigned long long c) {
    unsigned long long d;
    asm("fma.rn.f32x2 %0, %1, %2, %3;" : "=l"(d) : "l"(a), "l"(b), "l"(c));
    return d;
}
__device__ __forceinline__ unsigned long long splat2(float v) {
    unsigned long long d;
    asm("mov.b64 %0, {%1, %1};" : "=l"(d) : "f"(v));
    return d;
}

__device__ __forceinline__ unsigned smem_u32(const void* p) {
    unsigned a;
    asm("{ .reg .u64 t; cvta.to.shared.u64 t, %1; cvt.u32.u64 %0, t; }"
        : "=r"(a) : "l"(p));
    return a;
}

__device__ __forceinline__ unsigned short bf16_bits(float v) {
    __nv_bfloat16 h = __float2bfloat16(v);
    return *reinterpret_cast<unsigned short*>(&h);
}
__device__ __forceinline__ float bf16_val(unsigned short u) {
    __nv_bfloat16 h = *reinterpret_cast<__nv_bfloat16*>(&u);
    return __bfloat162float(h);
}

// ---------------- kernel 1: offset/mask conv + B-fragment weight prep ----------------
// 256 CTAs x 128 threads, TWO horizontal pixels per thread: each weight
// LDS.128 feeds 14 fma2 (was 7), and the two 3x3 windows share 6/12 loads.
__global__ void __launch_bounds__(128)
offset_conv(const float* __restrict__ x, const float* __restrict__ w_om,
            const float* __restrict__ b_om, const float* __restrict__ weight) {
    extern __shared__ float wA[];     // 576*28 floats = 64512 B

    const int tid = threadIdx.x;

    // --- main weight -> mma B-fragment layout, bf16 hi/lo split ---
    {
        int i = blockIdx.x*128 + tid;           // 32768 threads cover 9216
        if (i < 9216) {
            int t    = i / 1024;
            int r    = i - t*1024;
            int kc   = r >> 8;
            int r2   = r & 255;
            int nt   = r2 >> 5;
            int lane = r2 & 31;
            int n  = nt*8 + (lane >> 2);
            int kb = (lane & 3)*2;
            unsigned hv[2], lv[2];
            #pragma unroll
            for (int u = 0; u < 2; u++) {
                int c0 = kc*16 + kb + u*8;
                float w0 = weight[n*CK_ + c0*9 + t];
                float w1 = weight[n*CK_ + (c0+1)*9 + t];
                unsigned short h0 = bf16_bits(w0);
                unsigned short h1 = bf16_bits(w1);
                unsigned short l0 = bf16_bits(w0 - bf16_val(h0));
                unsigned short l1 = bf16_bits(w1 - bf16_val(h1));
                hv[u] = (unsigned)h0 | ((unsigned)h1 << 16);
                lv[u] = (unsigned)l0 | ((unsigned)l1 << 16);
            }
            uint2 hi; hi.x = hv[0]; hi.y = hv[1];
            uint2 lo; lo.x = lv[0]; lo.y = lv[1];
            g_wB_hi[i] = hi;
            g_wB_lo[i] = lo;
        }
    }

    // offset-conv weight: w_om[r][ck] -> wA[ck][28] (pad zeroed)
    for (int i = tid; i < 27*CK_; i += 128) {
        int r = i / CK_, ck = i - r*CK_;
        wA[ck*28 + r] = w_om[i];
    }
    for (int ck = tid; ck < CK_; ck += 128) wA[ck*28 + 27] = 0.f;
    __syncthreads();

    const int p2   = blockIdx.x*128 + tid;    // pair index 0..32767
    const int b    = p2 >> 13;
    const int pix  = (p2 & 8191)*2;           // even pixel within image
    const int y    = pix >> 7, x0 = pix & 127;
    const float* xb = x + (size_t)b*C_*HW_;

    const bool vy0 = (y  > 0), vy2 = (y < H_-1);
    const bool vcl = (x0 > 0), vcr = (x0 < 126);
    const int base00 = (y-1)*W_ + (x0-1);

    unsigned long long acc0[14], acc1[14];
    #pragma unroll
    for (int j = 0; j < 14; j++) { acc0[j] = 0ull; acc1[j] = 0ull; }

    for (int c = 0; c < C_; c++) {
        const float* xp = xb + c*HW_ + base00;
        float v[12];                          // 3 rows x 4 cols
        #pragma unroll
        for (int r = 0; r < 3; r++) {
            const bool vr = (r == 0) ? vy0 : (r == 2) ? vy2 : true;
            const float* row = xp + r*W_;
            v[r*4+0] = (vr && vcl) ? row[0] : 0.f;
            v[r*4+1] =  vr         ? row[1] : 0.f;
            v[r*4+2] =  vr         ? row[2] : 0.f;
            v[r*4+3] = (vr && vcr) ? row[3] : 0.f;
        }

        const float* wc = wA + c*9*28;
        #pragma unroll
        for (int ty = 0; ty < 3; ty++) {
            #pragma unroll
            for (int tx = 0; tx < 3; tx++) {
                unsigned long long vv0 = splat2(v[ty*4 + tx]);
                unsigned long long vv1 = splat2(v[ty*4 + tx + 1]);
                const ulonglong2* wr = (const ulonglong2*)(wc + (ty*3 + tx)*28);
                #pragma unroll
                for (int q = 0; q < 7; q++) {
                    ulonglong2 w4 = wr[q];
                    acc0[2*q]   = fma2(vv0, w4.x, acc0[2*q]);
                    acc0[2*q+1] = fma2(vv0, w4.y, acc0[2*q+1]);
                    acc1[2*q]   = fma2(vv1, w4.x, acc1[2*q]);
                    acc1[2*q+1] = fma2(vv1, w4.y, acc1[2*q+1]);
                }
            }
        }
    }

    float a0[28], a1[28];
    #pragma unroll
    for (int j = 0; j < 14; j++) {
        a0[2*j]   = __uint_as_float((unsigned)(acc0[j] & 0xffffffffULL));
        a0[2*j+1] = __uint_as_float((unsigned)(acc0[j] >> 32));
        a1[2*j]   = __uint_as_float((unsigned)(acc1[j] & 0xffffffffULL));
        a1[2*j+1] = __uint_as_float((unsigned)(acc1[j] >> 32));
    }
    #pragma unroll
    for (int k = 0; k < 9; k++) {
        const int base = (b*9 + k)*HW_ + pix;
        float by = b_om[2*k], bx = b_om[2*k+1], bm = b_om[18+k];
        float2 dy2; dy2.x = a0[2*k]   + by; dy2.y = a1[2*k]   + by;
        float2 dx2; dx2.x = a0[2*k+1] + bx; dx2.y = a1[2*k+1] + bx;
        float m0 = a0[18+k] + bm, m1 = a1[18+k] + bm;
        float2 mk2;
        mk2.x = 1.f / (1.f + __expf(-m0));
        mk2.y = 1.f / (1.f + __expf(-m1));
        *(float2*)&g_dy[base]   = dy2;
        *(float2*)&g_dx[base]   = dx2;
        *(float2*)&g_mask[base] = mk2;
    }
}

// ---------------- kernel 2: implicit GEMM via mma.sync (bf16 3-pass) ----------------
// M=64-pixel tiles, 128 threads, 7 CTAs/SM (32 KB SMEM) -> grid 1024 fits in
// ONE wave (148*7=1036 slots) with 28 warps/SM for latency hiding.
__global__ void __launch_bounds__(128, 7)
deform_mma(const float* __restrict__ x, const float* __restrict__ bias,
           float* __restrict__ out) {
    __shared__ __align__(16) unsigned char sA[16384];   // hi @0, lo @8192
    __shared__ uint2 sB_hi[1024];                       // 8 KB
    __shared__ uint2 sB_lo[1024];                       // 8 KB

    const int tid  = threadIdx.x;
    const int lane = tid & 31;
    const int wp   = tid >> 5;          // warp 0..3 -> pixels wp*16..+15
    const int b    = blockIdx.x >> 8;
    const int tile = blockIdx.x & 255;  // 64-pixel tile
    const float* xb = x + (size_t)b*C_*HW_;

    const int px  = tid & 63;           // gather pixel within tile
    const int grp = tid >> 6;           // channel half 0/1
    const int gpix = tile*64 + px;
    const int y   = gpix >> 7, xq = gpix & 127;

    const unsigned sAu = smem_u32(sA);

    float acc[8][4];
    #pragma unroll
    for (int nt = 0; nt < 8; nt++)
        #pragma unroll
        for (int j = 0; j < 4; j++) acc[nt][j] = 0.f;

    #pragma unroll 1
    for (int t = 0; t < 9; t++) {
        // ---- B fragments for this tap: global -> SMEM (8 KB each) ----
        {
            const uint4* srcH = (const uint4*)(g_wB_hi + t*1024);
            const uint4* srcL = (const uint4*)(g_wB_lo + t*1024);
            uint4* dstH = (uint4*)sB_hi;
            uint4* dstL = (uint4*)sB_lo;
            #pragma unroll
            for (int j = tid; j < 512; j += 128) {
                dstH[j] = srcH[j];
                dstL[j] = srcL[j];
            }
        }

        // ---- bilinear coefficients for (px, tap) ----
        const int obase = (b*9 + t)*HW_ + gpix;
        const float m  = g_mask[obase];
        const int ky = t / 3, kx = t - ky*3;
        const float sy = g_dy[obase] + (float)(ky + y  - 1);
        const float sx = g_dx[obase] + (float)(kx + xq - 1);

        const float y0f = floorf(sy), x0f = floorf(sx);
        const int iy0 = (int)y0f, ix0 = (int)x0f;
        const float wy1 = sy - y0f, wx1 = sx - x0f;
        const float wy0 = 1.f - wy1, wx0 = 1.f - wx1;

        const bool py0 = (iy0   >= 0) && (iy0   < H_);
        const bool py1 = (iy0+1 >= 0) && (iy0+1 < H_);
        const bool pxv0 = (ix0   >= 0) && (ix0   < W_);
        const bool pxv1 = (ix0+1 >= 0) && (ix0+1 < W_);

        const int y0c = min(max(iy0,   0), H_-1);
        const int y1c = min(max(iy0+1, 0), H_-1);
        const int x0c = min(max(ix0,   0), W_-1);
        const int x1c = min(max(ix0+1, 0), W_-1);

        const int o00 = y0c*W_ + x0c, o01 = y0c*W_ + x1c;
        const int o10 = y1c*W_ + x0c, o11 = y1c*W_ + x1c;

        const float c00 = (py0 && pxv0) ? wy0*wx0*m : 0.f;
        const float c01 = (py0 && pxv1) ? wy0*wx1*m : 0.f;
        const float c10 = (py1 && pxv0) ? wy1*wx0*m : 0.f;
        const float c11 = (py1 && pxv1) ? wy1*wx1*m : 0.f;

        // ---- A tile: 32 channels per thread, bf16 hi/lo, swizzled STS.128 ----
        #pragma unroll
        for (int mch = 0; mch < 4; mch++) {
            const int cb = grp*32 + mch*8;
            float v[8];
            #pragma unroll
            for (int e = 0; e < 8; e++) {
                const float* xp = xb + (cb + e)*HW_;
                float a0 = xp[o00], a1 = xp[o01], a2 = xp[o10], a3 = xp[o11];
                v[e] = fmaf(c01, a1, c00*a0) + fmaf(c11, a3, c10*a2);
            }
            unsigned hs[4], ls[4];
            #pragma unroll
            for (int pr = 0; pr < 4; pr++) {
                const float v0 = v[2*pr], v1 = v[2*pr+1];
                const unsigned u0 = __float_as_uint(v0), u1 = __float_as_uint(v1);
                unsigned hp;
                asm("prmt.b32 %0, %1, %2, 0x7632;" : "=r"(hp) : "r"(u0), "r"(u1));
                const float rem0 = v0 - __uint_as_float(u0 & 0xFFFF0000u);
                const float rem1 = v1 - __uint_as_float(u1 & 0xFFFF0000u);
                unsigned lp;
                asm("cvt.rn.bf16x2.f32 %0, %1, %2;" : "=r"(lp) : "f"(rem1), "f"(rem0));
                hs[pr] = hp; ls[pr] = lp;
            }
            uint4 hv, lv;
            hv.x = hs[0]; hv.y = hs[1]; hv.z = hs[2]; hv.w = hs[3];
            lv.x = ls[0]; lv.y = ls[1]; lv.z = ls[2]; lv.w = ls[3];
            const int chunk = grp*4 + mch;                    // 16B chunk 0..7
            const unsigned off = (unsigned)(px*128 + 16*(chunk ^ (px & 7)));
            *(uint4*)(sA + off)        = hv;
            *(uint4*)(sA + 8192 + off) = lv;
        }

        __syncthreads();

        // ---- mma phase: warp wp covers pixels wp*16..wp*16+15 ----
        #pragma unroll
        for (int kc = 0; kc < 4; kc++) {
            const int prow = wp*16 + (lane & 15);
            const int chnk = 2*kc + (lane >> 4);
            const unsigned aoff = sAu + (unsigned)(prow*128 + 16*(chnk ^ (prow & 7)));
            unsigned ah0, ah1, ah2, ah3, al0, al1, al2, al3;
            asm volatile("ldmatrix.sync.aligned.m8n8.x4.shared.b16 {%0,%1,%2,%3}, [%4];"
                         : "=r"(ah0), "=r"(ah1), "=r"(ah2), "=r"(ah3) : "r"(aoff));
            asm volatile("ldmatrix.sync.aligned.m8n8.x4.shared.b16 {%0,%1,%2,%3}, [%4];"
                         : "=r"(al0), "=r"(al1), "=r"(al2), "=r"(al3) : "r"(aoff + 8192u));

            #pragma unroll
            for (int nt = 0; nt < 8; nt++) {
                const uint2 bh = sB_hi[(kc*8 + nt)*32 + lane];
                const uint2 bl = sB_lo[(kc*8 + nt)*32 + lane];
                float* d = acc[nt];
                asm volatile(
                    "mma.sync.aligned.m16n8k16.row.col.f32.bf16.bf16.f32 "
                    "{%0,%1,%2,%3}, {%4,%5,%6,%7}, {%8,%9}, {%0,%1,%2,%3};"
                    : "+f"(d[0]), "+f"(d[1]), "+f"(d[2]), "+f"(d[3])
                    : "r"(ah0), "r"(ah1), "r"(ah2), "r"(ah3), "r"(bh.x), "r"(bh.y));
                asm volatile(
                    "mma.sync.aligned.m16n8k16.row.col.f32.bf16.bf16.f32 "
                    "{%0,%1,%2,%3}, {%4,%5,%6,%7}, {%8,%9}, {%0,%1,%2,%3};"
                    : "+f"(d[0]), "+f"(d[1]), "+f"(d[2]), "+f"(d[3])
                    : "r"(ah0), "r"(ah1), "r"(ah2), "r"(ah3), "r"(bl.x), "r"(bl.y));
                asm volatile(
                    "mma.sync.aligned.m16n8k16.row.col.f32.bf16.bf16.f32 "
                    "{%0,%1,%2,%3}, {%4,%5,%6,%7}, {%8,%9}, {%0,%1,%2,%3};"
                    : "+f"(d[0]), "+f"(d[1]), "+f"(d[2]), "+f"(d[3])
                    : "r"(al0), "r"(al1), "r"(al2), "r"(al3), "r"(bh.x), "r"(bh.y));
            }
        }

        __syncthreads();
    }

    // ---- epilogue: D fragments -> global ----
    {
        const int r0 = lane >> 2;
        const int cp = (lane & 3)*2;
        float* obase = out + (size_t)(b*O_)*HW_ + tile*64 + wp*16;
        #pragma unroll
        for (int nt = 0; nt < 8; nt++) {
            const int o = nt*8 + cp;
            const float bi0 = bias[o], bi1 = bias[o+1];
            obase[(size_t)o*HW_     + r0    ] = acc[nt][0] + bi0;
            obase[(size_t)(o+1)*HW_ + r0    ] = acc[nt][1] + bi1;
            obase[(size_t)o*HW_     + r0 + 8] = acc[nt][2] + bi0;
            obase[(size_t)(o+1)*HW_ + r0 + 8] = acc[nt][3] + bi1;
        }
    }
}

// ---------------- launch ----------------
extern "C" void kernel_launch(void* const* d_in, const int* in_sizes, int n_in,
                              void* d_out, int out_size) {
    const float* x      = (const float*)d_in[0];
    const float* w_om   = (const float*)d_in[1];
    const float* b_om   = (const float*)d_in[2];
    const float* weight = (const float*)d_in[3];
    const float* bias   = (const float*)d_in[4];
    float* out = (float*)d_out;

    const int SMEM_A = (CK_*28) * 4;              // 64512
    cudaFuncSetAttribute(offset_conv, cudaFuncAttributeMaxDynamicSharedMemorySize, SMEM_A);
    cudaFuncSetAttribute(offset_conv, cudaFuncAttributePreferredSharedMemoryCarveout, 100);
    cudaFuncSetAttribute(deform_mma,  cudaFuncAttributePreferredSharedMemoryCarveout, 100);

    offset_conv<<<256, 128, SMEM_A>>>(x, w_om, b_om, weight);
    deform_mma<<<1024, 128>>>(x, bias, out);
}

// round 10
// speedup vs baseline: 1.9090x; 1.1440x over previous
#include <cuda_runtime.h>
#include <cuda_bf16.h>
#include <cuda_fp16.h>
#include <math.h>

// Problem constants (fixed by the reference)
#define B_  4
#define C_  64
#define O_  64
#define H_  128
#define W_  128
#define K2_ 9
#define HW_ (H_*W_)
#define CK_ (C_*K2_)          // 576

// ---------------- scratch (no allocations allowed) ----------------
// Main weight pre-arranged in mma.sync B-fragment layout:
// entry idx = ((t*4 + kc)*8 + nt)*32 + lane ; .x = k-pair (lane%4)*2, .y = +8
__device__ uint2 g_wB_hi[9*4*8*32];
__device__ uint2 g_wB_lo[9*4*8*32];
__device__ float g_dy   [B_*K2_*HW_];
__device__ float g_dx   [B_*K2_*HW_];
__device__ float g_mask [B_*K2_*HW_];
// x packed as fp16 horizontal pairs: word i = (h(x[i]), h(x[i+1]))
__device__ unsigned g_xw[B_*C_*HW_];

// ---------------- packed f32x2 FMA (sm_100+) ----------------
__device__ __forceinline__ unsigned long long fma2(unsigned long long a,
                                                   unsigned long long b,
                                                   unsigned long long c) {
    unsigned long long d;
    asm("fma.rn.f32x2 %0, %1, %2, %3;" : "=l"(d) : "l"(a), "l"(b), "l"(c));
    return d;
}
__device__ __forceinline__ unsigned long long splat2(float v) {
    unsigned long long d;
    asm("mov.b64 %0, {%1, %1};" : "=l"(d) : "f"(v));
    return d;
}

__device__ __forceinline__ unsigned smem_u32(const void* p) {
    unsigned a;
    asm("{ .reg .u64 t; cvta.to.shared.u64 t, %1; cvt.u32.u64 %0, t; }"
        : "=r"(a) : "l"(p));
    return a;
}

__device__ __forceinline__ unsigned short bf16_bits(float v) {
    __nv_bfloat16 h = __float2bfloat16(v);
    return *reinterpret_cast<unsigned short*>(&h);
}
__device__ __forceinline__ float bf16_val(unsigned short u) {
    __nv_bfloat16 h = *reinterpret_cast<__nv_bfloat16*>(&u);
    return __bfloat162float(h);
}

// ---------------- kernel 1: offset/mask conv + weight prep + x packing ----------------
// 256 CTAs x 128 threads, two horizontal pixels per thread.
__global__ void __launch_bounds__(128)
offset_conv(const float* __restrict__ x, const float* __restrict__ w_om,
            const float* __restrict__ b_om, const float* __restrict__ weight) {
    extern __shared__ float wA[];     // 576*28 floats = 64512 B

    const int tid = threadIdx.x;

    // --- pack x into fp16 pairs (for deform_mma gathers) ---
    {
        const int gid = blockIdx.x*128 + tid;       // 32768 threads
        const int NTOT = B_*C_*HW_;
        for (int i = gid; i < NTOT; i += 32768) {
            float a  = x[i];
            float b2 = x[(i+1 < NTOT) ? i+1 : i];
            __half2 h = __floats2half2_rn(a, b2);
            g_xw[i] = *reinterpret_cast<unsigned*>(&h);
        }
    }

    // --- main weight -> mma B-fragment layout, bf16 hi/lo split ---
    {
        int i = blockIdx.x*128 + tid;               // 32768 threads cover 9216
        if (i < 9216) {
            int t    = i / 1024;
            int r    = i - t*1024;
            int kc   = r >> 8;
            int r2   = r & 255;
            int nt   = r2 >> 5;
            int lane = r2 & 31;
            int n  = nt*8 + (lane >> 2);
            int kb = (lane & 3)*2;
            unsigned hv[2], lv[2];
            #pragma unroll
            for (int u = 0; u < 2; u++) {
                int c0 = kc*16 + kb + u*8;
                float w0 = weight[n*CK_ + c0*9 + t];
                float w1 = weight[n*CK_ + (c0+1)*9 + t];
                unsigned short h0 = bf16_bits(w0);
                unsigned short h1 = bf16_bits(w1);
                unsigned short l0 = bf16_bits(w0 - bf16_val(h0));
                unsigned short l1 = bf16_bits(w1 - bf16_val(h1));
                hv[u] = (unsigned)h0 | ((unsigned)h1 << 16);
                lv[u] = (unsigned)l0 | ((unsigned)l1 << 16);
            }
            uint2 hi; hi.x = hv[0]; hi.y = hv[1];
            uint2 lo; lo.x = lv[0]; lo.y = lv[1];
            g_wB_hi[i] = hi;
            g_wB_lo[i] = lo;
        }
    }

    // offset-conv weight: w_om[r][ck] -> wA[ck][28] (pad zeroed)
    for (int i = tid; i < 27*CK_; i += 128) {
        int r = i / CK_, ck = i - r*CK_;
        wA[ck*28 + r] = w_om[i];
    }
    for (int ck = tid; ck < CK_; ck += 128) wA[ck*28 + 27] = 0.f;
    __syncthreads();

    const int p2   = blockIdx.x*128 + tid;    // pair index 0..32767
    const int b    = p2 >> 13;
    const int pix  = (p2 & 8191)*2;           // even pixel within image
    const int y    = pix >> 7, x0 = pix & 127;
    const float* xb = x + (size_t)b*C_*HW_;

    const bool vy0 = (y  > 0), vy2 = (y < H_-1);
    const bool vcl = (x0 > 0), vcr = (x0 < 126);
    const int base00 = (y-1)*W_ + (x0-1);

    unsigned long long acc0[14], acc1[14];
    #pragma unroll
    for (int j = 0; j < 14; j++) { acc0[j] = 0ull; acc1[j] = 0ull; }

    for (int c = 0; c < C_; c++) {
        const float* xp = xb + c*HW_ + base00;
        float v[12];                          // 3 rows x 4 cols
        #pragma unroll
        for (int r = 0; r < 3; r++) {
            const bool vr = (r == 0) ? vy0 : (r == 2) ? vy2 : true;
            const float* row = xp + r*W_;
            v[r*4+0] = (vr && vcl) ? row[0] : 0.f;
            v[r*4+1] =  vr         ? row[1] : 0.f;
            v[r*4+2] =  vr         ? row[2] : 0.f;
            v[r*4+3] = (vr && vcr) ? row[3] : 0.f;
        }

        const float* wc = wA + c*9*28;
        #pragma unroll
        for (int ty = 0; ty < 3; ty++) {
            #pragma unroll
            for (int tx = 0; tx < 3; tx++) {
                unsigned long long vv0 = splat2(v[ty*4 + tx]);
                unsigned long long vv1 = splat2(v[ty*4 + tx + 1]);
                const ulonglong2* wr = (const ulonglong2*)(wc + (ty*3 + tx)*28);
                #pragma unroll
                for (int q = 0; q < 7; q++) {
                    ulonglong2 w4 = wr[q];
                    acc0[2*q]   = fma2(vv0, w4.x, acc0[2*q]);
                    acc0[2*q+1] = fma2(vv0, w4.y, acc0[2*q+1]);
                    acc1[2*q]   = fma2(vv1, w4.x, acc1[2*q]);
                    acc1[2*q+1] = fma2(vv1, w4.y, acc1[2*q+1]);
                }
            }
        }
    }

    float a0[28], a1[28];
    #pragma unroll
    for (int j = 0; j < 14; j++) {
        a0[2*j]   = __uint_as_float((unsigned)(acc0[j] & 0xffffffffULL));
        a0[2*j+1] = __uint_as_float((unsigned)(acc0[j] >> 32));
        a1[2*j]   = __uint_as_float((unsigned)(acc1[j] & 0xffffffffULL));
        a1[2*j+1] = __uint_as_float((unsigned)(acc1[j] >> 32));
    }
    #pragma unroll
    for (int k = 0; k < 9; k++) {
        const int base = (b*9 + k)*HW_ + pix;
        float by = b_om[2*k], bx = b_om[2*k+1], bm = b_om[18+k];
        float2 dy2; dy2.x = a0[2*k]   + by; dy2.y = a1[2*k]   + by;
        float2 dx2; dx2.x = a0[2*k+1] + bx; dx2.y = a1[2*k+1] + bx;
        float m0 = a0[18+k] + bm, m1 = a1[18+k] + bm;
        float2 mk2;
        mk2.x = 1.f / (1.f + __expf(-m0));
        mk2.y = 1.f / (1.f + __expf(-m1));
        *(float2*)&g_dy[base]   = dy2;
        *(float2*)&g_dx[base]   = dx2;
        *(float2*)&g_mask[base] = mk2;
    }
}

// ---------------- kernel 2: implicit GEMM via mma.sync (bf16 3-pass) ----------------
// M=128 pixels x N=64, K=576. Gathers use fp16-pair words: ONE LDG.32 per
// sample row (2 per channel instead of 4), with per-tap coefficient remap
// (cL/cR per row) absorbing all clamp cases.
__global__ void __launch_bounds__(256, 3)
deform_mma(const float* __restrict__ bias, float* __restrict__ out) {
    __shared__ __align__(16) unsigned char sA[32768];   // hi @0, lo @16384
    __shared__ uint2 sB_hi[1024];                       // 8 KB
    __shared__ uint2 sB_lo[1024];                       // 8 KB

    const int tid  = threadIdx.x;
    const int lane = tid & 31;
    const int wp   = tid >> 5;          // warp 0..7 -> pixels wp*16..+15
    const int b    = blockIdx.x >> 7;
    const int tile = blockIdx.x & 127;  // image row
    const unsigned* xwb = g_xw + (size_t)b*C_*HW_;

    const int px  = tid & 127;          // gather pixel
    const int grp = tid >> 7;           // channel half 0/1
    const int gpix = tile*128 + px;

    const unsigned sAu = smem_u32(sA);

    float acc[8][4];
    #pragma unroll
    for (int nt = 0; nt < 8; nt++)
        #pragma unroll
        for (int j = 0; j < 4; j++) acc[nt][j] = 0.f;

    #pragma unroll 1
    for (int t = 0; t < 9; t++) {
        // ---- B fragments for this tap: global -> SMEM (8 KB each) ----
        {
            const uint4* srcH = (const uint4*)(g_wB_hi + t*1024);
            const uint4* srcL = (const uint4*)(g_wB_lo + t*1024);
            uint4* dstH = (uint4*)sB_hi;
            uint4* dstL = (uint4*)sB_lo;
            for (int j = tid; j < 512; j += 256) {
                dstH[j] = srcH[j];
                dstL[j] = srcL[j];
            }
        }

        // ---- bilinear coefficients for (px, tap) ----
        const int obase = (b*9 + t)*HW_ + gpix;
        const float m  = g_mask[obase];
        const int ky = t / 3, kx = t - ky*3;
        const float sy = g_dy[obase] + (float)(ky + tile - 1);
        const float sx = g_dx[obase] + (float)(kx + px   - 1);

        const float y0f = floorf(sy), x0f = floorf(sx);
        const int iy0 = (int)y0f, ix0 = (int)x0f;
        const float wy1 = sy - y0f, wx1 = sx - x0f;
        const float wy0 = 1.f - wy1, wx0 = 1.f - wx1;

        const bool py0 = (iy0   >= 0) && (iy0   < H_);
        const bool py1 = (iy0+1 >= 0) && (iy0+1 < H_);
        const bool pxv0 = (ix0   >= 0) && (ix0   < W_);
        const bool pxv1 = (ix0+1 >= 0) && (ix0+1 < W_);

        const int y0c = min(max(iy0,   0), H_-1);
        const int y1c = min(max(iy0+1, 0), H_-1);
        const int x0c = min(max(ix0,   0), W_-1);
        const int x1c = min(max(ix0+1, 0), W_-1);

        const float c00 = (py0 && pxv0) ? wy0*wx0*m : 0.f;
        const float c01 = (py0 && pxv1) ? wy0*wx1*m : 0.f;
        const float c10 = (py1 && pxv0) ? wy1*wx0*m : 0.f;
        const float c11 = (py1 && pxv1) ? wy1*wx1*m : 0.f;

        // map x taps onto pair word at xbase (x0c, x1c ∈ {xbase, xbase+1})
        const int xbase = min(max(ix0, 0), W_-2);
        const bool aL = (x0c == xbase);
        const bool bL = (x1c == xbase);
        const float cLt = (aL ? c00 : 0.f) + (bL ? c01 : 0.f);
        const float cRt = (aL ? 0.f : c00) + (bL ? 0.f : c01);
        const float cLb = (aL ? c10 : 0.f) + (bL ? c11 : 0.f);
        const float cRb = (aL ? 0.f : c10) + (bL ? 0.f : c11);
        const int oT = y0c*W_ + xbase;
        const int oB = y1c*W_ + xbase;

        // ---- A tile: 32 channels per thread, 2 LDG.32 per channel ----
        #pragma unroll
        for (int mch = 0; mch < 4; mch++) {
            const int cb = grp*32 + mch*8;
            unsigned wT[8], wB[8];
            #pragma unroll
            for (int e = 0; e < 8; e++) {
                const unsigned* xw = xwb + (size_t)(cb + e)*HW_;
                wT[e] = xw[oT];
                wB[e] = xw[oB];
            }
            float v[8];
            #pragma unroll
            for (int e = 0; e < 8; e++) {
                float2 tf = __half22float2(*(const __half2*)&wT[e]);
                float2 bf = __half22float2(*(const __half2*)&wB[e]);
                v[e] = fmaf(cRt, tf.y, cLt*tf.x) + fmaf(cRb, bf.y, cLb*bf.x);
            }
            unsigned hs[4], ls[4];
            #pragma unroll
            for (int pr = 0; pr < 4; pr++) {
                const float v0 = v[2*pr], v1 = v[2*pr+1];
                const unsigned u0 = __float_as_uint(v0), u1 = __float_as_uint(v1);
                unsigned hp;
                asm("prmt.b32 %0, %1, %2, 0x7632;" : "=r"(hp) : "r"(u0), "r"(u1));
                const float rem0 = v0 - __uint_as_float(u0 & 0xFFFF0000u);
                const float rem1 = v1 - __uint_as_float(u1 & 0xFFFF0000u);
                unsigned lp;
                asm("cvt.rn.bf16x2.f32 %0, %1, %2;" : "=r"(lp) : "f"(rem1), "f"(rem0));
                hs[pr] = hp; ls[pr] = lp;
            }
            uint4 hv, lv;
            hv.x = hs[0]; hv.y = hs[1]; hv.z = hs[2]; hv.w = hs[3];
            lv.x = ls[0]; lv.y = ls[1]; lv.z = ls[2]; lv.w = ls[3];
            const int chunk = grp*4 + mch;                    // 16B chunk 0..7
            const unsigned off = (unsigned)(px*128 + 16*(chunk ^ (px & 7)));
            *(uint4*)(sA + off)         = hv;
            *(uint4*)(sA + 16384 + off) = lv;
        }

        __syncthreads();

        // ---- mma phase: warp wp covers pixels wp*16..wp*16+15 ----
        #pragma unroll
        for (int kc = 0; kc < 4; kc++) {
            const int prow = wp*16 + (lane & 15);
            const int chnk = 2*kc + (lane >> 4);
            const unsigned aoff = sAu + (unsigned)(prow*128 + 16*(chnk ^ (prow & 7)));
            unsigned ah0, ah1, ah2, ah3, al0, al1, al2, al3;
            asm volatile("ldmatrix.sync.aligned.m8n8.x4.shared.b16 {%0,%1,%2,%3}, [%4];"
                         : "=r"(ah0), "=r"(ah1), "=r"(ah2), "=r"(ah3) : "r"(aoff));
            asm volatile("ldmatrix.sync.aligned.m8n8.x4.shared.b16 {%0,%1,%2,%3}, [%4];"
                         : "=r"(al0), "=r"(al1), "=r"(al2), "=r"(al3) : "r"(aoff + 16384u));

            #pragma unroll
            for (int nt = 0; nt < 8; nt++) {
                const uint2 bh = sB_hi[(kc*8 + nt)*32 + lane];
                const uint2 bl = sB_lo[(kc*8 + nt)*32 + lane];
                float* d = acc[nt];
                asm volatile(
                    "mma.sync.aligned.m16n8k16.row.col.f32.bf16.bf16.f32 "
                    "{%0,%1,%2,%3}, {%4,%5,%6,%7}, {%8,%9}, {%0,%1,%2,%3};"
                    : "+f"(d[0]), "+f"(d[1]), "+f"(d[2]), "+f"(d[3])
                    : "r"(ah0), "r"(ah1), "r"(ah2), "r"(ah3), "r"(bh.x), "r"(bh.y));
                asm volatile(
                    "mma.sync.aligned.m16n8k16.row.col.f32.bf16.bf16.f32 "
                    "{%0,%1,%2,%3}, {%4,%5,%6,%7}, {%8,%9}, {%0,%1,%2,%3};"
                    : "+f"(d[0]), "+f"(d[1]), "+f"(d[2]), "+f"(d[3])
                    : "r"(ah0), "r"(ah1), "r"(ah2), "r"(ah3), "r"(bl.x), "r"(bl.y));
                asm volatile(
                    "mma.sync.aligned.m16n8k16.row.col.f32.bf16.bf16.f32 "
                    "{%0,%1,%2,%3}, {%4,%5,%6,%7}, {%8,%9}, {%0,%1,%2,%3};"
                    : "+f"(d[0]), "+f"(d[1]), "+f"(d[2]), "+f"(d[3])
                    : "r"(al0), "r"(al1), "r"(al2), "r"(al3), "r"(bh.x), "r"(bh.y));
            }
        }

        __syncthreads();
    }

    // ---- epilogue: D fragments -> global ----
    {
        const int r0 = lane >> 2;
        const int cp = (lane & 3)*2;
        float* obase = out + (size_t)(b*O_)*HW_ + tile*128 + wp*16;
        #pragma unroll
        for (int nt = 0; nt < 8; nt++) {
            const int o = nt*8 + cp;
            const float bi0 = bias[o], bi1 = bias[o+1];
            obase[(size_t)o*HW_     + r0    ] = acc[nt][0] + bi0;
            obase[(size_t)(o+1)*HW_ + r0    ] = acc[nt][1] + bi1;
            obase[(size_t)o*HW_     + r0 + 8] = acc[nt][2] + bi0;
            obase[(size_t)(o+1)*HW_ + r0 + 8] = acc[nt][3] + bi1;
        }
    }
}

// ---------------- launch ----------------
extern "C" void kernel_launch(void* const* d_in, const int* in_sizes, int n_in,
                              void* d_out, int out_size) {
    const float* x      = (const float*)d_in[0];
    const float* w_om   = (const float*)d_in[1];
    const float* b_om   = (const float*)d_in[2];
    const float* weight = (const float*)d_in[3];
    const float* bias   = (const float*)d_in[4];
    float* out = (float*)d_out;

    const int SMEM_A = (CK_*28) * 4;              // 64512
    cudaFuncSetAttribute(offset_conv, cudaFuncAttributeMaxDynamicSharedMemorySize, SMEM_A);
    cudaFuncSetAttribute(offset_conv, cudaFuncAttributePreferredSharedMemoryCarveout, 100);
    cudaFuncSetAttribute(deform_mma,  cudaFuncAttributePreferredSharedMemoryCarveout, 100);

    offset_conv<<<256, 128, SMEM_A>>>(x, w_om, b_om, weight);
    deform_mma<<<512, 256>>>(bias, out);
}

// round 11
// speedup vs baseline: 2.0704x; 1.0845x over previous
#include <cuda_runtime.h>
#include <cuda_bf16.h>
#include <cuda_fp16.h>
#include <math.h>

// Problem constants (fixed by the reference)
#define B_  4
#define C_  64
#define O_  64
#define H_  128
#define W_  128
#define K2_ 9
#define HW_ (H_*W_)
#define CK_ (C_*K2_)          // 576

// ---------------- scratch (no allocations allowed) ----------------
// Main weight pre-arranged in mma.sync B-fragment layout (fp16 hi/lo):
// entry idx = ((t*4 + kc)*8 + nt)*32 + lane ; .x = k-pair (lane%4)*2, .y = +8
__device__ uint2 g_wB_hi[9*4*8*32];
__device__ uint2 g_wB_lo[9*4*8*32];
__device__ float g_dy   [B_*K2_*HW_];
__device__ float g_dx   [B_*K2_*HW_];
__device__ float g_mask [B_*K2_*HW_];
// x repacked channel-major fp16: pixel-major, 64 ch contiguous = 128B/pixel
__device__ uint4 g_xc[B_*HW_*8];

// ---------------- packed f32x2 FMA (sm_100+) ----------------
__device__ __forceinline__ unsigned long long fma2(unsigned long long a,
                                                   unsigned long long b,
                                                   unsigned long long c) {
    unsigned long long d;
    asm("fma.rn.f32x2 %0, %1, %2, %3;" : "=l"(d) : "l"(a), "l"(b), "l"(c));
    return d;
}
__device__ __forceinline__ unsigned long long splat2(float v) {
    unsigned long long d;
    asm("mov.b64 %0, {%1, %1};" : "=l"(d) : "f"(v));
    return d;
}

__device__ __forceinline__ unsigned smem_u32(const void* p) {
    unsigned a;
    asm("{ .reg .u64 t; cvta.to.shared.u64 t, %1; cvt.u32.u64 %0, t; }"
        : "=r"(a) : "l"(p));
    return a;
}

__device__ __forceinline__ unsigned short fp16_bits(float v) {
    __half h = __float2half_rn(v);
    return *reinterpret_cast<unsigned short*>(&h);
}
__device__ __forceinline__ float fp16_val(unsigned short u) {
    __half h = *reinterpret_cast<__half*>(&u);
    return __half2float(h);
}

// ---------------- kernel 1: offset/mask conv + weight prep + x transpose ----------------
// 256 CTAs x 128 threads, two horizontal pixels per thread (conv part).
__global__ void __launch_bounds__(128)
offset_conv(const float* __restrict__ x, const float* __restrict__ w_om,
            const float* __restrict__ b_om, const float* __restrict__ weight) {
    extern __shared__ float wA[];     // 576*28 floats = 64512 B

    const int tid = threadIdx.x;

    // --- transpose x into channel-major fp16 (128B per pixel) ---
    {
        const int gid = blockIdx.x*128 + tid;       // 32768 threads, 65536 px
        for (int g = gid; g < B_*HW_; g += 32768) {
            const int b = g >> 14, pix = g & (HW_-1);
            const float* xs = x + (size_t)b*C_*HW_ + pix;
            uint4* dst = g_xc + (size_t)g*8;
            #pragma unroll
            for (int ch = 0; ch < 8; ch++) {
                unsigned w[4];
                #pragma unroll
                for (int j = 0; j < 4; j++) {
                    float v0 = xs[(size_t)(ch*8 + 2*j    )*HW_];
                    float v1 = xs[(size_t)(ch*8 + 2*j + 1)*HW_];
                    __half2 h = __floats2half2_rn(v0, v1);   // v0 -> low
                    w[j] = *reinterpret_cast<unsigned*>(&h);
                }
                uint4 o; o.x = w[0]; o.y = w[1]; o.z = w[2]; o.w = w[3];
                dst[ch] = o;
            }
        }
    }

    // --- main weight -> mma B-fragment layout, fp16 hi/lo split ---
    {
        int i = blockIdx.x*128 + tid;               // 32768 threads cover 9216
        if (i < 9216) {
            int t    = i / 1024;
            int r    = i - t*1024;
            int kc   = r >> 8;
            int r2   = r & 255;
            int nt   = r2 >> 5;
            int lane = r2 & 31;
            int n  = nt*8 + (lane >> 2);
            int kb = (lane & 3)*2;
            unsigned hv[2], lv[2];
            #pragma unroll
            for (int u = 0; u < 2; u++) {
                int c0 = kc*16 + kb + u*8;
                float w0 = weight[n*CK_ + c0*9 + t];
                float w1 = weight[n*CK_ + (c0+1)*9 + t];
                unsigned short h0 = fp16_bits(w0);
                unsigned short h1 = fp16_bits(w1);
                unsigned short l0 = fp16_bits(w0 - fp16_val(h0));
                unsigned short l1 = fp16_bits(w1 - fp16_val(h1));
                hv[u] = (unsigned)h0 | ((unsigned)h1 << 16);
                lv[u] = (unsigned)l0 | ((unsigned)l1 << 16);
            }
            uint2 hi; hi.x = hv[0]; hi.y = hv[1];
            uint2 lo; lo.x = lv[0]; lo.y = lv[1];
            g_wB_hi[i] = hi;
            g_wB_lo[i] = lo;
        }
    }

    // offset-conv weight: w_om[r][ck] -> wA[ck][28] (pad zeroed)
    for (int i = tid; i < 27*CK_; i += 128) {
        int r = i / CK_, ck = i - r*CK_;
        wA[ck*28 + r] = w_om[i];
    }
    for (int ck = tid; ck < CK_; ck += 128) wA[ck*28 + 27] = 0.f;
    __syncthreads();

    const int p2   = blockIdx.x*128 + tid;    // pair index 0..32767
    const int b    = p2 >> 13;
    const int pix  = (p2 & 8191)*2;           // even pixel within image
    const int y    = pix >> 7, x0 = pix & 127;
    const float* xb = x + (size_t)b*C_*HW_;

    const bool vy0 = (y  > 0), vy2 = (y < H_-1);
    const bool vcl = (x0 > 0), vcr = (x0 < 126);
    const int base00 = (y-1)*W_ + (x0-1);

    unsigned long long acc0[14], acc1[14];
    #pragma unroll
    for (int j = 0; j < 14; j++) { acc0[j] = 0ull; acc1[j] = 0ull; }

    for (int c = 0; c < C_; c++) {
        const float* xp = xb + c*HW_ + base00;
        float v[12];                          // 3 rows x 4 cols
        #pragma unroll
        for (int r = 0; r < 3; r++) {
            const bool vr = (r == 0) ? vy0 : (r == 2) ? vy2 : true;
            const float* row = xp + r*W_;
            v[r*4+0] = (vr && vcl) ? row[0] : 0.f;
            v[r*4+1] =  vr         ? row[1] : 0.f;
            v[r*4+2] =  vr         ? row[2] : 0.f;
            v[r*4+3] = (vr && vcr) ? row[3] : 0.f;
        }

        const float* wc = wA + c*9*28;
        #pragma unroll
        for (int ty = 0; ty < 3; ty++) {
            #pragma unroll
            for (int tx = 0; tx < 3; tx++) {
                unsigned long long vv0 = splat2(v[ty*4 + tx]);
                unsigned long long vv1 = splat2(v[ty*4 + tx + 1]);
                const ulonglong2* wr = (const ulonglong2*)(wc + (ty*3 + tx)*28);
                #pragma unroll
                for (int q = 0; q < 7; q++) {
                    ulonglong2 w4 = wr[q];
                    acc0[2*q]   = fma2(vv0, w4.x, acc0[2*q]);
                    acc0[2*q+1] = fma2(vv0, w4.y, acc0[2*q+1]);
                    acc1[2*q]   = fma2(vv1, w4.x, acc1[2*q]);
                    acc1[2*q+1] = fma2(vv1, w4.y, acc1[2*q+1]);
                }
            }
        }
    }

    float a0[28], a1[28];
    #pragma unroll
    for (int j = 0; j < 14; j++) {
        a0[2*j]   = __uint_as_float((unsigned)(acc0[j] & 0xffffffffULL));
        a0[2*j+1] = __uint_as_float((unsigned)(acc0[j] >> 32));
        a1[2*j]   = __uint_as_float((unsigned)(acc1[j] & 0xffffffffULL));
        a1[2*j+1] = __uint_as_float((unsigned)(acc1[j] >> 32));
    }
    #pragma unroll
    for (int k = 0; k < 9; k++) {
        const int base = (b*9 + k)*HW_ + pix;
        float by = b_om[2*k], bx = b_om[2*k+1], bm = b_om[18+k];
        float2 dy2; dy2.x = a0[2*k]   + by; dy2.y = a1[2*k]   + by;
        float2 dx2; dx2.x = a0[2*k+1] + bx; dx2.y = a1[2*k+1] + bx;
        float m0 = a0[18+k] + bm, m1 = a1[18+k] + bm;
        float2 mk2;
        mk2.x = 1.f / (1.f + __expf(-m0));
        mk2.y = 1.f / (1.f + __expf(-m1));
        *(float2*)&g_dy[base]   = dy2;
        *(float2*)&g_dx[base]   = dx2;
        *(float2*)&g_mask[base] = mk2;
    }
}

// ---------------- kernel 2: implicit GEMM via mma.sync (fp16 A, fp16 hi/lo B) ----------------
// M=128 pixels x N=64, K=576. Gathers from channel-major fp16 x: per warp-tap
// 16 LDG.128 covering 16 px x 4 positions x full 128B channel lines.
// Coefficients computed on lanes 0..15, distributed by shfl.
__global__ void __launch_bounds__(256, 3)
deform_mma(const float* __restrict__ bias, float* __restrict__ out) {
    __shared__ __align__(16) unsigned char sA[16384];   // fp16 A tile 128x64
    __shared__ uint2 sB_hi[1024];                       // 8 KB
    __shared__ uint2 sB_lo[1024];                       // 8 KB

    const int tid  = threadIdx.x;
    const int lane = tid & 31;
    const int wp   = tid >> 5;          // warp 0..7 -> pixels wp*16..+15
    const int b    = blockIdx.x >> 7;
    const int tile = blockIdx.x & 127;  // image row
    const uint4* xcb = g_xc + (size_t)b*HW_*8;

    const unsigned sAu = smem_u32(sA);

    const int pidx = lane & 15;               // coefficient pixel (dup on hi lanes)
    const int px_c = wp*16 + pidx;            // pixel within tile
    const int gpix = tile*128 + px_c;

    float acc[8][4];
    #pragma unroll
    for (int nt = 0; nt < 8; nt++)
        #pragma unroll
        for (int j = 0; j < 4; j++) acc[nt][j] = 0.f;

    #pragma unroll 1
    for (int t = 0; t < 9; t++) {
        // ---- B fragments for this tap: global -> SMEM (8 KB each) ----
        {
            const uint4* srcH = (const uint4*)(g_wB_hi + t*1024);
            const uint4* srcL = (const uint4*)(g_wB_lo + t*1024);
            uint4* dstH = (uint4*)sB_hi;
            uint4* dstL = (uint4*)sB_lo;
            for (int j = tid; j < 512; j += 256) {
                dstH[j] = srcH[j];
                dstL[j] = srcL[j];
            }
        }

        // ---- bilinear coefficients for pixel px_c, tap t ----
        int o00, o01, o10, o11;
        float c00, c01, c10, c11;
        {
            const int obase = (b*9 + t)*HW_ + gpix;
            const float m  = g_mask[obase];
            const int ky = t / 3, kx = t - ky*3;
            const float sy = g_dy[obase] + (float)(ky + tile - 1);
            const float sx = g_dx[obase] + (float)(kx + px_c - 1);

            const float y0f = floorf(sy), x0f = floorf(sx);
            const int iy0 = (int)y0f, ix0 = (int)x0f;
            const float wy1 = sy - y0f, wx1 = sx - x0f;
            const float wy0 = 1.f - wy1, wx0 = 1.f - wx1;

            const bool py0 = (iy0   >= 0) && (iy0   < H_);
            const bool py1 = (iy0+1 >= 0) && (iy0+1 < H_);
            const bool qx0 = (ix0   >= 0) && (ix0   < W_);
            const bool qx1 = (ix0+1 >= 0) && (ix0+1 < W_);

            const int y0c = min(max(iy0,   0), H_-1);
            const int y1c = min(max(iy0+1, 0), H_-1);
            const int x0c = min(max(ix0,   0), W_-1);
            const int x1c = min(max(ix0+1, 0), W_-1);

            o00 = y0c*W_ + x0c;  o01 = y0c*W_ + x1c;
            o10 = y1c*W_ + x0c;  o11 = y1c*W_ + x1c;

            c00 = (py0 && qx0) ? wy0*wx0*m : 0.f;
            c01 = (py0 && qx1) ? wy0*wx1*m : 0.f;
            c10 = (py1 && qx0) ? wy1*wx0*m : 0.f;
            c11 = (py1 && qx1) ? wy1*wx1*m : 0.f;
        }

        // ---- gather: 4 iterations, lane = (px_sub<<3)|chunk ----
        const int chunk = lane & 7;
        #pragma unroll
        for (int it = 0; it < 4; it++) {
            const int j = it*4 + (lane >> 3);       // pixel idx 0..15 in warp
            const int p0 = __shfl_sync(0xffffffffu, o00, j);
            const int p1 = __shfl_sync(0xffffffffu, o01, j);
            const int p2 = __shfl_sync(0xffffffffu, o10, j);
            const int p3 = __shfl_sync(0xffffffffu, o11, j);
            const float k0 = __shfl_sync(0xffffffffu, c00, j);
            const float k1 = __shfl_sync(0xffffffffu, c01, j);
            const float k2 = __shfl_sync(0xffffffffu, c10, j);
            const float k3 = __shfl_sync(0xffffffffu, c11, j);

            const uint4 w0 = xcb[p0*8 + chunk];
            const uint4 w1 = xcb[p1*8 + chunk];
            const uint4 w2 = xcb[p2*8 + chunk];
            const uint4 w3 = xcb[p3*8 + chunk];

            unsigned outw[4];
            #pragma unroll
            for (int q = 0; q < 4; q++) {
                const unsigned u0 = (&w0.x)[q], u1 = (&w1.x)[q];
                const unsigned u2 = (&w2.x)[q], u3 = (&w3.x)[q];
                float2 f0 = __half22float2(*(const __half2*)&u0);
                float2 f1 = __half22float2(*(const __half2*)&u1);
                float2 f2 = __half22float2(*(const __half2*)&u2);
                float2 f3 = __half22float2(*(const __half2*)&u3);
                float vx = fmaf(k3, f3.x, fmaf(k2, f2.x, fmaf(k1, f1.x, k0*f0.x)));
                float vy = fmaf(k3, f3.y, fmaf(k2, f2.y, fmaf(k1, f1.y, k0*f0.y)));
                __half2 h = __floats2half2_rn(vx, vy);
                outw[q] = *reinterpret_cast<unsigned*>(&h);
            }
            uint4 ov; ov.x = outw[0]; ov.y = outw[1]; ov.z = outw[2]; ov.w = outw[3];
            const int prow = wp*16 + j;
            const unsigned off = (unsigned)(prow*128 + 16*(chunk ^ (prow & 7)));
            *(uint4*)(sA + off) = ov;
        }

        __syncthreads();

        // ---- mma phase: warp wp covers pixels wp*16..wp*16+15 ----
        #pragma unroll
        for (int kc = 0; kc < 4; kc++) {
            const int prow = wp*16 + (lane & 15);
            const int chnk = 2*kc + (lane >> 4);
            const unsigned aoff = sAu + (unsigned)(prow*128 + 16*(chnk ^ (prow & 7)));
            unsigned a0, a1, a2, a3;
            asm volatile("ldmatrix.sync.aligned.m8n8.x4.shared.b16 {%0,%1,%2,%3}, [%4];"
                         : "=r"(a0), "=r"(a1), "=r"(a2), "=r"(a3) : "r"(aoff));

            #pragma unroll
            for (int nt = 0; nt < 8; nt++) {
                const uint2 bh = sB_hi[(kc*8 + nt)*32 + lane];
                const uint2 bl = sB_lo[(kc*8 + nt)*32 + lane];
                float* d = acc[nt];
                asm volatile(
                    "mma.sync.aligned.m16n8k16.row.col.f32.f16.f16.f32 "
                    "{%0,%1,%2,%3}, {%4,%5,%6,%7}, {%8,%9}, {%0,%1,%2,%3};"
                    : "+f"(d[0]), "+f"(d[1]), "+f"(d[2]), "+f"(d[3])
                    : "r"(a0), "r"(a1), "r"(a2), "r"(a3), "r"(bh.x), "r"(bh.y));
                asm volatile(
                    "mma.sync.aligned.m16n8k16.row.col.f32.f16.f16.f32 "
                    "{%0,%1,%2,%3}, {%4,%5,%6,%7}, {%8,%9}, {%0,%1,%2,%3};"
                    : "+f"(d[0]), "+f"(d[1]), "+f"(d[2]), "+f"(d[3])
                    : "r"(a0), "r"(a1), "r"(a2), "r"(a3), "r"(bl.x), "r"(bl.y));
            }
        }

        __syncthreads();
    }

    // ---- epilogue: D fragments -> global ----
    {
        const int r0 = lane >> 2;
        const int cp = (lane & 3)*2;
        float* obase = out + (size_t)(b*O_)*HW_ + tile*128 + wp*16;
        #pragma unroll
        for (int nt = 0; nt < 8; nt++) {
            const int o = nt*8 + cp;
            const float bi0 = bias[o], bi1 = bias[o+1];
            obase[(size_t)o*HW_     + r0    ] = acc[nt][0] + bi0;
            obase[(size_t)(o+1)*HW_ + r0    ] = acc[nt][1] + bi1;
            obase[(size_t)o*HW_     + r0 + 8] = acc[nt][2] + bi0;
            obase[(size_t)(o+1)*HW_ + r0 + 8] = acc[nt][3] + bi1;
        }
    }
}

// ---------------- launch ----------------
extern "C" void kernel_launch(void* const* d_in, const int* in_sizes, int n_in,
                              void* d_out, int out_size) {
    const float* x      = (const float*)d_in[0];
    const float* w_om   = (const float*)d_in[1];
    const float* b_om   = (const float*)d_in[2];
    const float* weight = (const float*)d_in[3];
    const float* bias   = (const float*)d_in[4];
    float* out = (float*)d_out;

    const int SMEM_A = (CK_*28) * 4;              // 64512
    cudaFuncSetAttribute(offset_conv, cudaFuncAttributeMaxDynamicSharedMemorySize, SMEM_A);
    cudaFuncSetAttribute(offset_conv, cudaFuncAttributePreferredSharedMemoryCarveout, 100);
    cudaFuncSetAttribute(deform_mma,  cudaFuncAttributePreferredSharedMemoryCarveout, 100);

    offset_conv<<<256, 128, SMEM_A>>>(x, w_om, b_om, weight);
    deform_mma<<<512, 256>>>(bias, out);
}

// round 12
// speedup vs baseline: 2.5758x; 1.2441x over previous
#include <cuda_runtime.h>
#include <cuda_bf16.h>
#include <cuda_fp16.h>
#include <math.h>

// Problem constants (fixed by the reference)
#define B_  4
#define C_  64
#define O_  64
#define H_  128
#define W_  128
#define K2_ 9
#define HW_ (H_*W_)
#define CK_ (C_*K2_)          // 576

// ---------------- scratch (no allocations allowed) ----------------
// Main weight in mma.sync B-fragment layout, fp16 single precision pass:
// entry idx = ((t*4 + kc)*8 + nt)*32 + lane ; .x = k-pair (lane%4)*2, .y = +8
__device__ uint2 g_wB[9*4*8*32];
__device__ float g_dy   [B_*K2_*HW_];
__device__ float g_dx   [B_*K2_*HW_];
__device__ float g_mask [B_*K2_*HW_];
// x repacked channel-major fp16: pixel-major, 64 ch contiguous = 128B/pixel
__device__ uint4 g_xc[B_*HW_*8];

// ---------------- packed f32x2 FMA (sm_100+) ----------------
__device__ __forceinline__ unsigned long long fma2(unsigned long long a,
                                                   unsigned long long b,
                                                   unsigned long long c) {
    unsigned long long d;
    asm("fma.rn.f32x2 %0, %1, %2, %3;" : "=l"(d) : "l"(a), "l"(b), "l"(c));
    return d;
}
__device__ __forceinline__ unsigned long long splat2(float v) {
    unsigned long long d;
    asm("mov.b64 %0, {%1, %1};" : "=l"(d) : "f"(v));
    return d;
}

__device__ __forceinline__ unsigned smem_u32(const void* p) {
    unsigned a;
    asm("{ .reg .u64 t; cvta.to.shared.u64 t, %1; cvt.u32.u64 %0, t; }"
        : "=r"(a) : "l"(p));
    return a;
}

// ---------------- kernel 1: offset/mask conv + weight prep + x transpose ----------------
// 256 CTAs x 128 threads, two horizontal pixels per thread (conv part).
__global__ void __launch_bounds__(128)
offset_conv(const float* __restrict__ x, const float* __restrict__ w_om,
            const float* __restrict__ b_om, const float* __restrict__ weight) {
    extern __shared__ float wA[];     // 576*28 floats = 64512 B

    const int tid = threadIdx.x;

    // --- transpose x into channel-major fp16 (128B per pixel) ---
    {
        const int gid = blockIdx.x*128 + tid;       // 32768 threads, 65536 px
        for (int g = gid; g < B_*HW_; g += 32768) {
            const int b = g >> 14, pix = g & (HW_-1);
            const float* xs = x + (size_t)b*C_*HW_ + pix;
            uint4* dst = g_xc + (size_t)g*8;
            #pragma unroll
            for (int ch = 0; ch < 8; ch++) {
                unsigned w[4];
                #pragma unroll
                for (int j = 0; j < 4; j++) {
                    float v0 = xs[(size_t)(ch*8 + 2*j    )*HW_];
                    float v1 = xs[(size_t)(ch*8 + 2*j + 1)*HW_];
                    __half2 h = __floats2half2_rn(v0, v1);   // v0 -> low
                    w[j] = *reinterpret_cast<unsigned*>(&h);
                }
                uint4 o; o.x = w[0]; o.y = w[1]; o.z = w[2]; o.w = w[3];
                dst[ch] = o;
            }
        }
    }

    // --- main weight -> mma B-fragment layout, fp16 ---
    {
        int i = blockIdx.x*128 + tid;               // 32768 threads cover 9216
        if (i < 9216) {
            int t    = i / 1024;
            int r    = i - t*1024;
            int kc   = r >> 8;
            int r2   = r & 255;
            int nt   = r2 >> 5;
            int lane = r2 & 31;
            int n  = nt*8 + (lane >> 2);
            int kb = (lane & 3)*2;
            unsigned hv[2];
            #pragma unroll
            for (int u = 0; u < 2; u++) {
                int c0 = kc*16 + kb + u*8;
                float w0 = weight[n*CK_ + c0*9 + t];
                float w1 = weight[n*CK_ + (c0+1)*9 + t];
                __half2 h = __floats2half2_rn(w0, w1);
                hv[u] = *reinterpret_cast<unsigned*>(&h);
            }
            uint2 hi; hi.x = hv[0]; hi.y = hv[1];
            g_wB[i] = hi;
        }
    }

    // offset-conv weight: w_om[r][ck] -> wA[ck][28] (pad zeroed)
    for (int i = tid; i < 27*CK_; i += 128) {
        int r = i / CK_, ck = i - r*CK_;
        wA[ck*28 + r] = w_om[i];
    }
    for (int ck = tid; ck < CK_; ck += 128) wA[ck*28 + 27] = 0.f;
    __syncthreads();

    const int p2   = blockIdx.x*128 + tid;    // pair index 0..32767
    const int b    = p2 >> 13;
    const int pix  = (p2 & 8191)*2;           // even pixel within image
    const int y    = pix >> 7, x0 = pix & 127;
    const float* xb = x + (size_t)b*C_*HW_;

    const bool vy0 = (y  > 0), vy2 = (y < H_-1);
    const bool vcl = (x0 > 0), vcr = (x0 < 126);
    const int base00 = (y-1)*W_ + (x0-1);

    unsigned long long acc0[14], acc1[14];
    #pragma unroll
    for (int j = 0; j < 14; j++) { acc0[j] = 0ull; acc1[j] = 0ull; }

    for (int c = 0; c < C_; c++) {
        const float* xp = xb + c*HW_ + base00;
        float v[12];                          // 3 rows x 4 cols
        #pragma unroll
        for (int r = 0; r < 3; r++) {
            const bool vr = (r == 0) ? vy0 : (r == 2) ? vy2 : true;
            const float* row = xp + r*W_;
            v[r*4+0] = (vr && vcl) ? row[0] : 0.f;
            v[r*4+1] =  vr         ? row[1] : 0.f;
            v[r*4+2] =  vr         ? row[2] : 0.f;
            v[r*4+3] = (vr && vcr) ? row[3] : 0.f;
        }

        const float* wc = wA + c*9*28;
        #pragma unroll
        for (int ty = 0; ty < 3; ty++) {
            #pragma unroll
            for (int tx = 0; tx < 3; tx++) {
                unsigned long long vv0 = splat2(v[ty*4 + tx]);
                unsigned long long vv1 = splat2(v[ty*4 + tx + 1]);
                const ulonglong2* wr = (const ulonglong2*)(wc + (ty*3 + tx)*28);
                #pragma unroll
                for (int q = 0; q < 7; q++) {
                    ulonglong2 w4 = wr[q];
                    acc0[2*q]   = fma2(vv0, w4.x, acc0[2*q]);
                    acc0[2*q+1] = fma2(vv0, w4.y, acc0[2*q+1]);
                    acc1[2*q]   = fma2(vv1, w4.x, acc1[2*q]);
                    acc1[2*q+1] = fma2(vv1, w4.y, acc1[2*q+1]);
                }
            }
        }
    }

    float a0[28], a1[28];
    #pragma unroll
    for (int j = 0; j < 14; j++) {
        a0[2*j]   = __uint_as_float((unsigned)(acc0[j] & 0xffffffffULL));
        a0[2*j+1] = __uint_as_float((unsigned)(acc0[j] >> 32));
        a1[2*j]   = __uint_as_float((unsigned)(acc1[j] & 0xffffffffULL));
        a1[2*j+1] = __uint_as_float((unsigned)(acc1[j] >> 32));
    }
    #pragma unroll
    for (int k = 0; k < 9; k++) {
        const int base = (b*9 + k)*HW_ + pix;
        float by = b_om[2*k], bx = b_om[2*k+1], bm = b_om[18+k];
        float2 dy2; dy2.x = a0[2*k]   + by; dy2.y = a1[2*k]   + by;
        float2 dx2; dx2.x = a0[2*k+1] + bx; dx2.y = a1[2*k+1] + bx;
        float m0 = a0[18+k] + bm, m1 = a1[18+k] + bm;
        float2 mk2;
        mk2.x = 1.f / (1.f + __expf(-m0));
        mk2.y = 1.f / (1.f + __expf(-m1));
        *(float2*)&g_dy[base]   = dy2;
        *(float2*)&g_dx[base]   = dx2;
        *(float2*)&g_mask[base] = mk2;
    }
}

// ---------------- kernel 2: implicit GEMM via mma.sync (fp16 x fp16) ----------------
// M=256 pixels (two image rows) x N=64, K=576. Each warp owns 32 px (two m16
// tiles) -> B-fragment LDS and barriers amortize over 2x the M work. All 9
// taps' B fragments preloaded once into SMEM (72 KB).
#define SMEM_D (32768 + 9*8192)     // sA 32KB + sB 72KB = 106496

__global__ void __launch_bounds__(256, 2)
deform_mma(const float* __restrict__ bias, float* __restrict__ out) {
    extern __shared__ unsigned char smem[];
    unsigned char* sA = smem;                       // fp16 A tile 256x64 = 32KB
    uint2* sB = (uint2*)(smem + 32768);             // [9][4][8][32] uint2

    const int tid  = threadIdx.x;
    const int lane = tid & 31;
    const int wp   = tid >> 5;          // warp 0..7 -> pixels wp*32..+31
    const int b    = blockIdx.x >> 6;
    const int tile = blockIdx.x & 63;   // 2-row tile
    const uint4* xcb = g_xc + (size_t)b*HW_*8;

    const unsigned sAu = smem_u32(sA);

    // preload all 9 taps of B fragments (covered by first tap's barrier)
    {
        const uint4* src = (const uint4*)g_wB;
        uint4* dst = (uint4*)sB;
        #pragma unroll
        for (int j = tid; j < 4608; j += 256) dst[j] = src[j];
    }

    const int px_c = tid;                       // pixel within tile (0..255)
    const int gpix = tile*256 + px_c;
    const int yq   = gpix >> 7, xq = gpix & 127;

    float acc[2][8][4];
    #pragma unroll
    for (int ti = 0; ti < 2; ti++)
        #pragma unroll
        for (int nt = 0; nt < 8; nt++)
            #pragma unroll
            for (int j = 0; j < 4; j++) acc[ti][nt][j] = 0.f;

    #pragma unroll 1
    for (int t = 0; t < 9; t++) {
        // ---- bilinear coefficients for pixel px_c, tap t ----
        int o00, o01, o10, o11;
        float c00, c01, c10, c11;
        {
            const int obase = (b*9 + t)*HW_ + gpix;
            const float m  = g_mask[obase];
            const int ky = t / 3, kx = t - ky*3;
            const float sy = g_dy[obase] + (float)(ky + yq - 1);
            const float sx = g_dx[obase] + (float)(kx + xq - 1);

            const float y0f = floorf(sy), x0f = floorf(sx);
            const int iy0 = (int)y0f, ix0 = (int)x0f;
            const float wy1 = sy - y0f, wx1 = sx - x0f;
            const float wy0 = 1.f - wy1, wx0 = 1.f - wx1;

            const bool py0 = (iy0   >= 0) && (iy0   < H_);
            const bool py1 = (iy0+1 >= 0) && (iy0+1 < H_);
            const bool qx0 = (ix0   >= 0) && (ix0   < W_);
            const bool qx1 = (ix0+1 >= 0) && (ix0+1 < W_);

            const int y0c = min(max(iy0,   0), H_-1);
            const int y1c = min(max(iy0+1, 0), H_-1);
            const int x0c = min(max(ix0,   0), W_-1);
            const int x1c = min(max(ix0+1, 0), W_-1);

            o00 = y0c*W_ + x0c;  o01 = y0c*W_ + x1c;
            o10 = y1c*W_ + x0c;  o11 = y1c*W_ + x1c;

            c00 = (py0 && qx0) ? wy0*wx0*m : 0.f;
            c01 = (py0 && qx1) ? wy0*wx1*m : 0.f;
            c10 = (py1 && qx0) ? wy1*wx0*m : 0.f;
            c11 = (py1 && qx1) ? wy1*wx1*m : 0.f;
        }

        // ---- gather: 8 iterations, lane = (px_sub<<3)|chunk ----
        const int chunk = lane & 7;
        #pragma unroll
        for (int it = 0; it < 8; it++) {
            const int j = it*4 + (lane >> 3);       // pixel idx 0..31 in warp
            const int p0 = __shfl_sync(0xffffffffu, o00, j);
            const int p1 = __shfl_sync(0xffffffffu, o01, j);
            const int p2 = __shfl_sync(0xffffffffu, o10, j);
            const int p3 = __shfl_sync(0xffffffffu, o11, j);
            const float k0 = __shfl_sync(0xffffffffu, c00, j);
            const float k1 = __shfl_sync(0xffffffffu, c01, j);
            const float k2 = __shfl_sync(0xffffffffu, c10, j);
            const float k3 = __shfl_sync(0xffffffffu, c11, j);

            const uint4 w0 = xcb[p0*8 + chunk];
            const uint4 w1 = xcb[p1*8 + chunk];
            const uint4 w2 = xcb[p2*8 + chunk];
            const uint4 w3 = xcb[p3*8 + chunk];

            unsigned outw[4];
            #pragma unroll
            for (int q = 0; q < 4; q++) {
                const unsigned u0 = (&w0.x)[q], u1 = (&w1.x)[q];
                const unsigned u2 = (&w2.x)[q], u3 = (&w3.x)[q];
                float2 f0 = __half22float2(*(const __half2*)&u0);
                float2 f1 = __half22float2(*(const __half2*)&u1);
                float2 f2 = __half22float2(*(const __half2*)&u2);
                float2 f3 = __half22float2(*(const __half2*)&u3);
                float vx = fmaf(k3, f3.x, fmaf(k2, f2.x, fmaf(k1, f1.x, k0*f0.x)));
                float vy = fmaf(k3, f3.y, fmaf(k2, f2.y, fmaf(k1, f1.y, k0*f0.y)));
                __half2 h = __floats2half2_rn(vx, vy);
                outw[q] = *reinterpret_cast<unsigned*>(&h);
            }
            uint4 ov; ov.x = outw[0]; ov.y = outw[1]; ov.z = outw[2]; ov.w = outw[3];
            const int prow = wp*32 + j;
            const unsigned off = (unsigned)(prow*128 + 16*(chunk ^ (prow & 7)));
            *(uint4*)(sA + off) = ov;
        }

        __syncthreads();

        // ---- mma phase: warp wp covers pixels wp*32..wp*32+31 (2 tiles) ----
        #pragma unroll
        for (int kc = 0; kc < 4; kc++) {
            const uint2* sBk = sB + (t*4 + kc)*256;
            #pragma unroll
            for (int ti = 0; ti < 2; ti++) {
                const int prow = wp*32 + ti*16 + (lane & 15);
                const int chnk = 2*kc + (lane >> 4);
                const unsigned aoff = sAu + (unsigned)(prow*128 + 16*(chnk ^ (prow & 7)));
                unsigned a0, a1, a2, a3;
                asm volatile("ldmatrix.sync.aligned.m8n8.x4.shared.b16 {%0,%1,%2,%3}, [%4];"
                             : "=r"(a0), "=r"(a1), "=r"(a2), "=r"(a3) : "r"(aoff));

                #pragma unroll
                for (int nt = 0; nt < 8; nt++) {
                    const uint2 bh = sBk[nt*32 + lane];
                    float* d = acc[ti][nt];
                    asm volatile(
                        "mma.sync.aligned.m16n8k16.row.col.f32.f16.f16.f32 "
                        "{%0,%1,%2,%3}, {%4,%5,%6,%7}, {%8,%9}, {%0,%1,%2,%3};"
                        : "+f"(d[0]), "+f"(d[1]), "+f"(d[2]), "+f"(d[3])
                        : "r"(a0), "r"(a1), "r"(a2), "r"(a3), "r"(bh.x), "r"(bh.y));
                }
            }
        }

        __syncthreads();
    }

    // ---- epilogue: D fragments -> global ----
    {
        const int r0 = lane >> 2;
        const int cp = (lane & 3)*2;
        #pragma unroll
        for (int ti = 0; ti < 2; ti++) {
            float* obase = out + (size_t)(b*O_)*HW_ + tile*256 + wp*32 + ti*16;
            #pragma unroll
            for (int nt = 0; nt < 8; nt++) {
                const int o = nt*8 + cp;
                const float bi0 = bias[o], bi1 = bias[o+1];
                obase[(size_t)o*HW_     + r0    ] = acc[ti][nt][0] + bi0;
                obase[(size_t)(o+1)*HW_ + r0    ] = acc[ti][nt][1] + bi1;
                obase[(size_t)o*HW_     + r0 + 8] = acc[ti][nt][2] + bi0;
                obase[(size_t)(o+1)*HW_ + r0 + 8] = acc[ti][nt][3] + bi1;
            }
        }
    }
}

// ---------------- launch ----------------
extern "C" void kernel_launch(void* const* d_in, const int* in_sizes, int n_in,
                              void* d_out, int out_size) {
    const float* x      = (const float*)d_in[0];
    const float* w_om   = (const float*)d_in[1];
    const float* b_om   = (const float*)d_in[2];
    const float* weight = (const float*)d_in[3];
    const float* bias   = (const float*)d_in[4];
    float* out = (float*)d_out;

    const int SMEM_A = (CK_*28) * 4;              // 64512
    cudaFuncSetAttribute(offset_conv, cudaFuncAttributeMaxDynamicSharedMemorySize, SMEM_A);
    cudaFuncSetAttribute(offset_conv, cudaFuncAttributePreferredSharedMemoryCarveout, 100);
    cudaFuncSetAttribute(deform_mma,  cudaFuncAttributeMaxDynamicSharedMemorySize, SMEM_D);
    cudaFuncSetAttribute(deform_mma,  cudaFuncAttributePreferredSharedMemoryCarveout, 100);

    offset_conv<<<256, 128, SMEM_A>>>(x, w_om, b_om, weight);
    deform_mma<<<256, 256, SMEM_D>>>(bias, out);
}

// round 13
// speedup vs baseline: 4.0322x; 1.5654x over previous
#include <cuda_runtime.h>
#include <cuda_bf16.h>
#include <cuda_fp16.h>
#include <math.h>

// Problem constants (fixed by the reference)
#define B_  4
#define C_  64
#define O_  64
#define H_  128
#define W_  128
#define K2_ 9
#define HW_ (H_*W_)
#define CK_ (C_*K2_)          // 576

// ---------------- scratch (no allocations allowed) ----------------
// Main weight in mma.sync B-fragment layout (fp16 single pass):
// idx = ((t*4 + kc)*8 + nt)*32 + lane
__device__ uint2 g_wB[9*4*8*32];
// Offset-conv weight, B-fragment layout, fp16 hi(+lo) passes, N padded to 32:
// idx = pass*4608 + ((t*4 + kc)*4 + nt)*32 + lane
__device__ uint2 g_wOB[2*9*4*4*32];
__device__ float g_dy   [B_*K2_*HW_];
__device__ float g_dx   [B_*K2_*HW_];
__device__ float g_mask [B_*K2_*HW_];
// x repacked channel-major fp16: pixel-major, 64 ch contiguous = 128B/pixel
__device__ uint4 g_xc[B_*HW_*8];

__device__ __forceinline__ unsigned smem_u32(const void* p) {
    unsigned a;
    asm("{ .reg .u64 t; cvta.to.shared.u64 t, %1; cvt.u32.u64 %0, t; }"
        : "=r"(a) : "l"(p));
    return a;
}
__device__ __forceinline__ unsigned short fp16_bits(float v) {
    __half h = __float2half_rn(v);
    return *reinterpret_cast<unsigned short*>(&h);
}
__device__ __forceinline__ float fp16_val(unsigned short u) {
    __half h = *reinterpret_cast<__half*>(&u);
    return __half2float(h);
}

// ---------------- kernel 0: prep (x transpose + both weight fragments) ----------------
__global__ void __launch_bounds__(256)
prep(const float* __restrict__ x, const float* __restrict__ w_om,
     const float* __restrict__ weight) {
    const int gid = blockIdx.x*256 + threadIdx.x;     // 32768 threads

    // --- transpose x into channel-major fp16 (128B per pixel) ---
    for (int g = gid; g < B_*HW_; g += 32768) {
        const int b = g >> 14, pix = g & (HW_-1);
        const float* xs = x + (size_t)b*C_*HW_ + pix;
        uint4* dst = g_xc + (size_t)g*8;
        #pragma unroll
        for (int ch = 0; ch < 8; ch++) {
            unsigned w[4];
            #pragma unroll
            for (int j = 0; j < 4; j++) {
                float v0 = xs[(size_t)(ch*8 + 2*j    )*HW_];
                float v1 = xs[(size_t)(ch*8 + 2*j + 1)*HW_];
                __half2 h = __floats2half2_rn(v0, v1);   // v0 -> low
                w[j] = *reinterpret_cast<unsigned*>(&h);
            }
            uint4 o; o.x = w[0]; o.y = w[1]; o.z = w[2]; o.w = w[3];
            dst[ch] = o;
        }
    }

    // --- main weight -> mma B-fragment layout, fp16 ---
    if (gid < 9216) {
        int i = gid;
        int t    = i / 1024;
        int r    = i - t*1024;
        int kc   = r >> 8;
        int r2   = r & 255;
        int nt   = r2 >> 5;
        int lane = r2 & 31;
        int n  = nt*8 + (lane >> 2);
        int kb = (lane & 3)*2;
        unsigned hv[2];
        #pragma unroll
        for (int u = 0; u < 2; u++) {
            int c0 = kc*16 + kb + u*8;
            float w0 = weight[n*CK_ + c0*9 + t];
            float w1 = weight[n*CK_ + (c0+1)*9 + t];
            __half2 h = __floats2half2_rn(w0, w1);
            hv[u] = *reinterpret_cast<unsigned*>(&h);
        }
        uint2 hi; hi.x = hv[0]; hi.y = hv[1];
        g_wB[i] = hi;
    }

    // --- offset-conv weight -> B fragments (N=32 pad, fp16 hi + lo) ---
    if (gid < 4608) {
        int i = gid;
        int t    = i / 512;
        int r    = i - t*512;
        int kc   = r >> 7;
        int r2   = r & 127;
        int nt   = r2 >> 5;
        int lane = r2 & 31;
        int n  = nt*8 + (lane >> 2);
        int kb = (lane & 3)*2;
        unsigned hv[2], lv[2];
        #pragma unroll
        for (int u = 0; u < 2; u++) {
            int c0 = kc*16 + kb + u*8;
            float w0 = (n < 27) ? w_om[n*CK_ + c0*9 + t]     : 0.f;
            float w1 = (n < 27) ? w_om[n*CK_ + (c0+1)*9 + t] : 0.f;
            unsigned short h0 = fp16_bits(w0);
            unsigned short h1 = fp16_bits(w1);
            unsigned short l0 = fp16_bits(w0 - fp16_val(h0));
            unsigned short l1 = fp16_bits(w1 - fp16_val(h1));
            hv[u] = (unsigned)h0 | ((unsigned)h1 << 16);
            lv[u] = (unsigned)l0 | ((unsigned)l1 << 16);
        }
        uint2 hi; hi.x = hv[0]; hi.y = hv[1];
        uint2 lo; lo.x = lv[0]; lo.y = lv[1];
        g_wOB[i]        = hi;
        g_wOB[4608 + i] = lo;
    }
}

// ---------------- kernel 1: offset/mask conv via mma.sync ----------------
// M=256 px tile, N=32 (27 used), K=576. A tiles are plain shifted copies of
// the channel-major fp16 x lines (zero-padded at borders).
#define SMEM_O (32768 + 73728)      // sA 32KB + sB(hi+lo) 72KB = 106496

__global__ void __launch_bounds__(256, 2)
offset_mma(const float* __restrict__ b_om) {
    extern __shared__ unsigned char smem[];
    unsigned char* sA = smem;                   // fp16 A tile 256x64 = 32KB
    uint2* sB = (uint2*)(smem + 32768);         // [2][9][4][4][32]
    float* sD = (float*)(smem + 32768);         // epilogue reuse (33792 B)

    const int tid  = threadIdx.x;
    const int lane = tid & 31;
    const int wp   = tid >> 5;          // warp 0..7 -> pixels wp*32..+31
    const int b    = blockIdx.x >> 6;
    const int tile = blockIdx.x & 63;   // 2-row tile
    const uint4* xcb = g_xc + (size_t)b*HW_*8;

    const unsigned sAu = smem_u32(sA);

    {   // preload both passes of offset-weight fragments (72 KB)
        const uint4* src = (const uint4*)g_wOB;
        uint4* dst = (uint4*)sB;
        #pragma unroll
        for (int j = tid; j < 4608; j += 256) dst[j] = src[j];
    }

    float acc[2][4][4];
    #pragma unroll
    for (int ti = 0; ti < 2; ti++)
        #pragma unroll
        for (int nt = 0; nt < 4; nt++)
            #pragma unroll
            for (int j = 0; j < 4; j++) acc[ti][nt][j] = 0.f;

    const int chunk = lane & 7;

    #pragma unroll 1
    for (int t = 0; t < 9; t++) {
        const int ky = t / 3, kx = t - ky*3;

        // ---- A tile: shifted x lines, zero-padded ----
        #pragma unroll
        for (int it = 0; it < 8; it++) {
            const int j = it*4 + (lane >> 3);       // pixel idx 0..31 in warp
            const int prow = wp*32 + j;
            const int gp = tile*256 + prow;
            const int yy = (gp >> 7) + ky - 1;
            const int xx = (gp & 127) + kx - 1;
            uint4 v = make_uint4(0u, 0u, 0u, 0u);
            if (yy >= 0 && yy < H_ && xx >= 0 && xx < W_)
                v = xcb[(yy*W_ + xx)*8 + chunk];
            const unsigned off = (unsigned)(prow*128 + 16*(chunk ^ (prow & 7)));
            *(uint4*)(sA + off) = v;
        }

        __syncthreads();

        // ---- mma: 2 passes (hi, lo), N=32 ----
        #pragma unroll
        for (int kc = 0; kc < 4; kc++) {
            const uint2* sBh = sB + ((t*4 + kc)*4)*32;
            const uint2* sBl = sBh + 4608;
            #pragma unroll
            for (int ti = 0; ti < 2; ti++) {
                const int prow = wp*32 + ti*16 + (lane & 15);
                const int chnk = 2*kc + (lane >> 4);
                const unsigned aoff = sAu + (unsigned)(prow*128 + 16*(chnk ^ (prow & 7)));
                unsigned a0, a1, a2, a3;
                asm volatile("ldmatrix.sync.aligned.m8n8.x4.shared.b16 {%0,%1,%2,%3}, [%4];"
                             : "=r"(a0), "=r"(a1), "=r"(a2), "=r"(a3) : "r"(aoff));
                #pragma unroll
                for (int nt = 0; nt < 4; nt++) {
                    const uint2 bh = sBh[nt*32 + lane];
                    const uint2 bl = sBl[nt*32 + lane];
                    float* d = acc[ti][nt];
                    asm volatile(
                        "mma.sync.aligned.m16n8k16.row.col.f32.f16.f16.f32 "
                        "{%0,%1,%2,%3}, {%4,%5,%6,%7}, {%8,%9}, {%0,%1,%2,%3};"
                        : "+f"(d[0]), "+f"(d[1]), "+f"(d[2]), "+f"(d[3])
                        : "r"(a0), "r"(a1), "r"(a2), "r"(a3), "r"(bh.x), "r"(bh.y));
                    asm volatile(
                        "mma.sync.aligned.m16n8k16.row.col.f32.f16.f16.f32 "
                        "{%0,%1,%2,%3}, {%4,%5,%6,%7}, {%8,%9}, {%0,%1,%2,%3};"
                        : "+f"(d[0]), "+f"(d[1]), "+f"(d[2]), "+f"(d[3])
                        : "r"(a0), "r"(a1), "r"(a2), "r"(a3), "r"(bl.x), "r"(bl.y));
                }
            }
        }

        __syncthreads();
    }

    // ---- epilogue: D -> SMEM (stride 33) -> dy/dx/mask ----
    {
        const int r0 = lane >> 2;
        const int cp = (lane & 3)*2;
        #pragma unroll
        for (int ti = 0; ti < 2; ti++) {
            const int row = wp*32 + ti*16 + r0;
            #pragma unroll
            for (int nt = 0; nt < 4; nt++) {
                const int col = nt*8 + cp;
                float* d = acc[ti][nt];
                sD[row*33 + col]         = d[0];
                sD[row*33 + col + 1]     = d[1];
                sD[(row + 8)*33 + col]     = d[2];
                sD[(row + 8)*33 + col + 1] = d[3];
            }
        }
    }
    __syncthreads();

    {
        const int p  = tid;
        const int gp = tile*256 + p;
        const float* row = sD + p*33;
        #pragma unroll
        for (int k = 0; k < 9; k++) {
            const int base = (b*9 + k)*HW_ + gp;
            g_dy[base]   = row[2*k]     + b_om[2*k];
            g_dx[base]   = row[2*k + 1] + b_om[2*k + 1];
            float ml     = row[18 + k]  + b_om[18 + k];
            g_mask[base] = 1.f / (1.f + __expf(-ml));
        }
    }
}

// ---------------- kernel 2: implicit GEMM via mma.sync (fp16 x fp16) ----------------
// (unchanged from R12: M=256 px, warp owns 32 px, all-tap B preload)
#define SMEM_D (32768 + 9*8192)     // sA 32KB + sB 72KB = 106496

__global__ void __launch_bounds__(256, 2)
deform_mma(const float* __restrict__ bias, float* __restrict__ out) {
    extern __shared__ unsigned char smem[];
    unsigned char* sA = smem;                       // fp16 A tile 256x64 = 32KB
    uint2* sB = (uint2*)(smem + 32768);             // [9][4][8][32] uint2

    const int tid  = threadIdx.x;
    const int lane = tid & 31;
    const int wp   = tid >> 5;          // warp 0..7 -> pixels wp*32..+31
    const int b    = blockIdx.x >> 6;
    const int tile = blockIdx.x & 63;   // 2-row tile
    const uint4* xcb = g_xc + (size_t)b*HW_*8;

    const unsigned sAu = smem_u32(sA);

    {
        const uint4* src = (const uint4*)g_wB;
        uint4* dst = (uint4*)sB;
        #pragma unroll
        for (int j = tid; j < 4608; j += 256) dst[j] = src[j];
    }

    const int px_c = tid;                       // pixel within tile (0..255)
    const int gpix = tile*256 + px_c;
    const int yq   = gpix >> 7, xq = gpix & 127;

    float acc[2][8][4];
    #pragma unroll
    for (int ti = 0; ti < 2; ti++)
        #pragma unroll
        for (int nt = 0; nt < 8; nt++)
            #pragma unroll
            for (int j = 0; j < 4; j++) acc[ti][nt][j] = 0.f;

    #pragma unroll 1
    for (int t = 0; t < 9; t++) {
        int o00, o01, o10, o11;
        float c00, c01, c10, c11;
        {
            const int obase = (b*9 + t)*HW_ + gpix;
            const float m  = g_mask[obase];
            const int ky = t / 3, kx = t - ky*3;
            const float sy = g_dy[obase] + (float)(ky + yq - 1);
            const float sx = g_dx[obase] + (float)(kx + xq - 1);

            const float y0f = floorf(sy), x0f = floorf(sx);
            const int iy0 = (int)y0f, ix0 = (int)x0f;
            const float wy1 = sy - y0f, wx1 = sx - x0f;
            const float wy0 = 1.f - wy1, wx0 = 1.f - wx1;

            const bool py0 = (iy0   >= 0) && (iy0   < H_);
            const bool py1 = (iy0+1 >= 0) && (iy0+1 < H_);
            const bool qx0 = (ix0   >= 0) && (ix0   < W_);
            const bool qx1 = (ix0+1 >= 0) && (ix0+1 < W_);

            const int y0c = min(max(iy0,   0), H_-1);
            const int y1c = min(max(iy0+1, 0), H_-1);
            const int x0c = min(max(ix0,   0), W_-1);
            const int x1c = min(max(ix0+1, 0), W_-1);

            o00 = y0c*W_ + x0c;  o01 = y0c*W_ + x1c;
            o10 = y1c*W_ + x0c;  o11 = y1c*W_ + x1c;

            c00 = (py0 && qx0) ? wy0*wx0*m : 0.f;
            c01 = (py0 && qx1) ? wy0*wx1*m : 0.f;
            c10 = (py1 && qx0) ? wy1*wx0*m : 0.f;
            c11 = (py1 && qx1) ? wy1*wx1*m : 0.f;
        }

        const int chunk = lane & 7;
        #pragma unroll
        for (int it = 0; it < 8; it++) {
            const int j = it*4 + (lane >> 3);       // pixel idx 0..31 in warp
            const int p0 = __shfl_sync(0xffffffffu, o00, j);
            const int p1 = __shfl_sync(0xffffffffu, o01, j);
            const int p2 = __shfl_sync(0xffffffffu, o10, j);
            const int p3 = __shfl_sync(0xffffffffu, o11, j);
            const float k0 = __shfl_sync(0xffffffffu, c00, j);
            const float k1 = __shfl_sync(0xffffffffu, c01, j);
            const float k2 = __shfl_sync(0xffffffffu, c10, j);
            const float k3 = __shfl_sync(0xffffffffu, c11, j);

            const uint4 w0 = xcb[p0*8 + chunk];
            const uint4 w1 = xcb[p1*8 + chunk];
            const uint4 w2 = xcb[p2*8 + chunk];
            const uint4 w3 = xcb[p3*8 + chunk];

            unsigned outw[4];
            #pragma unroll
            for (int q = 0; q < 4; q++) {
                const unsigned u0 = (&w0.x)[q], u1 = (&w1.x)[q];
                const unsigned u2 = (&w2.x)[q], u3 = (&w3.x)[q];
                float2 f0 = __half22float2(*(const __half2*)&u0);
                float2 f1 = __half22float2(*(const __half2*)&u1);
                float2 f2 = __half22float2(*(const __half2*)&u2);
                float2 f3 = __half22float2(*(const __half2*)&u3);
                float vx = fmaf(k3, f3.x, fmaf(k2, f2.x, fmaf(k1, f1.x, k0*f0.x)));
                float vy = fmaf(k3, f3.y, fmaf(k2, f2.y, fmaf(k1, f1.y, k0*f0.y)));
                __half2 h = __floats2half2_rn(vx, vy);
                outw[q] = *reinterpret_cast<unsigned*>(&h);
            }
            uint4 ov; ov.x = outw[0]; ov.y = outw[1]; ov.z = outw[2]; ov.w = outw[3];
            const int prow = wp*32 + j;
            const unsigned off = (unsigned)(prow*128 + 16*(chunk ^ (prow & 7)));
            *(uint4*)(sA + off) = ov;
        }

        __syncthreads();

        #pragma unroll
        for (int kc = 0; kc < 4; kc++) {
            const uint2* sBk = sB + (t*4 + kc)*256;
            #pragma unroll
            for (int ti = 0; ti < 2; ti++) {
                const int prow = wp*32 + ti*16 + (lane & 15);
                const int chnk = 2*kc + (lane >> 4);
                const unsigned aoff = sAu + (unsigned)(prow*128 + 16*(chnk ^ (prow & 7)));
                unsigned a0, a1, a2, a3;
                asm volatile("ldmatrix.sync.aligned.m8n8.x4.shared.b16 {%0,%1,%2,%3}, [%4];"
                             : "=r"(a0), "=r"(a1), "=r"(a2), "=r"(a3) : "r"(aoff));

                #pragma unroll
                for (int nt = 0; nt < 8; nt++) {
                    const uint2 bh = sBk[nt*32 + lane];
                    float* d = acc[ti][nt];
                    asm volatile(
                        "mma.sync.aligned.m16n8k16.row.col.f32.f16.f16.f32 "
                        "{%0,%1,%2,%3}, {%4,%5,%6,%7}, {%8,%9}, {%0,%1,%2,%3};"
                        : "+f"(d[0]), "+f"(d[1]), "+f"(d[2]), "+f"(d[3])
                        : "r"(a0), "r"(a1), "r"(a2), "r"(a3), "r"(bh.x), "r"(bh.y));
                }
            }
        }

        __syncthreads();
    }

    {
        const int r0 = lane >> 2;
        const int cp = (lane & 3)*2;
        #pragma unroll
        for (int ti = 0; ti < 2; ti++) {
            float* obase = out + (size_t)(b*O_)*HW_ + tile*256 + wp*32 + ti*16;
            #pragma unroll
            for (int nt = 0; nt < 8; nt++) {
                const int o = nt*8 + cp;
                const float bi0 = bias[o], bi1 = bias[o+1];
                obase[(size_t)o*HW_     + r0    ] = acc[ti][nt][0] + bi0;
                obase[(size_t)(o+1)*HW_ + r0    ] = acc[ti][nt][1] + bi1;
                obase[(size_t)o*HW_     + r0 + 8] = acc[ti][nt][2] + bi0;
                obase[(size_t)(o+1)*HW_ + r0 + 8] = acc[ti][nt][3] + bi1;
            }
        }
    }
}

// ---------------- launch ----------------
extern "C" void kernel_launch(void* const* d_in, const int* in_sizes, int n_in,
                              void* d_out, int out_size) {
    const float* x      = (const float*)d_in[0];
    const float* w_om   = (const float*)d_in[1];
    const float* b_om   = (const float*)d_in[2];
    const float* weight = (const float*)d_in[3];
    const float* bias   = (const float*)d_in[4];
    float* out = (float*)d_out;

    cudaFuncSetAttribute(offset_mma, cudaFuncAttributeMaxDynamicSharedMemorySize, SMEM_O);
    cudaFuncSetAttribute(offset_mma, cudaFuncAttributePreferredSharedMemoryCarveout, 100);
    cudaFuncSetAttribute(deform_mma, cudaFuncAttributeMaxDynamicSharedMemorySize, SMEM_D);
    cudaFuncSetAttribute(deform_mma, cudaFuncAttributePreferredSharedMemoryCarveout, 100);

    prep<<<128, 256>>>(x, w_om, weight);
    offset_mma<<<256, 256, SMEM_O>>>(b_om);
    deform_mma<<<256, 256, SMEM_D>>>(bias, out);
}

// round 14
// speedup vs baseline: 4.1219x; 1.0222x over previous
#include <cuda_runtime.h>
#include <cuda_bf16.h>
#include <cuda_fp16.h>
#include <math.h>

// Problem constants (fixed by the reference)
#define B_  4
#define C_  64
#define O_  64
#define H_  128
#define W_  128
#define K2_ 9
#define HW_ (H_*W_)
#define CK_ (C_*K2_)          // 576

// ---------------- scratch (no allocations allowed) ----------------
// Main weight in mma.sync B-fragment layout (fp16 single pass):
// idx = ((t*4 + kc)*8 + nt)*32 + lane
__device__ uint2 g_wB[9*4*8*32];
// Offset-conv weight, B-fragment layout, fp16 hi(+lo) passes, N padded to 32:
// idx = pass*4608 + ((t*4 + kc)*4 + nt)*32 + lane
__device__ uint2 g_wOB[2*9*4*4*32];
__device__ float g_dy   [B_*K2_*HW_];
__device__ float g_dx   [B_*K2_*HW_];
__device__ float g_mask [B_*K2_*HW_];
// x repacked channel-major fp16: pixel-major, 64 ch contiguous = 128B/pixel
__device__ uint4 g_xc[B_*HW_*8];

__device__ __forceinline__ unsigned smem_u32(const void* p) {
    unsigned a;
    asm("{ .reg .u64 t; cvta.to.shared.u64 t, %1; cvt.u32.u64 %0, t; }"
        : "=r"(a) : "l"(p));
    return a;
}
__device__ __forceinline__ unsigned short fp16_bits(float v) {
    __half h = __float2half_rn(v);
    return *reinterpret_cast<unsigned short*>(&h);
}
__device__ __forceinline__ float fp16_val(unsigned short u) {
    __half h = *reinterpret_cast<__half*>(&u);
    return __half2float(h);
}

// ---------------- kernel 0: prep (x transpose + both weight fragments) ----------------
// grid 256 x 256: one pixel per thread (2x the parallelism of R13).
__global__ void __launch_bounds__(256)
prep(const float* __restrict__ x, const float* __restrict__ w_om,
     const float* __restrict__ weight) {
    const int gid = blockIdx.x*256 + threadIdx.x;     // 65536 threads

    // --- transpose x into channel-major fp16 (128B per pixel) ---
    {
        const int g = gid;                  // one pixel per thread
        const int b = g >> 14, pix = g & (HW_-1);
        const float* xs = x + (size_t)b*C_*HW_ + pix;
        uint4* dst = g_xc + (size_t)g*8;
        #pragma unroll
        for (int ch = 0; ch < 8; ch++) {
            unsigned w[4];
            #pragma unroll
            for (int j = 0; j < 4; j++) {
                float v0 = xs[(size_t)(ch*8 + 2*j    )*HW_];
                float v1 = xs[(size_t)(ch*8 + 2*j + 1)*HW_];
                __half2 h = __floats2half2_rn(v0, v1);   // v0 -> low
                w[j] = *reinterpret_cast<unsigned*>(&h);
            }
            uint4 o; o.x = w[0]; o.y = w[1]; o.z = w[2]; o.w = w[3];
            dst[ch] = o;
        }
    }

    // --- main weight -> mma B-fragment layout, fp16 ---
    if (gid < 9216) {
        int i = gid;
        int t    = i / 1024;
        int r    = i - t*1024;
        int kc   = r >> 8;
        int r2   = r & 255;
        int nt   = r2 >> 5;
        int lane = r2 & 31;
        int n  = nt*8 + (lane >> 2);
        int kb = (lane & 3)*2;
        unsigned hv[2];
        #pragma unroll
        for (int u = 0; u < 2; u++) {
            int c0 = kc*16 + kb + u*8;
            float w0 = weight[n*CK_ + c0*9 + t];
            float w1 = weight[n*CK_ + (c0+1)*9 + t];
            __half2 h = __floats2half2_rn(w0, w1);
            hv[u] = *reinterpret_cast<unsigned*>(&h);
        }
        uint2 hi; hi.x = hv[0]; hi.y = hv[1];
        g_wB[i] = hi;
    }

    // --- offset-conv weight -> B fragments (N=32 pad, fp16 hi + lo) ---
    if (gid < 4608) {
        int i = gid;
        int t    = i / 512;
        int r    = i - t*512;
        int kc   = r >> 7;
        int r2   = r & 127;
        int nt   = r2 >> 5;
        int lane = r2 & 31;
        int n  = nt*8 + (lane >> 2);
        int kb = (lane & 3)*2;
        unsigned hv[2], lv[2];
        #pragma unroll
        for (int u = 0; u < 2; u++) {
            int c0 = kc*16 + kb + u*8;
            float w0 = (n < 27) ? w_om[n*CK_ + c0*9 + t]     : 0.f;
            float w1 = (n < 27) ? w_om[n*CK_ + (c0+1)*9 + t] : 0.f;
            unsigned short h0 = fp16_bits(w0);
            unsigned short h1 = fp16_bits(w1);
            unsigned short l0 = fp16_bits(w0 - fp16_val(h0));
            unsigned short l1 = fp16_bits(w1 - fp16_val(h1));
            hv[u] = (unsigned)h0 | ((unsigned)h1 << 16);
            lv[u] = (unsigned)l0 | ((unsigned)l1 << 16);
        }
        uint2 hi; hi.x = hv[0]; hi.y = hv[1];
        uint2 lo; lo.x = lv[0]; lo.y = lv[1];
        g_wOB[i]        = hi;
        g_wOB[4608 + i] = lo;
    }
}

// ---------------- kernel 1: offset/mask conv via mma.sync ----------------
// M=256 px tile, N=32 (27 used), K=576. A tiles are plain shifted copies of
// the channel-major fp16 x lines (zero-padded at borders).
#define SMEM_O (32768 + 73728)      // sA 32KB + sB(hi+lo) 72KB = 106496

__global__ void __launch_bounds__(256, 2)
offset_mma(const float* __restrict__ b_om) {
    extern __shared__ unsigned char smem[];
    unsigned char* sA = smem;                   // fp16 A tile 256x64 = 32KB
    uint2* sB = (uint2*)(smem + 32768);         // [2][9][4][4][32]
    float* sD = (float*)(smem + 32768);         // epilogue reuse (33792 B)

    const int tid  = threadIdx.x;
    const int lane = tid & 31;
    const int wp   = tid >> 5;          // warp 0..7 -> pixels wp*32..+31
    const int b    = blockIdx.x >> 6;
    const int tile = blockIdx.x & 63;   // 2-row tile
    const uint4* xcb = g_xc + (size_t)b*HW_*8;

    const unsigned sAu = smem_u32(sA);

    {   // preload both passes of offset-weight fragments (72 KB)
        const uint4* src = (const uint4*)g_wOB;
        uint4* dst = (uint4*)sB;
        #pragma unroll
        for (int j = tid; j < 4608; j += 256) dst[j] = src[j];
    }

    float acc[2][4][4];
    #pragma unroll
    for (int ti = 0; ti < 2; ti++)
        #pragma unroll
        for (int nt = 0; nt < 4; nt++)
            #pragma unroll
            for (int j = 0; j < 4; j++) acc[ti][nt][j] = 0.f;

    const int chunk = lane & 7;

    #pragma unroll 1
    for (int t = 0; t < 9; t++) {
        const int ky = t / 3, kx = t - ky*3;

        // ---- A tile: shifted x lines, zero-padded ----
        #pragma unroll
        for (int it = 0; it < 8; it++) {
            const int j = it*4 + (lane >> 3);       // pixel idx 0..31 in warp
            const int prow = wp*32 + j;
            const int gp = tile*256 + prow;
            const int yy = (gp >> 7) + ky - 1;
            const int xx = (gp & 127) + kx - 1;
            uint4 v = make_uint4(0u, 0u, 0u, 0u);
            if (yy >= 0 && yy < H_ && xx >= 0 && xx < W_)
                v = xcb[(yy*W_ + xx)*8 + chunk];
            const unsigned off = (unsigned)(prow*128 + 16*(chunk ^ (prow & 7)));
            *(uint4*)(sA + off) = v;
        }

        __syncthreads();

        // ---- mma: 2 passes (hi, lo), N=32, B hoisted per kc ----
        #pragma unroll
        for (int kc = 0; kc < 4; kc++) {
            const uint2* sBh = sB + ((t*4 + kc)*4)*32;
            const uint2* sBl = sBh + 4608;
            uint2 bh[4], bl[4];
            #pragma unroll
            for (int nt = 0; nt < 4; nt++) {
                bh[nt] = sBh[nt*32 + lane];
                bl[nt] = sBl[nt*32 + lane];
            }
            #pragma unroll
            for (int ti = 0; ti < 2; ti++) {
                const int prow = wp*32 + ti*16 + (lane & 15);
                const int chnk = 2*kc + (lane >> 4);
                const unsigned aoff = sAu + (unsigned)(prow*128 + 16*(chnk ^ (prow & 7)));
                unsigned a0, a1, a2, a3;
                asm volatile("ldmatrix.sync.aligned.m8n8.x4.shared.b16 {%0,%1,%2,%3}, [%4];"
                             : "=r"(a0), "=r"(a1), "=r"(a2), "=r"(a3) : "r"(aoff));
                #pragma unroll
                for (int nt = 0; nt < 4; nt++) {
                    float* d = acc[ti][nt];
                    asm volatile(
                        "mma.sync.aligned.m16n8k16.row.col.f32.f16.f16.f32 "
                        "{%0,%1,%2,%3}, {%4,%5,%6,%7}, {%8,%9}, {%0,%1,%2,%3};"
                        : "+f"(d[0]), "+f"(d[1]), "+f"(d[2]), "+f"(d[3])
                        : "r"(a0), "r"(a1), "r"(a2), "r"(a3), "r"(bh[nt].x), "r"(bh[nt].y));
                    asm volatile(
                        "mma.sync.aligned.m16n8k16.row.col.f32.f16.f16.f32 "
                        "{%0,%1,%2,%3}, {%4,%5,%6,%7}, {%8,%9}, {%0,%1,%2,%3};"
                        : "+f"(d[0]), "+f"(d[1]), "+f"(d[2]), "+f"(d[3])
                        : "r"(a0), "r"(a1), "r"(a2), "r"(a3), "r"(bl[nt].x), "r"(bl[nt].y));
                }
            }
        }

        __syncthreads();
    }

    // ---- epilogue: D -> SMEM (stride 33) -> dy/dx/mask ----
    {
        const int r0 = lane >> 2;
        const int cp = (lane & 3)*2;
        #pragma unroll
        for (int ti = 0; ti < 2; ti++) {
            const int row = wp*32 + ti*16 + r0;
            #pragma unroll
            for (int nt = 0; nt < 4; nt++) {
                const int col = nt*8 + cp;
                float* d = acc[ti][nt];
                sD[row*33 + col]         = d[0];
                sD[row*33 + col + 1]     = d[1];
                sD[(row + 8)*33 + col]     = d[2];
                sD[(row + 8)*33 + col + 1] = d[3];
            }
        }
    }
    __syncthreads();

    {
        const int p  = tid;
        const int gp = tile*256 + p;
        const float* row = sD + p*33;
        #pragma unroll
        for (int k = 0; k < 9; k++) {
            const int base = (b*9 + k)*HW_ + gp;
            g_dy[base]   = row[2*k]     + b_om[2*k];
            g_dx[base]   = row[2*k + 1] + b_om[2*k + 1];
            float ml     = row[18 + k]  + b_om[18 + k];
            g_mask[base] = 1.f / (1.f + __expf(-ml));
        }
    }
}

// ---------------- kernel 2: implicit GEMM via mma.sync (fp16 x fp16) ----------------
// M=256 px, warp owns 32 px, all-tap B preload. Bilinear combine in half2
// (HMUL2/HFMA2), B fragments hoisted to registers per kc.
#define SMEM_D (32768 + 9*8192)     // sA 32KB + sB 72KB = 106496

__global__ void __launch_bounds__(256, 2)
deform_mma(const float* __restrict__ bias, float* __restrict__ out) {
    extern __shared__ unsigned char smem[];
    unsigned char* sA = smem;                       // fp16 A tile 256x64 = 32KB
    uint2* sB = (uint2*)(smem + 32768);             // [9][4][8][32] uint2

    const int tid  = threadIdx.x;
    const int lane = tid & 31;
    const int wp   = tid >> 5;          // warp 0..7 -> pixels wp*32..+31
    const int b    = blockIdx.x >> 6;
    const int tile = blockIdx.x & 63;   // 2-row tile
    const uint4* xcb = g_xc + (size_t)b*HW_*8;

    const unsigned sAu = smem_u32(sA);

    {
        const uint4* src = (const uint4*)g_wB;
        uint4* dst = (uint4*)sB;
        #pragma unroll
        for (int j = tid; j < 4608; j += 256) dst[j] = src[j];
    }

    const int px_c = tid;                       // pixel within tile (0..255)
    const int gpix = tile*256 + px_c;
    const int yq   = gpix >> 7, xq = gpix & 127;

    float acc[2][8][4];
    #pragma unroll
    for (int ti = 0; ti < 2; ti++)
        #pragma unroll
        for (int nt = 0; nt < 8; nt++)
            #pragma unroll
            for (int j = 0; j < 4; j++) acc[ti][nt][j] = 0.f;

    #pragma unroll 1
    for (int t = 0; t < 9; t++) {
        int o00, o01, o10, o11;
        float c00, c01, c10, c11;
        {
            const int obase = (b*9 + t)*HW_ + gpix;
            const float m  = g_mask[obase];
            const int ky = t / 3, kx = t - ky*3;
            const float sy = g_dy[obase] + (float)(ky + yq - 1);
            const float sx = g_dx[obase] + (float)(kx + xq - 1);

            const float y0f = floorf(sy), x0f = floorf(sx);
            const int iy0 = (int)y0f, ix0 = (int)x0f;
            const float wy1 = sy - y0f, wx1 = sx - x0f;
            const float wy0 = 1.f - wy1, wx0 = 1.f - wx1;

            const bool py0 = (iy0   >= 0) && (iy0   < H_);
            const bool py1 = (iy0+1 >= 0) && (iy0+1 < H_);
            const bool qx0 = (ix0   >= 0) && (ix0   < W_);
            const bool qx1 = (ix0+1 >= 0) && (ix0+1 < W_);

            const int y0c = min(max(iy0,   0), H_-1);
            const int y1c = min(max(iy0+1, 0), H_-1);
            const int x0c = min(max(ix0,   0), W_-1);
            const int x1c = min(max(ix0+1, 0), W_-1);

            o00 = y0c*W_ + x0c;  o01 = y0c*W_ + x1c;
            o10 = y1c*W_ + x0c;  o11 = y1c*W_ + x1c;

            c00 = (py0 && qx0) ? wy0*wx0*m : 0.f;
            c01 = (py0 && qx1) ? wy0*wx1*m : 0.f;
            c10 = (py1 && qx0) ? wy1*wx0*m : 0.f;
            c11 = (py1 && qx1) ? wy1*wx1*m : 0.f;
        }

        const int chunk = lane & 7;
        #pragma unroll
        for (int it = 0; it < 8; it++) {
            const int j = it*4 + (lane >> 3);       // pixel idx 0..31 in warp
            const int p0 = __shfl_sync(0xffffffffu, o00, j);
            const int p1 = __shfl_sync(0xffffffffu, o01, j);
            const int p2 = __shfl_sync(0xffffffffu, o10, j);
            const int p3 = __shfl_sync(0xffffffffu, o11, j);
            const float k0 = __shfl_sync(0xffffffffu, c00, j);
            const float k1 = __shfl_sync(0xffffffffu, c01, j);
            const float k2 = __shfl_sync(0xffffffffu, c10, j);
            const float k3 = __shfl_sync(0xffffffffu, c11, j);

            const __half2 hk0 = __float2half2_rn(k0);
            const __half2 hk1 = __float2half2_rn(k1);
            const __half2 hk2 = __float2half2_rn(k2);
            const __half2 hk3 = __float2half2_rn(k3);

            const uint4 w0 = xcb[p0*8 + chunk];
            const uint4 w1 = xcb[p1*8 + chunk];
            const uint4 w2 = xcb[p2*8 + chunk];
            const uint4 w3 = xcb[p3*8 + chunk];

            unsigned outw[4];
            #pragma unroll
            for (int q = 0; q < 4; q++) {
                const __half2 f0 = *(const __half2*)&(&w0.x)[q];
                const __half2 f1 = *(const __half2*)&(&w1.x)[q];
                const __half2 f2 = *(const __half2*)&(&w2.x)[q];
                const __half2 f3 = *(const __half2*)&(&w3.x)[q];
                __half2 v = __hmul2(hk0, f0);
                v = __hfma2(hk1, f1, v);
                v = __hfma2(hk2, f2, v);
                v = __hfma2(hk3, f3, v);
                outw[q] = *reinterpret_cast<const unsigned*>(&v);
            }
            uint4 ov; ov.x = outw[0]; ov.y = outw[1]; ov.z = outw[2]; ov.w = outw[3];
            const int prow = wp*32 + j;
            const unsigned off = (unsigned)(prow*128 + 16*(chunk ^ (prow & 7)));
            *(uint4*)(sA + off) = ov;
        }

        __syncthreads();

        #pragma unroll
        for (int kc = 0; kc < 4; kc++) {
            const uint2* sBk = sB + (t*4 + kc)*256;
            uint2 bf[8];
            #pragma unroll
            for (int nt = 0; nt < 8; nt++) bf[nt] = sBk[nt*32 + lane];
            #pragma unroll
            for (int ti = 0; ti < 2; ti++) {
                const int prow = wp*32 + ti*16 + (lane & 15);
                const int chnk = 2*kc + (lane >> 4);
                const unsigned aoff = sAu + (unsigned)(prow*128 + 16*(chnk ^ (prow & 7)));
                unsigned a0, a1, a2, a3;
                asm volatile("ldmatrix.sync.aligned.m8n8.x4.shared.b16 {%0,%1,%2,%3}, [%4];"
                             : "=r"(a0), "=r"(a1), "=r"(a2), "=r"(a3) : "r"(aoff));

                #pragma unroll
                for (int nt = 0; nt < 8; nt++) {
                    float* d = acc[ti][nt];
                    asm volatile(
                        "mma.sync.aligned.m16n8k16.row.col.f32.f16.f16.f32 "
                        "{%0,%1,%2,%3}, {%4,%5,%6,%7}, {%8,%9}, {%0,%1,%2,%3};"
                        : "+f"(d[0]), "+f"(d[1]), "+f"(d[2]), "+f"(d[3])
                        : "r"(a0), "r"(a1), "r"(a2), "r"(a3), "r"(bf[nt].x), "r"(bf[nt].y));
                }
            }
        }

        __syncthreads();
    }

    {
        const int r0 = lane >> 2;
        const int cp = (lane & 3)*2;
        #pragma unroll
        for (int ti = 0; ti < 2; ti++) {
            float* obase = out + (size_t)(b*O_)*HW_ + tile*256 + wp*32 + ti*16;
            #pragma unroll
            for (int nt = 0; nt < 8; nt++) {
                const int o = nt*8 + cp;
                const float bi0 = bias[o], bi1 = bias[o+1];
                obase[(size_t)o*HW_     + r0    ] = acc[ti][nt][0] + bi0;
                obase[(size_t)(o+1)*HW_ + r0    ] = acc[ti][nt][1] + bi1;
                obase[(size_t)o*HW_     + r0 + 8] = acc[ti][nt][2] + bi0;
                obase[(size_t)(o+1)*HW_ + r0 + 8] = acc[ti][nt][3] + bi1;
            }
        }
    }
}

// ---------------- launch ----------------
extern "C" void kernel_launch(void* const* d_in, const int* in_sizes, int n_in,
                              void* d_out, int out_size) {
    const float* x      = (const float*)d_in[0];
    const float* w_om   = (const float*)d_in[1];
    const float* b_om   = (const float*)d_in[2];
    const float* weight = (const float*)d_in[3];
    const float* bias   = (const float*)d_in[4];
    float* out = (float*)d_out;

    cudaFuncSetAttribute(offset_mma, cudaFuncAttributeMaxDynamicSharedMemorySize, SMEM_O);
    cudaFuncSetAttribute(offset_mma, cudaFuncAttributePreferredSharedMemoryCarveout, 100);
    cudaFuncSetAttribute(deform_mma, cudaFuncAttributeMaxDynamicSharedMemorySize, SMEM_D);
    cudaFuncSetAttribute(deform_mma, cudaFuncAttributePreferredSharedMemoryCarveout, 100);

    prep<<<256, 256>>>(x, w_om, weight);
    offset_mma<<<256, 256, SMEM_O>>>(b_om);
    deform_mma<<<256, 256, SMEM_D>>>(bias, out);
}

// round 15
// speedup vs baseline: 4.5242x; 1.0976x over previous
#include <cuda_runtime.h>
#include <cuda_bf16.h>
#include <cuda_fp16.h>
#include <math.h>

// Problem constants (fixed by the reference)
#define B_  4
#define C_  64
#define O_  64
#define H_  128
#define W_  128
#define K2_ 9
#define HW_ (H_*W_)
#define CK_ (C_*K2_)          // 576

// ---------------- scratch (no allocations allowed) ----------------
// Main weight in mma.sync B-fragment layout (fp16 single pass):
// idx = ((t*4 + kc)*8 + nt)*32 + lane
__device__ uint2 g_wB[9*4*8*32];
// Offset-conv weight, B-fragment layout, fp16 hi only, N padded to 32:
// idx = ((t*4 + kc)*4 + nt)*32 + lane
__device__ uint2 g_wOB[9*4*4*32];
__device__ float g_dy   [B_*K2_*HW_];
__device__ float g_dx   [B_*K2_*HW_];
__device__ float g_mask [B_*K2_*HW_];
// x repacked channel-major fp16: pixel-major, 64 ch contiguous = 128B/pixel
__device__ uint4 g_xc[B_*HW_*8];

__device__ __forceinline__ unsigned smem_u32(const void* p) {
    unsigned a;
    asm("{ .reg .u64 t; cvta.to.shared.u64 t, %1; cvt.u32.u64 %0, t; }"
        : "=r"(a) : "l"(p));
    return a;
}

// ---------------- kernel 0: prep (tiled x transpose + weight fragments) ----------------
// 2048 CTAs x 256 threads. Each CTA transposes a 32-pixel x 64-channel tile
// through SMEM: reads coalesced (32 floats per channel row), writes coalesced
// (32 px x 128B channel-major lines).
__global__ void __launch_bounds__(256)
prep(const float* __restrict__ x, const float* __restrict__ w_om,
     const float* __restrict__ weight) {
    __shared__ float tile[64][33];

    const int tid = threadIdx.x;
    const int g32 = blockIdx.x;             // 32-px group, 512 per batch
    const int b   = g32 >> 9;
    const int p0  = (g32 & 511) * 32;

    // read: 64 channels x 32 px, coalesced
    const float* xb = x + (size_t)b*C_*HW_ + p0;
    #pragma unroll
    for (int i = tid; i < 64*32; i += 256) {
        const int c = i >> 5, px = i & 31;
        tile[c][px] = xb[(size_t)c*HW_ + px];
    }
    __syncthreads();

    // write: thread = (px, chunk); 8 fp16 per chunk, fully coalesced
    {
        const int px = tid >> 3, ch = tid & 7;
        unsigned w[4];
        #pragma unroll
        for (int j = 0; j < 4; j++) {
            __half2 h = __floats2half2_rn(tile[ch*8 + 2*j][px],
                                          tile[ch*8 + 2*j + 1][px]);
            w[j] = *reinterpret_cast<unsigned*>(&h);
        }
        uint4 o; o.x = w[0]; o.y = w[1]; o.z = w[2]; o.w = w[3];
        g_xc[(size_t)(b*HW_ + p0 + px)*8 + ch] = o;
    }

    // --- weight fragments (grid-strided over a flat id) ---
    const int gid = blockIdx.x*256 + tid;

    // main weight -> mma B-fragment layout, fp16
    if (gid < 9216) {
        int i = gid;
        int t    = i / 1024;
        int r    = i - t*1024;
        int kc   = r >> 8;
        int r2   = r & 255;
        int nt   = r2 >> 5;
        int lane = r2 & 31;
        int n  = nt*8 + (lane >> 2);
        int kb = (lane & 3)*2;
        unsigned hv[2];
        #pragma unroll
        for (int u = 0; u < 2; u++) {
            int c0 = kc*16 + kb + u*8;
            float w0 = weight[n*CK_ + c0*9 + t];
            float w1 = weight[n*CK_ + (c0+1)*9 + t];
            __half2 h = __floats2half2_rn(w0, w1);
            hv[u] = *reinterpret_cast<unsigned*>(&h);
        }
        uint2 hi; hi.x = hv[0]; hi.y = hv[1];
        g_wB[i] = hi;
    }

    // offset-conv weight -> B fragments (N=32 pad, fp16 hi only)
    if (gid < 4608) {
        int i = gid;
        int t    = i / 512;
        int r    = i - t*512;
        int kc   = r >> 7;
        int r2   = r & 127;
        int nt   = r2 >> 5;
        int lane = r2 & 31;
        int n  = nt*8 + (lane >> 2);
        int kb = (lane & 3)*2;
        unsigned hv[2];
        #pragma unroll
        for (int u = 0; u < 2; u++) {
            int c0 = kc*16 + kb + u*8;
            float w0 = (n < 27) ? w_om[n*CK_ + c0*9 + t]     : 0.f;
            float w1 = (n < 27) ? w_om[n*CK_ + (c0+1)*9 + t] : 0.f;
            __half2 h = __floats2half2_rn(w0, w1);
            hv[u] = *reinterpret_cast<unsigned*>(&h);
        }
        uint2 hi; hi.x = hv[0]; hi.y = hv[1];
        g_wOB[i] = hi;
    }
}

// ---------------- kernel 1: offset/mask conv via mma.sync (fp16 single pass) ----------------
// M=256 px tile, N=32 (27 used), K=576. A tiles are plain shifted copies of
// the channel-major fp16 x lines (zero-padded at borders).
#define SMEM_O (32768 + 36864)      // sA 32KB + sB 36KB = 69632

__global__ void __launch_bounds__(256, 2)
offset_mma(const float* __restrict__ b_om) {
    extern __shared__ unsigned char smem[];
    unsigned char* sA = smem;                   // fp16 A tile 256x64 = 32KB
    uint2* sB = (uint2*)(smem + 32768);         // [9][4][4][32]
    float* sD = (float*)(smem + 32768);         // epilogue reuse (33792 B)

    const int tid  = threadIdx.x;
    const int lane = tid & 31;
    const int wp   = tid >> 5;          // warp 0..7 -> pixels wp*32..+31
    const int b    = blockIdx.x >> 6;
    const int tile = blockIdx.x & 63;   // 2-row tile
    const uint4* xcb = g_xc + (size_t)b*HW_*8;

    const unsigned sAu = smem_u32(sA);

    {   // preload offset-weight fragments (36 KB)
        const uint4* src = (const uint4*)g_wOB;
        uint4* dst = (uint4*)sB;
        #pragma unroll
        for (int j = tid; j < 2304; j += 256) dst[j] = src[j];
    }

    float acc[2][4][4];
    #pragma unroll
    for (int ti = 0; ti < 2; ti++)
        #pragma unroll
        for (int nt = 0; nt < 4; nt++)
            #pragma unroll
            for (int j = 0; j < 4; j++) acc[ti][nt][j] = 0.f;

    const int chunk = lane & 7;

    #pragma unroll 1
    for (int t = 0; t < 9; t++) {
        const int ky = t / 3, kx = t - ky*3;

        // ---- A tile: shifted x lines, zero-padded ----
        #pragma unroll
        for (int it = 0; it < 8; it++) {
            const int j = it*4 + (lane >> 3);       // pixel idx 0..31 in warp
            const int prow = wp*32 + j;
            const int gp = tile*256 + prow;
            const int yy = (gp >> 7) + ky - 1;
            const int xx = (gp & 127) + kx - 1;
            uint4 v = make_uint4(0u, 0u, 0u, 0u);
            if (yy >= 0 && yy < H_ && xx >= 0 && xx < W_)
                v = xcb[(yy*W_ + xx)*8 + chunk];
            const unsigned off = (unsigned)(prow*128 + 16*(chunk ^ (prow & 7)));
            *(uint4*)(sA + off) = v;
        }

        __syncthreads();

        // ---- mma: single fp16 pass, N=32, B hoisted per kc ----
        #pragma unroll
        for (int kc = 0; kc < 4; kc++) {
            const uint2* sBh = sB + ((t*4 + kc)*4)*32;
            uint2 bh[4];
            #pragma unroll
            for (int nt = 0; nt < 4; nt++) bh[nt] = sBh[nt*32 + lane];
            #pragma unroll
            for (int ti = 0; ti < 2; ti++) {
                const int prow = wp*32 + ti*16 + (lane & 15);
                const int chnk = 2*kc + (lane >> 4);
                const unsigned aoff = sAu + (unsigned)(prow*128 + 16*(chnk ^ (prow & 7)));
                unsigned a0, a1, a2, a3;
                asm volatile("ldmatrix.sync.aligned.m8n8.x4.shared.b16 {%0,%1,%2,%3}, [%4];"
                             : "=r"(a0), "=r"(a1), "=r"(a2), "=r"(a3) : "r"(aoff));
                #pragma unroll
                for (int nt = 0; nt < 4; nt++) {
                    float* d = acc[ti][nt];
                    asm volatile(
                        "mma.sync.aligned.m16n8k16.row.col.f32.f16.f16.f32 "
                        "{%0,%1,%2,%3}, {%4,%5,%6,%7}, {%8,%9}, {%0,%1,%2,%3};"
                        : "+f"(d[0]), "+f"(d[1]), "+f"(d[2]), "+f"(d[3])
                        : "r"(a0), "r"(a1), "r"(a2), "r"(a3), "r"(bh[nt].x), "r"(bh[nt].y));
                }
            }
        }

        __syncthreads();
    }

    // ---- epilogue: D -> SMEM (stride 33) -> dy/dx/mask ----
    {
        const int r0 = lane >> 2;
        const int cp = (lane & 3)*2;
        #pragma unroll
        for (int ti = 0; ti < 2; ti++) {
            const int row = wp*32 + ti*16 + r0;
            #pragma unroll
            for (int nt = 0; nt < 4; nt++) {
                const int col = nt*8 + cp;
                float* d = acc[ti][nt];
                sD[row*33 + col]         = d[0];
                sD[row*33 + col + 1]     = d[1];
                sD[(row + 8)*33 + col]     = d[2];
                sD[(row + 8)*33 + col + 1] = d[3];
            }
        }
    }
    __syncthreads();

    {
        const int p  = tid;
        const int gp = tile*256 + p;
        const float* row = sD + p*33;
        #pragma unroll
        for (int k = 0; k < 9; k++) {
            const int base = (b*9 + k)*HW_ + gp;
            g_dy[base]   = row[2*k]     + b_om[2*k];
            g_dx[base]   = row[2*k + 1] + b_om[2*k + 1];
            float ml     = row[18 + k]  + b_om[18 + k];
            g_mask[base] = 1.f / (1.f + __expf(-ml));
        }
    }
}

// ---------------- kernel 2: implicit GEMM via mma.sync (fp16 x fp16) ----------------
// M=256 px, warp owns 32 px, all-tap B preload. Bilinear combine in half2,
// B fragments hoisted to registers per kc. (Unchanged from R14.)
#define SMEM_D (32768 + 9*8192)     // sA 32KB + sB 72KB = 106496

__global__ void __launch_bounds__(256, 2)
deform_mma(const float* __restrict__ bias, float* __restrict__ out) {
    extern __shared__ unsigned char smem[];
    unsigned char* sA = smem;                       // fp16 A tile 256x64 = 32KB
    uint2* sB = (uint2*)(smem + 32768);             // [9][4][8][32] uint2

    const int tid  = threadIdx.x;
    const int lane = tid & 31;
    const int wp   = tid >> 5;          // warp 0..7 -> pixels wp*32..+31
    const int b    = blockIdx.x >> 6;
    const int tile = blockIdx.x & 63;   // 2-row tile
    const uint4* xcb = g_xc + (size_t)b*HW_*8;

    const unsigned sAu = smem_u32(sA);

    {
        const uint4* src = (const uint4*)g_wB;
        uint4* dst = (uint4*)sB;
        #pragma unroll
        for (int j = tid; j < 4608; j += 256) dst[j] = src[j];
    }

    const int px_c = tid;                       // pixel within tile (0..255)
    const int gpix = tile*256 + px_c;
    const int yq   = gpix >> 7, xq = gpix & 127;

    float acc[2][8][4];
    #pragma unroll
    for (int ti = 0; ti < 2; ti++)
        #pragma unroll
        for (int nt = 0; nt < 8; nt++)
            #pragma unroll
            for (int j = 0; j < 4; j++) acc[ti][nt][j] = 0.f;

    #pragma unroll 1
    for (int t = 0; t < 9; t++) {
        int o00, o01, o10, o11;
        float c00, c01, c10, c11;
        {
            const int obase = (b*9 + t)*HW_ + gpix;
            const float m  = g_mask[obase];
            const int ky = t / 3, kx = t - ky*3;
            const float sy = g_dy[obase] + (float)(ky + yq - 1);
            const float sx = g_dx[obase] + (float)(kx + xq - 1);

            const float y0f = floorf(sy), x0f = floorf(sx);
            const int iy0 = (int)y0f, ix0 = (int)x0f;
            const float wy1 = sy - y0f, wx1 = sx - x0f;
            const float wy0 = 1.f - wy1, wx0 = 1.f - wx1;

            const bool py0 = (iy0   >= 0) && (iy0   < H_);
            const bool py1 = (iy0+1 >= 0) && (iy0+1 < H_);
            const bool qx0 = (ix0   >= 0) && (ix0   < W_);
            const bool qx1 = (ix0+1 >= 0) && (ix0+1 < W_);

            const int y0c = min(max(iy0,   0), H_-1);
            const int y1c = min(max(iy0+1, 0), H_-1);
            const int x0c = min(max(ix0,   0), W_-1);
            const int x1c = min(max(ix0+1, 0), W_-1);

            o00 = y0c*W_ + x0c;  o01 = y0c*W_ + x1c;
            o10 = y1c*W_ + x0c;  o11 = y1c*W_ + x1c;

            c00 = (py0 && qx0) ? wy0*wx0*m : 0.f;
            c01 = (py0 && qx1) ? wy0*wx1*m : 0.f;
            c10 = (py1 && qx0) ? wy1*wx0*m : 0.f;
            c11 = (py1 && qx1) ? wy1*wx1*m : 0.f;
        }

        const int chunk = lane & 7;
        #pragma unroll
        for (int it = 0; it < 8; it++) {
            const int j = it*4 + (lane >> 3);       // pixel idx 0..31 in warp
            const int p0 = __shfl_sync(0xffffffffu, o00, j);
            const int p1 = __shfl_sync(0xffffffffu, o01, j);
            const int p2 = __shfl_sync(0xffffffffu, o10, j);
            const int p3 = __shfl_sync(0xffffffffu, o11, j);
            const float k0 = __shfl_sync(0xffffffffu, c00, j);
            const float k1 = __shfl_sync(0xffffffffu, c01, j);
            const float k2 = __shfl_sync(0xffffffffu, c10, j);
            const float k3 = __shfl_sync(0xffffffffu, c11, j);

            const __half2 hk0 = __float2half2_rn(k0);
            const __half2 hk1 = __float2half2_rn(k1);
            const __half2 hk2 = __float2half2_rn(k2);
            const __half2 hk3 = __float2half2_rn(k3);

            const uint4 w0 = xcb[p0*8 + chunk];
            const uint4 w1 = xcb[p1*8 + chunk];
            const uint4 w2 = xcb[p2*8 + chunk];
            const uint4 w3 = xcb[p3*8 + chunk];

            unsigned outw[4];
            #pragma unroll
            for (int q = 0; q < 4; q++) {
                const __half2 f0 = *(const __half2*)&(&w0.x)[q];
                const __half2 f1 = *(const __half2*)&(&w1.x)[q];
                const __half2 f2 = *(const __half2*)&(&w2.x)[q];
                const __half2 f3 = *(const __half2*)&(&w3.x)[q];
                __half2 v = __hmul2(hk0, f0);
                v = __hfma2(hk1, f1, v);
                v = __hfma2(hk2, f2, v);
                v = __hfma2(hk3, f3, v);
                outw[q] = *reinterpret_cast<const unsigned*>(&v);
            }
            uint4 ov; ov.x = outw[0]; ov.y = outw[1]; ov.z = outw[2]; ov.w = outw[3];
            const int prow = wp*32 + j;
            const unsigned off = (unsigned)(prow*128 + 16*(chunk ^ (prow & 7)));
            *(uint4*)(sA + off) = ov;
        }

        __syncthreads();

        #pragma unroll
        for (int kc = 0; kc < 4; kc++) {
            const uint2* sBk = sB + (t*4 + kc)*256;
            uint2 bf[8];
            #pragma unroll
            for (int nt = 0; nt < 8; nt++) bf[nt] = sBk[nt*32 + lane];
            #pragma unroll
            for (int ti = 0; ti < 2; ti++) {
                const int prow = wp*32 + ti*16 + (lane & 15);
                const int chnk = 2*kc + (lane >> 4);
                const unsigned aoff = sAu + (unsigned)(prow*128 + 16*(chnk ^ (prow & 7)));
                unsigned a0, a1, a2, a3;
                asm volatile("ldmatrix.sync.aligned.m8n8.x4.shared.b16 {%0,%1,%2,%3}, [%4];"
                             : "=r"(a0), "=r"(a1), "=r"(a2), "=r"(a3) : "r"(aoff));

                #pragma unroll
                for (int nt = 0; nt < 8; nt++) {
                    float* d = acc[ti][nt];
                    asm volatile(
                        "mma.sync.aligned.m16n8k16.row.col.f32.f16.f16.f32 "
                        "{%0,%1,%2,%3}, {%4,%5,%6,%7}, {%8,%9}, {%0,%1,%2,%3};"
                        : "+f"(d[0]), "+f"(d[1]), "+f"(d[2]), "+f"(d[3])
                        : "r"(a0), "r"(a1), "r"(a2), "r"(a3), "r"(bf[nt].x), "r"(bf[nt].y));
                }
            }
        }

        __syncthreads();
    }

    {
        const int r0 = lane >> 2;
        const int cp = (lane & 3)*2;
        #pragma unroll
        for (int ti = 0; ti < 2; ti++) {
            float* obase = out + (size_t)(b*O_)*HW_ + tile*256 + wp*32 + ti*16;
            #pragma unroll
            for (int nt = 0; nt < 8; nt++) {
                const int o = nt*8 + cp;
                const float bi0 = bias[o], bi1 = bias[o+1];
                obase[(size_t)o*HW_     + r0    ] = acc[ti][nt][0] + bi0;
                obase[(size_t)(o+1)*HW_ + r0    ] = acc[ti][nt][1] + bi1;
                obase[(size_t)o*HW_     + r0 + 8] = acc[ti][nt][2] + bi0;
                obase[(size_t)(o+1)*HW_ + r0 + 8] = acc[ti][nt][3] + bi1;
            }
        }
    }
}

// ---------------- launch ----------------
extern "C" void kernel_launch(void* const* d_in, const int* in_sizes, int n_in,
                              void* d_out, int out_size) {
    const float* x      = (const float*)d_in[0];
    const float* w_om   = (const float*)d_in[1];
    const float* b_om   = (const float*)d_in[2];
    const float* weight = (const float*)d_in[3];
    const float* bias   = (const float*)d_in[4];
    float* out = (float*)d_out;

    cudaFuncSetAttribute(offset_mma, cudaFuncAttributeMaxDynamicSharedMemorySize, SMEM_O);
    cudaFuncSetAttribute(offset_mma, cudaFuncAttributePreferredSharedMemoryCarveout, 100);
    cudaFuncSetAttribute(deform_mma, cudaFuncAttributeMaxDynamicSharedMemorySize, SMEM_D);
    cudaFuncSetAttribute(deform_mma, cudaFuncAttributePreferredSharedMemoryCarveout, 100);

    prep<<<2048, 256>>>(x, w_om, weight);
    offset_mma<<<256, 256, SMEM_O>>>(b_om);
    deform_mma<<<256, 256, SMEM_D>>>(bias, out);
}

// round 16
// speedup vs baseline: 5.0673x; 1.1201x over previous
#include <cuda_runtime.h>
#include <cuda_bf16.h>
#include <cuda_fp16.h>
#include <math.h>

// Problem constants (fixed by the reference)
#define B_  4
#define C_  64
#define O_  64
#define H_  128
#define W_  128
#define K2_ 9
#define HW_ (H_*W_)
#define CK_ (C_*K2_)          // 576

// ---------------- scratch (no allocations allowed) ----------------
// Main weight in mma.sync B-fragment layout (fp16 single pass):
// idx = ((t*4 + kc)*8 + nt)*32 + lane
__device__ uint2 g_wB[9*4*8*32];
// Offset-conv weight, B-fragment layout, fp16 hi only, N padded to 32:
// idx = ((t*4 + kc)*4 + nt)*32 + lane
__device__ uint2 g_wOB[9*4*4*32];
__device__ float g_dy   [B_*K2_*HW_];
__device__ float g_dx   [B_*K2_*HW_];
__device__ float g_mask [B_*K2_*HW_];
// x repacked channel-major fp16: pixel-major, 64 ch contiguous = 128B/pixel
__device__ uint4 g_xc[B_*HW_*8];

__device__ __forceinline__ unsigned smem_u32(const void* p) {
    unsigned a;
    asm("{ .reg .u64 t; cvta.to.shared.u64 t, %1; cvt.u32.u64 %0, t; }"
        : "=r"(a) : "l"(p));
    return a;
}

// ---------------- kernel 0: prep (tiled x transpose + weight fragments) ----------------
__global__ void __launch_bounds__(256)
prep(const float* __restrict__ x, const float* __restrict__ w_om,
     const float* __restrict__ weight) {
    __shared__ float tile[64][33];

    const int tid = threadIdx.x;
    const int g32 = blockIdx.x;             // 32-px group, 512 per batch
    const int b   = g32 >> 9;
    const int p0  = (g32 & 511) * 32;

    const float* xb = x + (size_t)b*C_*HW_ + p0;
    #pragma unroll
    for (int i = tid; i < 64*32; i += 256) {
        const int c = i >> 5, px = i & 31;
        tile[c][px] = xb[(size_t)c*HW_ + px];
    }
    __syncthreads();

    {
        const int px = tid >> 3, ch = tid & 7;
        unsigned w[4];
        #pragma unroll
        for (int j = 0; j < 4; j++) {
            __half2 h = __floats2half2_rn(tile[ch*8 + 2*j][px],
                                          tile[ch*8 + 2*j + 1][px]);
            w[j] = *reinterpret_cast<unsigned*>(&h);
        }
        uint4 o; o.x = w[0]; o.y = w[1]; o.z = w[2]; o.w = w[3];
        g_xc[(size_t)(b*HW_ + p0 + px)*8 + ch] = o;
    }

    const int gid = blockIdx.x*256 + tid;

    if (gid < 9216) {
        int i = gid;
        int t    = i / 1024;
        int r    = i - t*1024;
        int kc   = r >> 8;
        int r2   = r & 255;
        int nt   = r2 >> 5;
        int lane = r2 & 31;
        int n  = nt*8 + (lane >> 2);
        int kb = (lane & 3)*2;
        unsigned hv[2];
        #pragma unroll
        for (int u = 0; u < 2; u++) {
            int c0 = kc*16 + kb + u*8;
            float w0 = weight[n*CK_ + c0*9 + t];
            float w1 = weight[n*CK_ + (c0+1)*9 + t];
            __half2 h = __floats2half2_rn(w0, w1);
            hv[u] = *reinterpret_cast<unsigned*>(&h);
        }
        uint2 hi; hi.x = hv[0]; hi.y = hv[1];
        g_wB[i] = hi;
    }

    if (gid < 4608) {
        int i = gid;
        int t    = i / 512;
        int r    = i - t*512;
        int kc   = r >> 7;
        int r2   = r & 127;
        int nt   = r2 >> 5;
        int lane = r2 & 31;
        int n  = nt*8 + (lane >> 2);
        int kb = (lane & 3)*2;
        unsigned hv[2];
        #pragma unroll
        for (int u = 0; u < 2; u++) {
            int c0 = kc*16 + kb + u*8;
            float w0 = (n < 27) ? w_om[n*CK_ + c0*9 + t]     : 0.f;
            float w1 = (n < 27) ? w_om[n*CK_ + (c0+1)*9 + t] : 0.f;
            __half2 h = __floats2half2_rn(w0, w1);
            hv[u] = *reinterpret_cast<unsigned*>(&h);
        }
        uint2 hi; hi.x = hv[0]; hi.y = hv[1];
        g_wOB[i] = hi;
    }
}

// ---------------- kernel 1: offset/mask conv via mma.sync (fp16 single pass) ----------------
#define SMEM_O (32768 + 36864)      // sA 32KB + sB 36KB = 69632

__global__ void __launch_bounds__(256, 2)
offset_mma(const float* __restrict__ b_om) {
    extern __shared__ unsigned char smem[];
    unsigned char* sA = smem;                   // fp16 A tile 256x64 = 32KB
    uint2* sB = (uint2*)(smem + 32768);         // [9][4][4][32]
    float* sD = (float*)(smem + 32768);         // epilogue reuse (33792 B)

    const int tid  = threadIdx.x;
    const int lane = tid & 31;
    const int wp   = tid >> 5;
    const int b    = blockIdx.x >> 6;
    const int tile = blockIdx.x & 63;
    const uint4* xcb = g_xc + (size_t)b*HW_*8;

    const unsigned sAu = smem_u32(sA);

    {
        const uint4* src = (const uint4*)g_wOB;
        uint4* dst = (uint4*)sB;
        #pragma unroll
        for (int j = tid; j < 2304; j += 256) dst[j] = src[j];
    }

    float acc[2][4][4];
    #pragma unroll
    for (int ti = 0; ti < 2; ti++)
        #pragma unroll
        for (int nt = 0; nt < 4; nt++)
            #pragma unroll
            for (int j = 0; j < 4; j++) acc[ti][nt][j] = 0.f;

    const int chunk = lane & 7;

    #pragma unroll 1
    for (int t = 0; t < 9; t++) {
        const int ky = t / 3, kx = t - ky*3;

        #pragma unroll
        for (int it = 0; it < 8; it++) {
            const int j = it*4 + (lane >> 3);
            const int prow = wp*32 + j;
            const int gp = tile*256 + prow;
            const int yy = (gp >> 7) + ky - 1;
            const int xx = (gp & 127) + kx - 1;
            uint4 v = make_uint4(0u, 0u, 0u, 0u);
            if (yy >= 0 && yy < H_ && xx >= 0 && xx < W_)
                v = xcb[(yy*W_ + xx)*8 + chunk];
            const unsigned off = (unsigned)(prow*128 + 16*(chunk ^ (prow & 7)));
            *(uint4*)(sA + off) = v;
        }

        __syncthreads();

        #pragma unroll
        for (int kc = 0; kc < 4; kc++) {
            const uint2* sBh = sB + ((t*4 + kc)*4)*32;
            uint2 bh[4];
            #pragma unroll
            for (int nt = 0; nt < 4; nt++) bh[nt] = sBh[nt*32 + lane];
            #pragma unroll
            for (int ti = 0; ti < 2; ti++) {
                const int prow = wp*32 + ti*16 + (lane & 15);
                const int chnk = 2*kc + (lane >> 4);
                const unsigned aoff = sAu + (unsigned)(prow*128 + 16*(chnk ^ (prow & 7)));
                unsigned a0, a1, a2, a3;
                asm volatile("ldmatrix.sync.aligned.m8n8.x4.shared.b16 {%0,%1,%2,%3}, [%4];"
                             : "=r"(a0), "=r"(a1), "=r"(a2), "=r"(a3) : "r"(aoff));
                #pragma unroll
                for (int nt = 0; nt < 4; nt++) {
                    float* d = acc[ti][nt];
                    asm volatile(
                        "mma.sync.aligned.m16n8k16.row.col.f32.f16.f16.f32 "
                        "{%0,%1,%2,%3}, {%4,%5,%6,%7}, {%8,%9}, {%0,%1,%2,%3};"
                        : "+f"(d[0]), "+f"(d[1]), "+f"(d[2]), "+f"(d[3])
                        : "r"(a0), "r"(a1), "r"(a2), "r"(a3), "r"(bh[nt].x), "r"(bh[nt].y));
                }
            }
        }

        __syncthreads();
    }

    {
        const int r0 = lane >> 2;
        const int cp = (lane & 3)*2;
        #pragma unroll
        for (int ti = 0; ti < 2; ti++) {
            const int row = wp*32 + ti*16 + r0;
            #pragma unroll
            for (int nt = 0; nt < 4; nt++) {
                const int col = nt*8 + cp;
                float* d = acc[ti][nt];
                sD[row*33 + col]         = d[0];
                sD[row*33 + col + 1]     = d[1];
                sD[(row + 8)*33 + col]     = d[2];
                sD[(row + 8)*33 + col + 1] = d[3];
            }
        }
    }
    __syncthreads();

    {
        const int p  = tid;
        const int gp = tile*256 + p;
        const float* row = sD + p*33;
        #pragma unroll
        for (int k = 0; k < 9; k++) {
            const int base = (b*9 + k)*HW_ + gp;
            g_dy[base]   = row[2*k]     + b_om[2*k];
            g_dx[base]   = row[2*k + 1] + b_om[2*k + 1];
            float ml     = row[18 + k]  + b_om[18 + k];
            g_mask[base] = 1.f / (1.f + __expf(-ml));
        }
    }
}

// ---------------- deform helpers ----------------
struct TapCoef {
    int o00, o01, o10, o11;
    float c00, c01, c10, c11;
};

__device__ __forceinline__ TapCoef tap_coeffs(int b, int t, int gpix, int yq, int xq) {
    TapCoef r;
    const int obase = (b*9 + t)*HW_ + gpix;
    const float m  = g_mask[obase];
    const int ky = t / 3, kx = t - ky*3;
    const float sy = g_dy[obase] + (float)(ky + yq - 1);
    const float sx = g_dx[obase] + (float)(kx + xq - 1);

    const float y0f = floorf(sy), x0f = floorf(sx);
    const int iy0 = (int)y0f, ix0 = (int)x0f;
    const float wy1 = sy - y0f, wx1 = sx - x0f;
    const float wy0 = 1.f - wy1, wx0 = 1.f - wx1;

    const bool py0 = (iy0   >= 0) && (iy0   < H_);
    const bool py1 = (iy0+1 >= 0) && (iy0+1 < H_);
    const bool qx0 = (ix0   >= 0) && (ix0   < W_);
    const bool qx1 = (ix0+1 >= 0) && (ix0+1 < W_);

    const int y0c = min(max(iy0,   0), H_-1);
    const int y1c = min(max(iy0+1, 0), H_-1);
    const int x0c = min(max(ix0,   0), W_-1);
    const int x1c = min(max(ix0+1, 0), W_-1);

    r.o00 = y0c*W_ + x0c;  r.o01 = y0c*W_ + x1c;
    r.o10 = y1c*W_ + x0c;  r.o11 = y1c*W_ + x1c;

    r.c00 = (py0 && qx0) ? wy0*wx0*m : 0.f;
    r.c01 = (py0 && qx1) ? wy0*wx1*m : 0.f;
    r.c10 = (py1 && qx0) ? wy1*wx0*m : 0.f;
    r.c11 = (py1 && qx1) ? wy1*wx1*m : 0.f;
    return r;
}

__device__ __forceinline__ void gather_tap(const uint4* xcb, unsigned char* sAbuf,
                                           int wp, int lane, const TapCoef& tc) {
    const int chunk = lane & 7;
    #pragma unroll
    for (int it = 0; it < 8; it++) {
        const int j = it*4 + (lane >> 3);       // pixel idx 0..31 in warp
        const int p0 = __shfl_sync(0xffffffffu, tc.o00, j);
        const int p1 = __shfl_sync(0xffffffffu, tc.o01, j);
        const int p2 = __shfl_sync(0xffffffffu, tc.o10, j);
        const int p3 = __shfl_sync(0xffffffffu, tc.o11, j);
        const float k0 = __shfl_sync(0xffffffffu, tc.c00, j);
        const float k1 = __shfl_sync(0xffffffffu, tc.c01, j);
        const float k2 = __shfl_sync(0xffffffffu, tc.c10, j);
        const float k3 = __shfl_sync(0xffffffffu, tc.c11, j);

        const __half2 hk0 = __float2half2_rn(k0);
        const __half2 hk1 = __float2half2_rn(k1);
        const __half2 hk2 = __float2half2_rn(k2);
        const __half2 hk3 = __float2half2_rn(k3);

        const uint4 w0 = xcb[p0*8 + chunk];
        const uint4 w1 = xcb[p1*8 + chunk];
        const uint4 w2 = xcb[p2*8 + chunk];
        const uint4 w3 = xcb[p3*8 + chunk];

        unsigned outw[4];
        #pragma unroll
        for (int q = 0; q < 4; q++) {
            const __half2 f0 = *(const __half2*)&(&w0.x)[q];
            const __half2 f1 = *(const __half2*)&(&w1.x)[q];
            const __half2 f2 = *(const __half2*)&(&w2.x)[q];
            const __half2 f3 = *(const __half2*)&(&w3.x)[q];
            __half2 v = __hmul2(hk0, f0);
            v = __hfma2(hk1, f1, v);
            v = __hfma2(hk2, f2, v);
            v = __hfma2(hk3, f3, v);
            outw[q] = *reinterpret_cast<const unsigned*>(&v);
        }
        uint4 ov; ov.x = outw[0]; ov.y = outw[1]; ov.z = outw[2]; ov.w = outw[3];
        const int prow = wp*32 + j;
        const unsigned off = (unsigned)(prow*128 + 16*(chunk ^ (prow & 7)));
        *(uint4*)(sAbuf + off) = ov;
    }
}

// ---------------- kernel 2: pipelined implicit GEMM via mma.sync ----------------
// M=256 px, warp owns 32 px. Double-buffered A (2x32KB): gather tap t+1
// overlaps mma of tap t; ONE barrier per tap. B fragments read straight from
// g_wB (36KB, L1-resident) -- no sB, no preload.
#define SMEM_D 65536

__global__ void __launch_bounds__(256, 2)
deform_mma(const float* __restrict__ bias, float* __restrict__ out) {
    extern __shared__ unsigned char smem[];     // sA[2]: 0 and 32768

    const int tid  = threadIdx.x;
    const int lane = tid & 31;
    const int wp   = tid >> 5;          // warp 0..7 -> pixels wp*32..+31
    const int b    = blockIdx.x >> 6;
    const int tile = blockIdx.x & 63;   // 2-row tile
    const uint4* xcb = g_xc + (size_t)b*HW_*8;

    const unsigned sAu = smem_u32(smem);

    const int px_c = tid;
    const int gpix = tile*256 + px_c;
    const int yq   = gpix >> 7, xq = gpix & 127;

    float acc[2][8][4];
    #pragma unroll
    for (int ti = 0; ti < 2; ti++)
        #pragma unroll
        for (int nt = 0; nt < 8; nt++)
            #pragma unroll
            for (int j = 0; j < 4; j++) acc[ti][nt][j] = 0.f;

    // prologue: gather tap 0 into buffer 0
    {
        TapCoef tc = tap_coeffs(b, 0, gpix, yq, xq);
        gather_tap(xcb, smem, wp, lane, tc);
    }
    __syncthreads();

    #pragma unroll 1
    for (int t = 0; t < 9; t++) {
        // gather next tap into the other buffer (overlaps with mma below)
        if (t < 8) {
            TapCoef tc = tap_coeffs(b, t + 1, gpix, yq, xq);
            gather_tap(xcb, smem + ((t + 1) & 1)*32768, wp, lane, tc);
        }

        // mma on buffer t&1; B fragments via LDG (L1-resident)
        const unsigned abase = sAu + (unsigned)((t & 1)*32768);
        #pragma unroll
        for (int kc = 0; kc < 4; kc++) {
            const uint2* gB = g_wB + (t*4 + kc)*256;
            uint2 bf[8];
            #pragma unroll
            for (int nt = 0; nt < 8; nt++) bf[nt] = gB[nt*32 + lane];
            #pragma unroll
            for (int ti = 0; ti < 2; ti++) {
                const int prow = wp*32 + ti*16 + (lane & 15);
                const int chnk = 2*kc + (lane >> 4);
                const unsigned aoff = abase + (unsigned)(prow*128 + 16*(chnk ^ (prow & 7)));
                unsigned a0, a1, a2, a3;
                asm volatile("ldmatrix.sync.aligned.m8n8.x4.shared.b16 {%0,%1,%2,%3}, [%4];"
                             : "=r"(a0), "=r"(a1), "=r"(a2), "=r"(a3) : "r"(aoff));

                #pragma unroll
                for (int nt = 0; nt < 8; nt++) {
                    float* d = acc[ti][nt];
                    asm volatile(
                        "mma.sync.aligned.m16n8k16.row.col.f32.f16.f16.f32 "
                        "{%0,%1,%2,%3}, {%4,%5,%6,%7}, {%8,%9}, {%0,%1,%2,%3};"
                        : "+f"(d[0]), "+f"(d[1]), "+f"(d[2]), "+f"(d[3])
                        : "r"(a0), "r"(a1), "r"(a2), "r"(a3), "r"(bf[nt].x), "r"(bf[nt].y));
                }
            }
        }

        __syncthreads();
    }

    // ---- epilogue ----
    {
        const int r0 = lane >> 2;
        const int cp = (lane & 3)*2;
        #pragma unroll
        for (int ti = 0; ti < 2; ti++) {
            float* obase = out + (size_t)(b*O_)*HW_ + tile*256 + wp*32 + ti*16;
            #pragma unroll
            for (int nt = 0; nt < 8; nt++) {
                const int o = nt*8 + cp;
                const float bi0 = bias[o], bi1 = bias[o+1];
                obase[(size_t)o*HW_     + r0    ] = acc[ti][nt][0] + bi0;
                obase[(size_t)(o+1)*HW_ + r0    ] = acc[ti][nt][1] + bi1;
                obase[(size_t)o*HW_     + r0 + 8] = acc[ti][nt][2] + bi0;
                obase[(size_t)(o+1)*HW_ + r0 + 8] = acc[ti][nt][3] + bi1;
            }
        }
    }
}

// ---------------- launch ----------------
extern "C" void kernel_launch(void* const* d_in, const int* in_sizes, int n_in,
                              void* d_out, int out_size) {
    const float* x      = (const float*)d_in[0];
    const float* w_om   = (const float*)d_in[1];
    const float* b_om   = (const float*)d_in[2];
    const float* weight = (const float*)d_in[3];
    const float* bias   = (const float*)d_in[4];
    float* out = (float*)d_out;

    cudaFuncSetAttribute(offset_mma, cudaFuncAttributeMaxDynamicSharedMemorySize, SMEM_O);
    cudaFuncSetAttribute(offset_mma, cudaFuncAttributePreferredSharedMemoryCarveout, 100);
    cudaFuncSetAttribute(deform_mma, cudaFuncAttributeMaxDynamicSharedMemorySize, SMEM_D);
    cudaFuncSetAttribute(deform_mma, cudaFuncAttributePreferredSharedMemoryCarveout, 100);

    prep<<<2048, 256>>>(x, w_om, weight);
    offset_mma<<<256, 256, SMEM_O>>>(b_om);
    deform_mma<<<256, 256, SMEM_D>>>(bias, out);
}